// round 1
// baseline (speedup 1.0000x reference)
#include <cuda_runtime.h>

// Problem constants
#define BATCHN 2
#define SEQL   2048
#define DIMN   2048
#define NH     16
#define NKV    8
#define HD     128
#define NCH    16
#define CHK    128

// Scratch (static device globals — no allocation allowed)
__device__ float g_q[(size_t)BATCHN * NH * SEQL * HD];      // q' = softmax(q*scale)/colsum  (B,H,S,D)
__device__ float g_k[(size_t)BATCHN * NKV * SEQL * HD];     // exp(rope(k))                  (B,Hk,S,D)
__device__ float g_v[(size_t)BATCHN * NKV * SEQL * HD];     // v                             (B,Hk,S,D)
__device__ float g_attn[(size_t)BATCHN * SEQL * DIMN];      // attention output              (B,S,H*D)
__device__ float g_kv[(size_t)BATCHN * NKV * NCH * HD * HD];  // per-chunk k^T v
__device__ float g_cum[(size_t)BATCHN * NKV * NCH * HD * HD]; // exclusive prefix over chunks
__device__ float g_colsum[BATCHN * NKV * HD];

// ---------------------------------------------------------------------------
// K1: fused QKV projection.  Y = X @ W^T for W in {wq, wk, wv}, scattered into
// (B, H, S, D) layouts. 128x128 tile, BK=16, 256 threads, 8x8 microtile.
// ---------------------------------------------------------------------------
__global__ __launch_bounds__(256) void k_qkv_gemm(
    const float* __restrict__ X, const float* __restrict__ Wq,
    const float* __restrict__ Wk, const float* __restrict__ Wv)
{
    __shared__ float As[16][132];
    __shared__ float Bs[16][132];
    const int K = DIMN;
    int m0 = blockIdx.y * 128;
    int n0 = blockIdx.x * 128;   // 0..4095: [0,2048)=q, [2048,3072)=k, [3072,4096)=v
    const float* W; int nb;
    if (n0 < 2048)      { W = Wq; nb = n0; }
    else if (n0 < 3072) { W = Wk; nb = n0 - 2048; }
    else                { W = Wv; nb = n0 - 3072; }

    int t = threadIdx.x;
    int ty = t >> 4, tx = t & 15;
    float acc[8][8];
#pragma unroll
    for (int i = 0; i < 8; i++)
#pragma unroll
        for (int j = 0; j < 8; j++) acc[i][j] = 0.f;

    for (int k0 = 0; k0 < K; k0 += 16) {
#pragma unroll
        for (int it = 0; it < 2; it++) {
            int p   = it * 256 + t;
            int row = p >> 2;
            int c4  = (p & 3) << 2;
            float4 av = *(const float4*)(X + (size_t)(m0 + row) * K + k0 + c4);
            As[c4 + 0][row] = av.x; As[c4 + 1][row] = av.y;
            As[c4 + 2][row] = av.z; As[c4 + 3][row] = av.w;
            float4 bv = *(const float4*)(W + (size_t)(nb + row) * K + k0 + c4);
            Bs[c4 + 0][row] = bv.x; Bs[c4 + 1][row] = bv.y;
            Bs[c4 + 2][row] = bv.z; Bs[c4 + 3][row] = bv.w;
        }
        __syncthreads();
#pragma unroll
        for (int kk = 0; kk < 16; kk++) {
            float a[8], b[8];
            float4 t0 = *(const float4*)&As[kk][ty * 8];
            float4 t1 = *(const float4*)&As[kk][ty * 8 + 4];
            a[0]=t0.x; a[1]=t0.y; a[2]=t0.z; a[3]=t0.w;
            a[4]=t1.x; a[5]=t1.y; a[6]=t1.z; a[7]=t1.w;
            float4 u0 = *(const float4*)&Bs[kk][tx * 8];
            float4 u1 = *(const float4*)&Bs[kk][tx * 8 + 4];
            b[0]=u0.x; b[1]=u0.y; b[2]=u0.z; b[3]=u0.w;
            b[4]=u1.x; b[5]=u1.y; b[6]=u1.z; b[7]=u1.w;
#pragma unroll
            for (int i = 0; i < 8; i++)
#pragma unroll
                for (int j = 0; j < 8; j++) acc[i][j] += a[i] * b[j];
        }
        __syncthreads();
    }

    int dloc = tx * 8;
#pragma unroll
    for (int i = 0; i < 8; i++) {
        int m  = m0 + ty * 8 + i;
        int bb = m >> 11;
        int s  = m & 2047;
        float* rp;
        if (n0 < 2048)
            rp = g_q + (((size_t)(bb * NH  + (n0 >> 7))) * SEQL + s) * HD + dloc;
        else if (n0 < 3072)
            rp = g_k + (((size_t)(bb * NKV + ((n0 - 2048) >> 7))) * SEQL + s) * HD + dloc;
        else
            rp = g_v + (((size_t)(bb * NKV + ((n0 - 3072) >> 7))) * SEQL + s) * HD + dloc;
        *(float4*)(rp)     = make_float4(acc[i][0], acc[i][1], acc[i][2], acc[i][3]);
        *(float4*)(rp + 4) = make_float4(acc[i][4], acc[i][5], acc[i][6], acc[i][7]);
    }
}

// ---------------------------------------------------------------------------
// zero colsum
// ---------------------------------------------------------------------------
__global__ void k_zero()
{
    int i = blockIdx.x * 1024 + threadIdx.x;
    if (i < BATCHN * NKV * HD) g_colsum[i] = 0.f;
}

// ---------------------------------------------------------------------------
// K3: k <- exp(rope(k)) in-place; accumulate column sums over S per (b,hk,d).
// grid (16, 32), 256 threads; warp handles 8 rows (lane owns d = 4l..4l+3).
// ---------------------------------------------------------------------------
__global__ __launch_bounds__(256) void k_rope_k(const float* __restrict__ fc)
{
    __shared__ float s_part[8][128];
    int bhk = blockIdx.x;   // b*8+hk
    int w   = threadIdx.x >> 5;
    int l   = threadIdx.x & 31;
    float sum0 = 0.f, sum1 = 0.f, sum2 = 0.f, sum3 = 0.f;
#pragma unroll
    for (int r = 0; r < 8; r++) {
        int s = blockIdx.y * 64 + w * 8 + r;
        float* rowp = g_k + ((size_t)bhk * SEQL + s) * HD + l * 4;
        float4 v = *(float4*)rowp;
        float4 f = *(const float4*)(fc + (size_t)s * HD + l * 4); // (c0,s0,c1,s1)
        float o0 = v.x * f.x - v.y * f.y;
        float o1 = v.x * f.y + v.y * f.x;
        float o2 = v.z * f.z - v.w * f.w;
        float o3 = v.z * f.w + v.w * f.z;
        float e0 = expf(o0), e1 = expf(o1), e2 = expf(o2), e3 = expf(o3);
        *(float4*)rowp = make_float4(e0, e1, e2, e3);
        sum0 += e0; sum1 += e1; sum2 += e2; sum3 += e3;
    }
    s_part[w][l * 4 + 0] = sum0;
    s_part[w][l * 4 + 1] = sum1;
    s_part[w][l * 4 + 2] = sum2;
    s_part[w][l * 4 + 3] = sum3;
    __syncthreads();
    if (threadIdx.x < 128) {
        float a = 0.f;
#pragma unroll
        for (int w2 = 0; w2 < 8; w2++) a += s_part[w2][threadIdx.x];
        atomicAdd(&g_colsum[bhk * HD + threadIdx.x], a);
    }
}

// ---------------------------------------------------------------------------
// K2: q <- softmax(rope(q) * D^-1/2) / colsum[hk]  in-place. Warp per row.
// ---------------------------------------------------------------------------
__global__ __launch_bounds__(256) void k_rope_q(const float* __restrict__ fc)
{
    int r = blockIdx.x * 8 + (threadIdx.x >> 5);  // row = (b*16+h)*2048 + s
    int l = threadIdx.x & 31;
    int s  = r & 2047;
    int bh = r >> 11;
    int h  = bh & 15;
    int b  = bh >> 4;

    float* rowp = g_q + (size_t)r * HD + l * 4;
    float4 v = *(float4*)rowp;
    float4 f = *(const float4*)(fc + (size_t)s * HD + l * 4);
    const float scale = 0.08838834764831845f;  // 1/sqrt(128)
    float o0 = (v.x * f.x - v.y * f.y) * scale;
    float o1 = (v.x * f.y + v.y * f.x) * scale;
    float o2 = (v.z * f.z - v.w * f.w) * scale;
    float o3 = (v.z * f.w + v.w * f.z) * scale;

    float mx = fmaxf(fmaxf(o0, o1), fmaxf(o2, o3));
#pragma unroll
    for (int off = 16; off; off >>= 1) mx = fmaxf(mx, __shfl_xor_sync(0xffffffffu, mx, off));
    float e0 = expf(o0 - mx), e1 = expf(o1 - mx), e2 = expf(o2 - mx), e3 = expf(o3 - mx);
    float ss = e0 + e1 + e2 + e3;
#pragma unroll
    for (int off = 16; off; off >>= 1) ss += __shfl_xor_sync(0xffffffffu, ss, off);
    float inv = 1.f / ss;

    const float* csp = g_colsum + ((b * NKV + (h >> 1)) * HD) + l * 4;
    float4 cs = *(const float4*)csp;
    *(float4*)rowp = make_float4(e0 * inv / cs.x, e1 * inv / cs.y,
                                 e2 * inv / cs.z, e3 * inv / cs.w);
}

// ---------------------------------------------------------------------------
// K4: per-chunk kv = ek_c^T @ v_c  (128x128, K=128). Block per (b,hk,n).
// ---------------------------------------------------------------------------
__global__ __launch_bounds__(256) void k_kvchunk()
{
    __shared__ float As[16][128];
    __shared__ float Bs[16][128];
    int bhk = blockIdx.x >> 4;
    int n   = blockIdx.x & 15;
    const float* ekc = g_k + ((size_t)bhk * SEQL + n * CHK) * HD;
    const float* vc  = g_v + ((size_t)bhk * SEQL + n * CHK) * HD;
    int t = threadIdx.x, ty = t >> 4, tx = t & 15;
    float acc[8][8];
#pragma unroll
    for (int i = 0; i < 8; i++)
#pragma unroll
        for (int j = 0; j < 8; j++) acc[i][j] = 0.f;

    for (int s0 = 0; s0 < 128; s0 += 16) {
#pragma unroll
        for (int it = 0; it < 2; it++) {
            int p = it * 256 + t;
            int row = p >> 5, c4 = (p & 31) * 4;
            *(float4*)&As[row][c4] = *(const float4*)(ekc + (size_t)(s0 + row) * HD + c4);
            *(float4*)&Bs[row][c4] = *(const float4*)(vc  + (size_t)(s0 + row) * HD + c4);
        }
        __syncthreads();
#pragma unroll
        for (int kk = 0; kk < 16; kk++) {
            float a[8], b[8];
            float4 t0 = *(const float4*)&As[kk][ty * 8];
            float4 t1 = *(const float4*)&As[kk][ty * 8 + 4];
            a[0]=t0.x; a[1]=t0.y; a[2]=t0.z; a[3]=t0.w;
            a[4]=t1.x; a[5]=t1.y; a[6]=t1.z; a[7]=t1.w;
            float4 u0 = *(const float4*)&Bs[kk][tx * 8];
            float4 u1 = *(const float4*)&Bs[kk][tx * 8 + 4];
            b[0]=u0.x; b[1]=u0.y; b[2]=u0.z; b[3]=u0.w;
            b[4]=u1.x; b[5]=u1.y; b[6]=u1.z; b[7]=u1.w;
#pragma unroll
            for (int i = 0; i < 8; i++)
#pragma unroll
                for (int j = 0; j < 8; j++) acc[i][j] += a[i] * b[j];
        }
        __syncthreads();
    }
    size_t base = ((size_t)bhk * NCH + n) * HD * HD;
#pragma unroll
    for (int i = 0; i < 8; i++) {
        float* rp = g_kv + base + (size_t)(ty * 8 + i) * HD + tx * 8;
        *(float4*)(rp)     = make_float4(acc[i][0], acc[i][1], acc[i][2], acc[i][3]);
        *(float4*)(rp + 4) = make_float4(acc[i][4], acc[i][5], acc[i][6], acc[i][7]);
    }
}

// ---------------------------------------------------------------------------
// K5: exclusive prefix sum over chunks. grid (16, 64), 256 threads, 1 elem each.
// ---------------------------------------------------------------------------
__global__ void k_prefix()
{
    int bhk  = blockIdx.x;
    int elem = blockIdx.y * 256 + threadIdx.x;    // 0..16383
    size_t base = (size_t)bhk * NCH * (HD * HD) + elem;
    float acc = 0.f;
#pragma unroll
    for (int n = 0; n < NCH; n++) {
        g_cum[base + (size_t)n * (HD * HD)] = acc;
        acc += g_kv[base + (size_t)n * (HD * HD)];
    }
}

// ---------------------------------------------------------------------------
// K6: per-(b,h,chunk) attention.
//   pass1: T[m][c] = sum_d ek[m,d] * q'[c,d], mask m<=c, store transposed scores
//   pass2: O[c][e] = sum_m T[m][c] v[m][e]  +  sum_d q'[c,d] cum_excl[d][e]
// ---------------------------------------------------------------------------
#define QSTR 132
#define ATTN_SMEM ((2 * 128 * QSTR + 16 * 128) * 4)

__global__ __launch_bounds__(256) void k_attn()
{
    extern __shared__ float sm[];
    float* qsT = sm;                       // [128 d][132]: q' transposed (d-major)
    float* scT = sm + 128 * QSTR;          // [128 m][132]: masked scores, m-major
    float* Bst = sm + 2 * 128 * QSTR;      // [16][128] staging

    int bid = blockIdx.x;
    int b = bid >> 8;
    int h = (bid >> 4) & 15;
    int n = bid & 15;
    int hk = h >> 1;
    int t = threadIdx.x, ty = t >> 4, tx = t & 15;

    const float* qb  = g_q + (((size_t)(b * NH  + h ) * SEQL) + n * CHK) * HD;
    const float* ekb = g_k + (((size_t)(b * NKV + hk) * SEQL) + n * CHK) * HD;
    const float* vb  = g_v + (((size_t)(b * NKV + hk) * SEQL) + n * CHK) * HD;
    const float* cb  = g_cum + ((size_t)(b * NKV + hk) * NCH + n) * (HD * HD);

    // Load q' chunk transposed: qsT[d][c]
#pragma unroll
    for (int it = 0; it < 16; it++) {
        int p = it * 256 + t;
        int c = p >> 5;
        int d4 = (p & 31) * 4;
        float4 v4 = *(const float4*)(qb + (size_t)c * HD + d4);
        qsT[(d4 + 0) * QSTR + c] = v4.x;
        qsT[(d4 + 1) * QSTR + c] = v4.y;
        qsT[(d4 + 2) * QSTR + c] = v4.z;
        qsT[(d4 + 3) * QSTR + c] = v4.w;
    }
    __syncthreads();

    float acc[8][8];
#pragma unroll
    for (int i = 0; i < 8; i++)
#pragma unroll
        for (int j = 0; j < 8; j++) acc[i][j] = 0.f;

    // pass1: transposed scores T[m=ty*8+i][c=tx*8+j]
    for (int d0 = 0; d0 < 128; d0 += 16) {
#pragma unroll
        for (int it = 0; it < 2; it++) {
            int p = it * 256 + t;
            int m = p >> 2;
            int dq = (p & 3) * 4;
            float4 v4 = *(const float4*)(ekb + (size_t)m * HD + d0 + dq);
            Bst[(dq + 0) * 128 + m] = v4.x;
            Bst[(dq + 1) * 128 + m] = v4.y;
            Bst[(dq + 2) * 128 + m] = v4.z;
            Bst[(dq + 3) * 128 + m] = v4.w;
        }
        __syncthreads();
#pragma unroll
        for (int kk = 0; kk < 16; kk++) {
            float a[8], b[8];
            float4 t0 = *(const float4*)&Bst[kk * 128 + ty * 8];
            float4 t1 = *(const float4*)&Bst[kk * 128 + ty * 8 + 4];
            a[0]=t0.x; a[1]=t0.y; a[2]=t0.z; a[3]=t0.w;
            a[4]=t1.x; a[5]=t1.y; a[6]=t1.z; a[7]=t1.w;
            float4 u0 = *(const float4*)&qsT[(d0 + kk) * QSTR + tx * 8];
            float4 u1 = *(const float4*)&qsT[(d0 + kk) * QSTR + tx * 8 + 4];
            b[0]=u0.x; b[1]=u0.y; b[2]=u0.z; b[3]=u0.w;
            b[4]=u1.x; b[5]=u1.y; b[6]=u1.z; b[7]=u1.w;
#pragma unroll
            for (int i = 0; i < 8; i++)
#pragma unroll
                for (int j = 0; j < 8; j++) acc[i][j] += a[i] * b[j];
        }
        __syncthreads();
    }

    // mask (keep m<=c) + vectorized store of scT rows; reset acc
#pragma unroll
    for (int i = 0; i < 8; i++) {
        int m = ty * 8 + i;
        float r[8];
#pragma unroll
        for (int j = 0; j < 8; j++) {
            int c = tx * 8 + j;
            r[j] = (m <= c) ? acc[i][j] : 0.f;
            acc[i][j] = 0.f;
        }
        *(float4*)&scT[m * QSTR + tx * 8]     = make_float4(r[0], r[1], r[2], r[3]);
        *(float4*)&scT[m * QSTR + tx * 8 + 4] = make_float4(r[4], r[5], r[6], r[7]);
    }
    __syncthreads();

    // pass2a: intra = scores^T-applied: O[c][e] += sum_m T[m][c] * v[m][e]
    for (int m0 = 0; m0 < 128; m0 += 16) {
#pragma unroll
        for (int it = 0; it < 2; it++) {
            int p = it * 256 + t;
            int row = p >> 5, e4 = (p & 31) * 4;
            *(float4*)&Bst[row * 128 + e4] =
                *(const float4*)(vb + (size_t)(m0 + row) * HD + e4);
        }
        __syncthreads();
#pragma unroll
        for (int kk = 0; kk < 16; kk++) {
            float a[8], b[8];
            float4 t0 = *(const float4*)&scT[(m0 + kk) * QSTR + ty * 8];
            float4 t1 = *(const float4*)&scT[(m0 + kk) * QSTR + ty * 8 + 4];
            a[0]=t0.x; a[1]=t0.y; a[2]=t0.z; a[3]=t0.w;
            a[4]=t1.x; a[5]=t1.y; a[6]=t1.z; a[7]=t1.w;
            float4 u0 = *(const float4*)&Bst[kk * 128 + tx * 8];
            float4 u1 = *(const float4*)&Bst[kk * 128 + tx * 8 + 4];
            b[0]=u0.x; b[1]=u0.y; b[2]=u0.z; b[3]=u0.w;
            b[4]=u1.x; b[5]=u1.y; b[6]=u1.z; b[7]=u1.w;
#pragma unroll
            for (int i = 0; i < 8; i++)
#pragma unroll
                for (int j = 0; j < 8; j++) acc[i][j] += a[i] * b[j];
        }
        __syncthreads();
    }

    // pass2b: inter: O[c][e] += sum_d q'[c,d] * cum_excl[d][e]
    for (int d0 = 0; d0 < 128; d0 += 16) {
#pragma unroll
        for (int it = 0; it < 2; it++) {
            int p = it * 256 + t;
            int row = p >> 5, e4 = (p & 31) * 4;
            *(float4*)&Bst[row * 128 + e4] =
                *(const float4*)(cb + (size_t)(d0 + row) * HD + e4);
        }
        __syncthreads();
#pragma unroll
        for (int kk = 0; kk < 16; kk++) {
            float a[8], b[8];
            float4 t0 = *(const float4*)&qsT[(d0 + kk) * QSTR + ty * 8];
            float4 t1 = *(const float4*)&qsT[(d0 + kk) * QSTR + ty * 8 + 4];
            a[0]=t0.x; a[1]=t0.y; a[2]=t0.z; a[3]=t0.w;
            a[4]=t1.x; a[5]=t1.y; a[6]=t1.z; a[7]=t1.w;
            float4 u0 = *(const float4*)&Bst[kk * 128 + tx * 8];
            float4 u1 = *(const float4*)&Bst[kk * 128 + tx * 8 + 4];
            b[0]=u0.x; b[1]=u0.y; b[2]=u0.z; b[3]=u0.w;
            b[4]=u1.x; b[5]=u1.y; b[6]=u1.z; b[7]=u1.w;
#pragma unroll
            for (int i = 0; i < 8; i++)
#pragma unroll
                for (int j = 0; j < 8; j++) acc[i][j] += a[i] * b[j];
        }
        __syncthreads();
    }

    // epilogue: attn[b][s][h*128 + e]  (rows c = ty*8+i)
#pragma unroll
    for (int i = 0; i < 8; i++) {
        int c = ty * 8 + i;
        int s = n * CHK + c;
        float* op = g_attn + ((size_t)(b * SEQL + s)) * DIMN + h * HD + tx * 8;
        *(float4*)(op)     = make_float4(acc[i][0], acc[i][1], acc[i][2], acc[i][3]);
        *(float4*)(op + 4) = make_float4(acc[i][4], acc[i][5], acc[i][6], acc[i][7]);
    }
}

// ---------------------------------------------------------------------------
// K7: output projection. out = attn @ wo^T.  Same SGEMM shape as K1.
// ---------------------------------------------------------------------------
__global__ __launch_bounds__(256) void k_out_gemm(const float* __restrict__ Wo,
                                                  float* __restrict__ out)
{
    __shared__ float As[16][132];
    __shared__ float Bs[16][132];
    const int K = DIMN;
    int m0 = blockIdx.y * 128;
    int n0 = blockIdx.x * 128;
    int t = threadIdx.x;
    int ty = t >> 4, tx = t & 15;
    float acc[8][8];
#pragma unroll
    for (int i = 0; i < 8; i++)
#pragma unroll
        for (int j = 0; j < 8; j++) acc[i][j] = 0.f;

    for (int k0 = 0; k0 < K; k0 += 16) {
#pragma unroll
        for (int it = 0; it < 2; it++) {
            int p   = it * 256 + t;
            int row = p >> 2;
            int c4  = (p & 3) << 2;
            float4 av = *(const float4*)(g_attn + (size_t)(m0 + row) * K + k0 + c4);
            As[c4 + 0][row] = av.x; As[c4 + 1][row] = av.y;
            As[c4 + 2][row] = av.z; As[c4 + 3][row] = av.w;
            float4 bv = *(const float4*)(Wo + (size_t)(n0 + row) * K + k0 + c4);
            Bs[c4 + 0][row] = bv.x; Bs[c4 + 1][row] = bv.y;
            Bs[c4 + 2][row] = bv.z; Bs[c4 + 3][row] = bv.w;
        }
        __syncthreads();
#pragma unroll
        for (int kk = 0; kk < 16; kk++) {
            float a[8], b[8];
            float4 t0 = *(const float4*)&As[kk][ty * 8];
            float4 t1 = *(const float4*)&As[kk][ty * 8 + 4];
            a[0]=t0.x; a[1]=t0.y; a[2]=t0.z; a[3]=t0.w;
            a[4]=t1.x; a[5]=t1.y; a[6]=t1.z; a[7]=t1.w;
            float4 u0 = *(const float4*)&Bs[kk][tx * 8];
            float4 u1 = *(const float4*)&Bs[kk][tx * 8 + 4];
            b[0]=u0.x; b[1]=u0.y; b[2]=u0.z; b[3]=u0.w;
            b[4]=u1.x; b[5]=u1.y; b[6]=u1.z; b[7]=u1.w;
#pragma unroll
            for (int i = 0; i < 8; i++)
#pragma unroll
                for (int j = 0; j < 8; j++) acc[i][j] += a[i] * b[j];
        }
        __syncthreads();
    }

#pragma unroll
    for (int i = 0; i < 8; i++) {
        int m = m0 + ty * 8 + i;
        float* rp = out + (size_t)m * DIMN + n0 + tx * 8;
        *(float4*)(rp)     = make_float4(acc[i][0], acc[i][1], acc[i][2], acc[i][3]);
        *(float4*)(rp + 4) = make_float4(acc[i][4], acc[i][5], acc[i][6], acc[i][7]);
    }
}

// ---------------------------------------------------------------------------
extern "C" void kernel_launch(void* const* d_in, const int* in_sizes, int n_in,
                              void* d_out, int out_size)
{
    const float* x  = (const float*)d_in[0];
    const float* fc = (const float*)d_in[1];
    const float* wq = (const float*)d_in[2];
    const float* wk = (const float*)d_in[3];
    const float* wv = (const float*)d_in[4];
    const float* wo = (const float*)d_in[5];
    float* out = (float*)d_out;

    cudaFuncSetAttribute(k_attn, cudaFuncAttributeMaxDynamicSharedMemorySize, ATTN_SMEM);

    k_qkv_gemm<<<dim3(32, 32), 256>>>(x, wq, wk, wv);   // q/k/v raw, scattered layouts
    k_zero<<<2, 1024>>>();                               // colsum = 0
    k_rope_k<<<dim3(16, 32), 256>>>(fc);                 // k <- exp(rope(k)), colsum
    k_rope_q<<<8192, 256>>>(fc);                         // q <- softmax(rope(q)*s)/colsum
    k_kvchunk<<<256, 256>>>();                           // per-chunk k^T v
    k_prefix<<<dim3(16, 64), 256>>>();                   // exclusive chunk prefix
    k_attn<<<512, 256, ATTN_SMEM>>>();                   // intra + inter -> attn
    k_out_gemm<<<dim3(16, 32), 256>>>(wo, out);          // out = attn @ wo^T
}

// round 4
// speedup vs baseline: 1.6994x; 1.6994x over previous
#include <cuda_runtime.h>
#include <cuda_bf16.h>
#include <cstdint>

// Problem constants
#define BATCHN 2
#define SEQL   2048
#define DIMN   2048
#define NH     16
#define NKV    8
#define HD     128
#define NCH    16
#define CHK    128
#define KP     6144   // 3-term split-K': 3*DIMN
#define BKC    32     // k-chunk (bf16 elems)
#define STR    40     // smem row stride in elems (conflict-free ldmatrix)

// ---------------------------------------------------------------------------
// Scratch (static device globals — no allocation allowed)
// ---------------------------------------------------------------------------
__device__ float g_q[(size_t)BATCHN * NH * SEQL * HD];
__device__ float g_k[(size_t)BATCHN * NKV * SEQL * HD];
__device__ float g_v[(size_t)BATCHN * NKV * SEQL * HD];
__device__ float g_attn[(size_t)BATCHN * SEQL * DIMN];
__device__ float g_kv[(size_t)BATCHN * NKV * NCH * HD * HD];
__device__ float g_cum[(size_t)BATCHN * NKV * NCH * HD * HD];
__device__ float g_colsum[BATCHN * NKV * HD];

// 3-term bf16 operands (K' = 6144)
__device__ unsigned short g_x2[(size_t)4096 * KP];   // A-style: [hi, lo, hi]
__device__ unsigned short g_w2[(size_t)4096 * KP];   // B-style: [hi, hi, lo]
__device__ unsigned short g_a2[(size_t)4096 * KP];   // A-style
__device__ unsigned short g_wo2[(size_t)2048 * KP];  // B-style

// ---------------------------------------------------------------------------
// PTX helpers (baseline ISA only: ldmatrix / mma.sync / cp.async)
// ---------------------------------------------------------------------------
__device__ __forceinline__ uint32_t smem_u32(const void* p) {
    uint32_t a;
    asm("{ .reg .u64 t; cvta.to.shared.u64 t, %1; cvt.u32.u64 %0, t; }"
        : "=r"(a) : "l"(p));
    return a;
}
__device__ __forceinline__ void ldm_x4(uint32_t* r, uint32_t addr) {
    asm volatile("ldmatrix.sync.aligned.m8n8.x4.shared.b16 {%0,%1,%2,%3}, [%4];"
                 : "=r"(r[0]), "=r"(r[1]), "=r"(r[2]), "=r"(r[3]) : "r"(addr));
}
__device__ __forceinline__ void mma_16816(float* c, const uint32_t* a,
                                          uint32_t b0, uint32_t b1) {
    asm volatile(
        "mma.sync.aligned.m16n8k16.row.col.f32.bf16.bf16.f32 "
        "{%0,%1,%2,%3}, {%4,%5,%6,%7}, {%8,%9}, {%0,%1,%2,%3};"
        : "+f"(c[0]), "+f"(c[1]), "+f"(c[2]), "+f"(c[3])
        : "r"(a[0]), "r"(a[1]), "r"(a[2]), "r"(a[3]), "r"(b0), "r"(b1));
}
__device__ __forceinline__ void cp16(uint32_t s, const void* g) {
    asm volatile("cp.async.cg.shared.global [%0], [%1], 16;" :: "r"(s), "l"(g));
}
__device__ __forceinline__ void cp_commit() {
    asm volatile("cp.async.commit_group;" ::: "memory");
}
template <int N> __device__ __forceinline__ void cp_wait() {
    asm volatile("cp.async.wait_group %0;" :: "n"(N) : "memory");
}

// ---------------------------------------------------------------------------
// fp32 -> 3-term bf16 splits.
//   A-style: dst[3k] = hi, dst[3k+1] = lo, dst[3k+2] = hi
//   B-style: dst[3k] = hi, dst[3k+1] = hi, dst[3k+2] = lo
// A.B aligned dot = hi*hi + lo*hi + hi*lo = a*b - lo*lo  (rel err ~2^-18)
// Each thread: 8 floats -> 24 bf16 (3x uint4 stores).
// ---------------------------------------------------------------------------
__global__ __launch_bounds__(256) void k_cvt_a(const float* __restrict__ src,
                                               unsigned short* __restrict__ dst)
{
    size_t i = ((size_t)blockIdx.x * 256 + threadIdx.x) * 8;
    float4 v0 = *(const float4*)(src + i);
    float4 v1 = *(const float4*)(src + i + 4);
    float f[8] = {v0.x, v0.y, v0.z, v0.w, v1.x, v1.y, v1.z, v1.w};
    __align__(16) __nv_bfloat16 o[24];
#pragma unroll
    for (int j = 0; j < 8; j++) {
        __nv_bfloat16 hh = __float2bfloat16(f[j]);
        __nv_bfloat16 ll = __float2bfloat16(f[j] - __bfloat162float(hh));
        o[3 * j]     = hh;
        o[3 * j + 1] = ll;
        o[3 * j + 2] = hh;
    }
    uint4* d = (uint4*)(dst + i * 3);
    d[0] = ((const uint4*)o)[0];
    d[1] = ((const uint4*)o)[1];
    d[2] = ((const uint4*)o)[2];
}

__global__ __launch_bounds__(256) void k_cvt_b(const float* __restrict__ src,
                                               unsigned short* __restrict__ dst)
{
    size_t i = ((size_t)blockIdx.x * 256 + threadIdx.x) * 8;
    float4 v0 = *(const float4*)(src + i);
    float4 v1 = *(const float4*)(src + i + 4);
    float f[8] = {v0.x, v0.y, v0.z, v0.w, v1.x, v1.y, v1.z, v1.w};
    __align__(16) __nv_bfloat16 o[24];
#pragma unroll
    for (int j = 0; j < 8; j++) {
        __nv_bfloat16 hh = __float2bfloat16(f[j]);
        __nv_bfloat16 ll = __float2bfloat16(f[j] - __bfloat162float(hh));
        o[3 * j]     = hh;
        o[3 * j + 1] = hh;
        o[3 * j + 2] = ll;
    }
    uint4* d = (uint4*)(dst + i * 3);
    d[0] = ((const uint4*)o)[0];
    d[1] = ((const uint4*)o)[1];
    d[2] = ((const uint4*)o)[2];
}

// ---------------------------------------------------------------------------
// HMMA bf16 GEMM: C[M,N] = A2[M,K'] @ B2[N,K']^T, fp32 accum.
// 128x128 tile, BK=32, cp.async double-buffered, ldmatrix fragments.
// mode 0: scatter into g_q/g_k/g_v.  mode 1: row-major C.
// ---------------------------------------------------------------------------
__global__ __launch_bounds__(256) void k_gemm_mma(
    const __nv_bfloat16* __restrict__ A, const __nv_bfloat16* __restrict__ B,
    float* __restrict__ C, int mode)
{
    __shared__ __align__(16) __nv_bfloat16 sA[2][128 * STR];
    __shared__ __align__(16) __nv_bfloat16 sB[2][128 * STR];

    const int t = threadIdx.x, lane = t & 31, wid = t >> 5;
    const int wm = wid >> 2, wn = wid & 3;           // warp grid 2 x 4
    const int m0 = blockIdx.y * 128, n0 = blockIdx.x * 128;

    uint32_t sAb = smem_u32(sA);
    uint32_t sBb = smem_u32(sB);
    const uint32_t TILE_B = 128 * STR * 2;           // bytes per buffer

    const __nv_bfloat16* ga = A + (size_t)(m0 + (t >> 2)) * KP + (t & 3) * 8;
    const __nv_bfloat16* gb = B + (size_t)(n0 + (t >> 2)) * KP + (t & 3) * 8;
    const uint32_t so = ((uint32_t)(t >> 2) * STR + (t & 3) * 8) * 2;

    auto load_tile = [&](int buf, int i) {
        uint32_t sa = sAb + buf * TILE_B + so;
        uint32_t sb = sBb + buf * TILE_B + so;
        int ko = i * BKC;
#pragma unroll
        for (int it = 0; it < 2; it++) {
            cp16(sa + it * 64 * STR * 2, ga + (size_t)it * 64 * KP + ko);
            cp16(sb + it * 64 * STR * 2, gb + (size_t)it * 64 * KP + ko);
        }
        cp_commit();
    };

    float acc[4][4][4];
#pragma unroll
    for (int i = 0; i < 4; i++)
#pragma unroll
        for (int j = 0; j < 4; j++)
#pragma unroll
            for (int r = 0; r < 4; r++) acc[i][j][r] = 0.f;

    const int lr = lane & 7;
    const int lm = (lane >> 3) & 1;
    const int lc = lane >> 4;
    const int NIT = KP / BKC;   // 192

    load_tile(0, 0);
    for (int i = 0; i < NIT; i++) {
        if (i + 1 < NIT) { load_tile((i + 1) & 1, i + 1); cp_wait<1>(); }
        else             { cp_wait<0>(); }
        __syncthreads();

        uint32_t sa = sAb + (i & 1) * TILE_B;
        uint32_t sb = sBb + (i & 1) * TILE_B;
#pragma unroll
        for (int ks = 0; ks < 2; ks++) {
            uint32_t afr[4][4], bfr[2][4];
            const uint32_t coff = ((uint32_t)(ks * 16 + lc * 8)) * 2;
#pragma unroll
            for (int mt = 0; mt < 4; mt++)
                ldm_x4(afr[mt],
                       sa + ((uint32_t)(wm * 64 + mt * 16 + lr + lm * 8) * STR) * 2 + coff);
#pragma unroll
            for (int nt2 = 0; nt2 < 2; nt2++)
                ldm_x4(bfr[nt2],
                       sb + ((uint32_t)(wn * 32 + nt2 * 16 + lr + lm * 8) * STR) * 2 + coff);
#pragma unroll
            for (int mt = 0; mt < 4; mt++)
#pragma unroll
                for (int nt = 0; nt < 4; nt++)
                    mma_16816(acc[mt][nt], afr[mt],
                              bfr[nt >> 1][nt & 1], bfr[nt >> 1][(nt & 1) + 2]);
        }
        __syncthreads();
    }

    // epilogue
    const int g = lane >> 2, c2 = (lane & 3) * 2;
#pragma unroll
    for (int mt = 0; mt < 4; mt++) {
        int mrow = m0 + wm * 64 + mt * 16 + g;
#pragma unroll
        for (int half = 0; half < 2; half++) {
            int m = mrow + half * 8;
            float* dst;
            if (mode == 0) {
                int b = m >> 11, s = m & 2047;
                int ht = n0 >> 7;
                if (ht < 16)
                    dst = g_q + (((size_t)(b * NH + ht)) * SEQL + s) * HD;
                else if (ht < 24)
                    dst = g_k + (((size_t)(b * NKV + (ht - 16))) * SEQL + s) * HD;
                else
                    dst = g_v + (((size_t)(b * NKV + (ht - 24))) * SEQL + s) * HD;
            } else {
                dst = C + (size_t)m * DIMN + n0;
            }
#pragma unroll
            for (int nt = 0; nt < 4; nt++) {
                int col = wn * 32 + nt * 8 + c2;
                float2 v2 = make_float2(acc[mt][nt][half * 2],
                                        acc[mt][nt][half * 2 + 1]);
                *(float2*)(dst + col) = v2;
            }
        }
    }
}

// ---------------------------------------------------------------------------
// zero colsum
// ---------------------------------------------------------------------------
__global__ void k_zero()
{
    int i = blockIdx.x * 1024 + threadIdx.x;
    if (i < BATCHN * NKV * HD) g_colsum[i] = 0.f;
}

// ---------------------------------------------------------------------------
// K3: k <- exp(rope(k)) in-place; accumulate column sums.
// ---------------------------------------------------------------------------
__global__ __launch_bounds__(256) void k_rope_k(const float* __restrict__ fc)
{
    __shared__ float s_part[8][128];
    int bhk = blockIdx.x;
    int w   = threadIdx.x >> 5;
    int l   = threadIdx.x & 31;
    float sum0 = 0.f, sum1 = 0.f, sum2 = 0.f, sum3 = 0.f;
#pragma unroll
    for (int r = 0; r < 8; r++) {
        int s = blockIdx.y * 64 + w * 8 + r;
        float* rowp = g_k + ((size_t)bhk * SEQL + s) * HD + l * 4;
        float4 v = *(float4*)rowp;
        float4 f = *(const float4*)(fc + (size_t)s * HD + l * 4);
        float o0 = v.x * f.x - v.y * f.y;
        float o1 = v.x * f.y + v.y * f.x;
        float o2 = v.z * f.z - v.w * f.w;
        float o3 = v.z * f.w + v.w * f.z;
        float e0 = expf(o0), e1 = expf(o1), e2 = expf(o2), e3 = expf(o3);
        *(float4*)rowp = make_float4(e0, e1, e2, e3);
        sum0 += e0; sum1 += e1; sum2 += e2; sum3 += e3;
    }
    s_part[w][l * 4 + 0] = sum0;
    s_part[w][l * 4 + 1] = sum1;
    s_part[w][l * 4 + 2] = sum2;
    s_part[w][l * 4 + 3] = sum3;
    __syncthreads();
    if (threadIdx.x < 128) {
        float a = 0.f;
#pragma unroll
        for (int w2 = 0; w2 < 8; w2++) a += s_part[w2][threadIdx.x];
        atomicAdd(&g_colsum[bhk * HD + threadIdx.x], a);
    }
}

// ---------------------------------------------------------------------------
// K2: q <- softmax(rope(q) * D^-1/2) / colsum[hk]  in-place.
// ---------------------------------------------------------------------------
__global__ __launch_bounds__(256) void k_rope_q(const float* __restrict__ fc)
{
    int r = blockIdx.x * 8 + (threadIdx.x >> 5);
    int l = threadIdx.x & 31;
    int s  = r & 2047;
    int bh = r >> 11;
    int h  = bh & 15;
    int b  = bh >> 4;

    float* rowp = g_q + (size_t)r * HD + l * 4;
    float4 v = *(float4*)rowp;
    float4 f = *(const float4*)(fc + (size_t)s * HD + l * 4);
    const float scale = 0.08838834764831845f;
    float o0 = (v.x * f.x - v.y * f.y) * scale;
    float o1 = (v.x * f.y + v.y * f.x) * scale;
    float o2 = (v.z * f.z - v.w * f.w) * scale;
    float o3 = (v.z * f.w + v.w * f.z) * scale;

    float mx = fmaxf(fmaxf(o0, o1), fmaxf(o2, o3));
#pragma unroll
    for (int off = 16; off; off >>= 1) mx = fmaxf(mx, __shfl_xor_sync(0xffffffffu, mx, off));
    float e0 = expf(o0 - mx), e1 = expf(o1 - mx), e2 = expf(o2 - mx), e3 = expf(o3 - mx);
    float ss = e0 + e1 + e2 + e3;
#pragma unroll
    for (int off = 16; off; off >>= 1) ss += __shfl_xor_sync(0xffffffffu, ss, off);
    float inv = 1.f / ss;

    const float* csp = g_colsum + ((b * NKV + (h >> 1)) * HD) + l * 4;
    float4 cs = *(const float4*)csp;
    *(float4*)rowp = make_float4(e0 * inv / cs.x, e1 * inv / cs.y,
                                 e2 * inv / cs.z, e3 * inv / cs.w);
}

// ---------------------------------------------------------------------------
// K4: per-chunk kv = ek_c^T @ v_c  (128x128, K=128).
// ---------------------------------------------------------------------------
__global__ __launch_bounds__(256) void k_kvchunk()
{
    __shared__ float As[16][128];
    __shared__ float Bs[16][128];
    int bhk = blockIdx.x >> 4;
    int n   = blockIdx.x & 15;
    const float* ekc = g_k + ((size_t)bhk * SEQL + n * CHK) * HD;
    const float* vc  = g_v + ((size_t)bhk * SEQL + n * CHK) * HD;
    int t = threadIdx.x, ty = t >> 4, tx = t & 15;
    float acc[8][8];
#pragma unroll
    for (int i = 0; i < 8; i++)
#pragma unroll
        for (int j = 0; j < 8; j++) acc[i][j] = 0.f;

    for (int s0 = 0; s0 < 128; s0 += 16) {
#pragma unroll
        for (int it = 0; it < 2; it++) {
            int p = it * 256 + t;
            int row = p >> 5, c4 = (p & 31) * 4;
            *(float4*)&As[row][c4] = *(const float4*)(ekc + (size_t)(s0 + row) * HD + c4);
            *(float4*)&Bs[row][c4] = *(const float4*)(vc  + (size_t)(s0 + row) * HD + c4);
        }
        __syncthreads();
#pragma unroll
        for (int kk = 0; kk < 16; kk++) {
            float a[8], b[8];
            float4 t0 = *(const float4*)&As[kk][ty * 8];
            float4 t1 = *(const float4*)&As[kk][ty * 8 + 4];
            a[0]=t0.x; a[1]=t0.y; a[2]=t0.z; a[3]=t0.w;
            a[4]=t1.x; a[5]=t1.y; a[6]=t1.z; a[7]=t1.w;
            float4 u0 = *(const float4*)&Bs[kk][tx * 8];
            float4 u1 = *(const float4*)&Bs[kk][tx * 8 + 4];
            b[0]=u0.x; b[1]=u0.y; b[2]=u0.z; b[3]=u0.w;
            b[4]=u1.x; b[5]=u1.y; b[6]=u1.z; b[7]=u1.w;
#pragma unroll
            for (int i = 0; i < 8; i++)
#pragma unroll
                for (int j = 0; j < 8; j++) acc[i][j] += a[i] * b[j];
        }
        __syncthreads();
    }
    size_t base = ((size_t)bhk * NCH + n) * HD * HD;
#pragma unroll
    for (int i = 0; i < 8; i++) {
        float* rp = g_kv + base + (size_t)(ty * 8 + i) * HD + tx * 8;
        *(float4*)(rp)     = make_float4(acc[i][0], acc[i][1], acc[i][2], acc[i][3]);
        *(float4*)(rp + 4) = make_float4(acc[i][4], acc[i][5], acc[i][6], acc[i][7]);
    }
}

// ---------------------------------------------------------------------------
// K5: exclusive prefix sum over chunks.
// ---------------------------------------------------------------------------
__global__ void k_prefix()
{
    int bhk  = blockIdx.x;
    int elem = blockIdx.y * 256 + threadIdx.x;
    size_t base = (size_t)bhk * NCH * (HD * HD) + elem;
    float acc = 0.f;
#pragma unroll
    for (int n = 0; n < NCH; n++) {
        g_cum[base + (size_t)n * (HD * HD)] = acc;
        acc += g_kv[base + (size_t)n * (HD * HD)];
    }
}

// ---------------------------------------------------------------------------
// K6: per-(b,h,chunk) attention (intra scores + inter via cum_excl).
// ---------------------------------------------------------------------------
#define QSTR 132
#define ATTN_SMEM ((2 * 128 * QSTR + 16 * 128) * 4)

__global__ __launch_bounds__(256) void k_attn()
{
    extern __shared__ float sm[];
    float* qsT = sm;
    float* scT = sm + 128 * QSTR;
    float* Bst = sm + 2 * 128 * QSTR;

    int bid = blockIdx.x;
    int b = bid >> 8;
    int h = (bid >> 4) & 15;
    int n = bid & 15;
    int hk = h >> 1;
    int t = threadIdx.x, ty = t >> 4, tx = t & 15;

    const float* qb  = g_q + (((size_t)(b * NH  + h ) * SEQL) + n * CHK) * HD;
    const float* ekb = g_k + (((size_t)(b * NKV + hk) * SEQL) + n * CHK) * HD;
    const float* vb  = g_v + (((size_t)(b * NKV + hk) * SEQL) + n * CHK) * HD;
    const float* cb  = g_cum + ((size_t)(b * NKV + hk) * NCH + n) * (HD * HD);

#pragma unroll
    for (int it = 0; it < 16; it++) {
        int p = it * 256 + t;
        int c = p >> 5;
        int d4 = (p & 31) * 4;
        float4 v4 = *(const float4*)(qb + (size_t)c * HD + d4);
        qsT[(d4 + 0) * QSTR + c] = v4.x;
        qsT[(d4 + 1) * QSTR + c] = v4.y;
        qsT[(d4 + 2) * QSTR + c] = v4.z;
        qsT[(d4 + 3) * QSTR + c] = v4.w;
    }
    __syncthreads();

    float acc[8][8];
#pragma unroll
    for (int i = 0; i < 8; i++)
#pragma unroll
        for (int j = 0; j < 8; j++) acc[i][j] = 0.f;

    for (int d0 = 0; d0 < 128; d0 += 16) {
#pragma unroll
        for (int it = 0; it < 2; it++) {
            int p = it * 256 + t;
            int m = p >> 2;
            int dq = (p & 3) * 4;
            float4 v4 = *(const float4*)(ekb + (size_t)m * HD + d0 + dq);
            Bst[(dq + 0) * 128 + m] = v4.x;
            Bst[(dq + 1) * 128 + m] = v4.y;
            Bst[(dq + 2) * 128 + m] = v4.z;
            Bst[(dq + 3) * 128 + m] = v4.w;
        }
        __syncthreads();
#pragma unroll
        for (int kk = 0; kk < 16; kk++) {
            float a[8], b[8];
            float4 t0 = *(const float4*)&Bst[kk * 128 + ty * 8];
            float4 t1 = *(const float4*)&Bst[kk * 128 + ty * 8 + 4];
            a[0]=t0.x; a[1]=t0.y; a[2]=t0.z; a[3]=t0.w;
            a[4]=t1.x; a[5]=t1.y; a[6]=t1.z; a[7]=t1.w;
            float4 u0 = *(const float4*)&qsT[(d0 + kk) * QSTR + tx * 8];
            float4 u1 = *(const float4*)&qsT[(d0 + kk) * QSTR + tx * 8 + 4];
            b[0]=u0.x; b[1]=u0.y; b[2]=u0.z; b[3]=u0.w;
            b[4]=u1.x; b[5]=u1.y; b[6]=u1.z; b[7]=u1.w;
#pragma unroll
            for (int i = 0; i < 8; i++)
#pragma unroll
                for (int j = 0; j < 8; j++) acc[i][j] += a[i] * b[j];
        }
        __syncthreads();
    }

#pragma unroll
    for (int i = 0; i < 8; i++) {
        int m = ty * 8 + i;
        float r[8];
#pragma unroll
        for (int j = 0; j < 8; j++) {
            int c = tx * 8 + j;
            r[j] = (m <= c) ? acc[i][j] : 0.f;
            acc[i][j] = 0.f;
        }
        *(float4*)&scT[m * QSTR + tx * 8]     = make_float4(r[0], r[1], r[2], r[3]);
        *(float4*)&scT[m * QSTR + tx * 8 + 4] = make_float4(r[4], r[5], r[6], r[7]);
    }
    __syncthreads();

    for (int m0 = 0; m0 < 128; m0 += 16) {
#pragma unroll
        for (int it = 0; it < 2; it++) {
            int p = it * 256 + t;
            int row = p >> 5, e4 = (p & 31) * 4;
            *(float4*)&Bst[row * 128 + e4] =
                *(const float4*)(vb + (size_t)(m0 + row) * HD + e4);
        }
        __syncthreads();
#pragma unroll
        for (int kk = 0; kk < 16; kk++) {
            float a[8], b[8];
            float4 t0 = *(const float4*)&scT[(m0 + kk) * QSTR + ty * 8];
            float4 t1 = *(const float4*)&scT[(m0 + kk) * QSTR + ty * 8 + 4];
            a[0]=t0.x; a[1]=t0.y; a[2]=t0.z; a[3]=t0.w;
            a[4]=t1.x; a[5]=t1.y; a[6]=t1.z; a[7]=t1.w;
            float4 u0 = *(const float4*)&Bst[kk * 128 + tx * 8];
            float4 u1 = *(const float4*)&Bst[kk * 128 + tx * 8 + 4];
            b[0]=u0.x; b[1]=u0.y; b[2]=u0.z; b[3]=u0.w;
            b[4]=u1.x; b[5]=u1.y; b[6]=u1.z; b[7]=u1.w;
#pragma unroll
            for (int i = 0; i < 8; i++)
#pragma unroll
                for (int j = 0; j < 8; j++) acc[i][j] += a[i] * b[j];
        }
        __syncthreads();
    }

    for (int d0 = 0; d0 < 128; d0 += 16) {
#pragma unroll
        for (int it = 0; it < 2; it++) {
            int p = it * 256 + t;
            int row = p >> 5, e4 = (p & 31) * 4;
            *(float4*)&Bst[row * 128 + e4] =
                *(const float4*)(cb + (size_t)(d0 + row) * HD + e4);
        }
        __syncthreads();
#pragma unroll
        for (int kk = 0; kk < 16; kk++) {
            float a[8], b[8];
            float4 t0 = *(const float4*)&qsT[(d0 + kk) * QSTR + ty * 8];
            float4 t1 = *(const float4*)&qsT[(d0 + kk) * QSTR + ty * 8 + 4];
            a[0]=t0.x; a[1]=t0.y; a[2]=t0.z; a[3]=t0.w;
            a[4]=t1.x; a[5]=t1.y; a[6]=t1.z; a[7]=t1.w;
            float4 u0 = *(const float4*)&Bst[kk * 128 + tx * 8];
            float4 u1 = *(const float4*)&Bst[kk * 128 + tx * 8 + 4];
            b[0]=u0.x; b[1]=u0.y; b[2]=u0.z; b[3]=u0.w;
            b[4]=u1.x; b[5]=u1.y; b[6]=u1.z; b[7]=u1.w;
#pragma unroll
            for (int i = 0; i < 8; i++)
#pragma unroll
                for (int j = 0; j < 8; j++) acc[i][j] += a[i] * b[j];
        }
        __syncthreads();
    }

#pragma unroll
    for (int i = 0; i < 8; i++) {
        int c = ty * 8 + i;
        int s = n * CHK + c;
        float* op = g_attn + ((size_t)(b * SEQL + s)) * DIMN + h * HD + tx * 8;
        *(float4*)(op)     = make_float4(acc[i][0], acc[i][1], acc[i][2], acc[i][3]);
        *(float4*)(op + 4) = make_float4(acc[i][4], acc[i][5], acc[i][6], acc[i][7]);
    }
}

// ---------------------------------------------------------------------------
extern "C" void kernel_launch(void* const* d_in, const int* in_sizes, int n_in,
                              void* d_out, int out_size)
{
    const float* x  = (const float*)d_in[0];
    const float* fc = (const float*)d_in[1];
    const float* wq = (const float*)d_in[2];
    const float* wk = (const float*)d_in[3];
    const float* wv = (const float*)d_in[4];
    const float* wo = (const float*)d_in[5];
    float* out = (float*)d_out;

    cudaFuncSetAttribute(k_attn, cudaFuncAttributeMaxDynamicSharedMemorySize, ATTN_SMEM);

    void *p_x2, *p_w2, *p_a2, *p_wo2, *p_attn;
    cudaGetSymbolAddress(&p_x2, g_x2);
    cudaGetSymbolAddress(&p_w2, g_w2);
    cudaGetSymbolAddress(&p_a2, g_a2);
    cudaGetSymbolAddress(&p_wo2, g_wo2);
    cudaGetSymbolAddress(&p_attn, g_attn);
    unsigned short* x2  = (unsigned short*)p_x2;
    unsigned short* w2  = (unsigned short*)p_w2;
    unsigned short* a2  = (unsigned short*)p_a2;
    unsigned short* wo2 = (unsigned short*)p_wo2;
    const float* attnp  = (const float*)p_attn;

    // fp32 -> 3-term bf16 conversions (A-style for activations, B-style for weights)
    k_cvt_a<<<4096, 256>>>(x,  x2);                       // 4096x2048 floats
    k_cvt_b<<<2048, 256>>>(wq, w2);                       // rows 0..2047
    k_cvt_b<<<1024, 256>>>(wk, w2 + (size_t)2048 * KP);   // rows 2048..3071
    k_cvt_b<<<1024, 256>>>(wv, w2 + (size_t)3072 * KP);   // rows 3072..4095

    // QKV projection on HMMA tensor cores (scatter epilogue)
    k_gemm_mma<<<dim3(32, 32), 256>>>(
        (const __nv_bfloat16*)x2, (const __nv_bfloat16*)w2, nullptr, 0);

    // RoPE + softmaxes
    k_zero<<<2, 1024>>>();
    k_rope_k<<<dim3(16, 32), 256>>>(fc);
    k_rope_q<<<8192, 256>>>(fc);

    // chunked linear attention (fp32)
    k_kvchunk<<<256, 256>>>();
    k_prefix<<<dim3(16, 64), 256>>>();
    k_attn<<<512, 256, ATTN_SMEM>>>();

    // output projection on HMMA
    k_cvt_a<<<4096, 256>>>(attnp, a2);
    k_cvt_b<<<2048, 256>>>(wo, wo2);
    k_gemm_mma<<<dim3(16, 32), 256>>>(
        (const __nv_bfloat16*)a2, (const __nv_bfloat16*)wo2, out, 1);
}

// round 5
// speedup vs baseline: 1.8303x; 1.0770x over previous
#include <cuda_runtime.h>
#include <cuda_bf16.h>
#include <cstdint>

// Problem constants
#define BATCHN 2
#define SEQL   2048
#define DIMN   2048
#define NH     16
#define NKV    8
#define HD     128
#define NCH    16
#define CHK    128
#define KP     6144   // 3-term split-K': 3*DIMN
#define BKC    64     // k-chunk (bf16 elems)
#define STR    72     // smem row stride in elems (conflict-free ldmatrix)
#define NITG   (KP / BKC)   // 96

// ---------------------------------------------------------------------------
// Scratch (static device globals — no allocation allowed)
// ---------------------------------------------------------------------------
__device__ float g_q[(size_t)BATCHN * NH * SEQL * HD];
__device__ float g_k[(size_t)BATCHN * NKV * SEQL * HD];
__device__ float g_v[(size_t)BATCHN * NKV * SEQL * HD];
__device__ float g_kv[(size_t)BATCHN * NKV * NCH * HD * HD];
__device__ float g_cum[(size_t)BATCHN * NKV * NCH * HD * HD];
__device__ float g_colsum[BATCHN * NKV * HD];

// 3-term bf16 operands (K' = 6144)
__device__ unsigned short g_x2[(size_t)4096 * KP];   // A-style: [hi, lo, hi]
__device__ unsigned short g_w2[(size_t)4096 * KP];   // B-style: [hi, hi, lo]
__device__ unsigned short g_a2[(size_t)4096 * KP];   // A-style (written by k_attn)
__device__ unsigned short g_wo2[(size_t)2048 * KP];  // B-style

// ---------------------------------------------------------------------------
// PTX helpers (baseline ISA only: ldmatrix / mma.sync / cp.async)
// ---------------------------------------------------------------------------
__device__ __forceinline__ uint32_t smem_u32(const void* p) {
    uint32_t a;
    asm("{ .reg .u64 t; cvta.to.shared.u64 t, %1; cvt.u32.u64 %0, t; }"
        : "=r"(a) : "l"(p));
    return a;
}
__device__ __forceinline__ void ldm_x4(uint32_t* r, uint32_t addr) {
    asm volatile("ldmatrix.sync.aligned.m8n8.x4.shared.b16 {%0,%1,%2,%3}, [%4];"
                 : "=r"(r[0]), "=r"(r[1]), "=r"(r[2]), "=r"(r[3]) : "r"(addr));
}
__device__ __forceinline__ void mma_16816(float* c, const uint32_t* a,
                                          uint32_t b0, uint32_t b1) {
    asm volatile(
        "mma.sync.aligned.m16n8k16.row.col.f32.bf16.bf16.f32 "
        "{%0,%1,%2,%3}, {%4,%5,%6,%7}, {%8,%9}, {%0,%1,%2,%3};"
        : "+f"(c[0]), "+f"(c[1]), "+f"(c[2]), "+f"(c[3])
        : "r"(a[0]), "r"(a[1]), "r"(a[2]), "r"(a[3]), "r"(b0), "r"(b1));
}
__device__ __forceinline__ void cp16(uint32_t s, const void* g) {
    asm volatile("cp.async.cg.shared.global [%0], [%1], 16;" :: "r"(s), "l"(g));
}
__device__ __forceinline__ void cp_commit() {
    asm volatile("cp.async.commit_group;" ::: "memory");
}
template <int N> __device__ __forceinline__ void cp_wait() {
    asm volatile("cp.async.wait_group %0;" :: "n"(N) : "memory");
}

// ---------------------------------------------------------------------------
// fp32 -> 3-term bf16 splits.
//   A-style: [hi, lo, hi]   B-style: [hi, hi, lo]
// Aligned dot = hi*hi + lo*hi + hi*lo = a*b - lo*lo  (rel err ~2^-18)
// ---------------------------------------------------------------------------
__global__ __launch_bounds__(256) void k_cvt_a(const float* __restrict__ src,
                                               unsigned short* __restrict__ dst)
{
    size_t i = ((size_t)blockIdx.x * 256 + threadIdx.x) * 8;
    float4 v0 = *(const float4*)(src + i);
    float4 v1 = *(const float4*)(src + i + 4);
    float f[8] = {v0.x, v0.y, v0.z, v0.w, v1.x, v1.y, v1.z, v1.w};
    __align__(16) __nv_bfloat16 o[24];
#pragma unroll
    for (int j = 0; j < 8; j++) {
        __nv_bfloat16 hh = __float2bfloat16(f[j]);
        __nv_bfloat16 ll = __float2bfloat16(f[j] - __bfloat162float(hh));
        o[3 * j]     = hh;
        o[3 * j + 1] = ll;
        o[3 * j + 2] = hh;
    }
    uint4* d = (uint4*)(dst + i * 3);
    d[0] = ((const uint4*)o)[0];
    d[1] = ((const uint4*)o)[1];
    d[2] = ((const uint4*)o)[2];
}

__global__ __launch_bounds__(256) void k_cvt_b(const float* __restrict__ src,
                                               unsigned short* __restrict__ dst)
{
    size_t i = ((size_t)blockIdx.x * 256 + threadIdx.x) * 8;
    float4 v0 = *(const float4*)(src + i);
    float4 v1 = *(const float4*)(src + i + 4);
    float f[8] = {v0.x, v0.y, v0.z, v0.w, v1.x, v1.y, v1.z, v1.w};
    __align__(16) __nv_bfloat16 o[24];
#pragma unroll
    for (int j = 0; j < 8; j++) {
        __nv_bfloat16 hh = __float2bfloat16(f[j]);
        __nv_bfloat16 ll = __float2bfloat16(f[j] - __bfloat162float(hh));
        o[3 * j]     = hh;
        o[3 * j + 1] = hh;
        o[3 * j + 2] = ll;
    }
    uint4* d = (uint4*)(dst + i * 3);
    d[0] = ((const uint4*)o)[0];
    d[1] = ((const uint4*)o)[1];
    d[2] = ((const uint4*)o)[2];
}

// ---------------------------------------------------------------------------
// HMMA bf16 GEMM: C[M,N] = A2[M,K'] @ B2[N,K']^T, fp32 accum.
// 256x128 CTA tile, 8 warps (4x2), 64x64 warp tile, BK=64,
// 3-stage cp.async pipeline, single __syncthreads per iteration.
// mode 0: scatter into g_q/g_k/g_v.  mode 1: row-major C (ldc = DIMN).
// ---------------------------------------------------------------------------
#define A_BUF (256 * STR)                 // elems per A stage
#define B_BUF (128 * STR)
#define GEMM_SMEM ((3 * (A_BUF + B_BUF)) * 2)   // 165888 bytes

__global__ __launch_bounds__(256, 1) void k_gemm_mma(
    const __nv_bfloat16* __restrict__ A, const __nv_bfloat16* __restrict__ B,
    float* __restrict__ C, int mode)
{
    extern __shared__ char smraw[];
    __nv_bfloat16* sA = (__nv_bfloat16*)smraw;
    __nv_bfloat16* sB = sA + 3 * A_BUF;

    const int t = threadIdx.x, lane = t & 31, wid = t >> 5;
    const int wm = wid >> 1, wn = wid & 1;          // warp grid 4 x 2
    const int m0 = blockIdx.y * 256, n0 = blockIdx.x * 128;

    uint32_t sAb = smem_u32(sA);
    uint32_t sBb = smem_u32(sB);

    const __nv_bfloat16* ga = A + (size_t)(m0 + (t >> 3)) * KP + (t & 7) * 8;
    const __nv_bfloat16* gb = B + (size_t)(n0 + (t >> 3)) * KP + (t & 7) * 8;
    const uint32_t so = ((uint32_t)(t >> 3) * STR + (t & 7) * 8) * 2;

    auto load_tile = [&](int buf, int i) {
        uint32_t sa = sAb + (uint32_t)buf * A_BUF * 2 + so;
        uint32_t sb = sBb + (uint32_t)buf * B_BUF * 2 + so;
        int ko = i * BKC;
#pragma unroll
        for (int j = 0; j < 8; j++)
            cp16(sa + j * 32 * STR * 2, ga + (size_t)j * 32 * KP + ko);
#pragma unroll
        for (int j = 0; j < 4; j++)
            cp16(sb + j * 32 * STR * 2, gb + (size_t)j * 32 * KP + ko);
        cp_commit();
    };

    float acc[4][8][4];
#pragma unroll
    for (int i = 0; i < 4; i++)
#pragma unroll
        for (int j = 0; j < 8; j++)
#pragma unroll
            for (int r = 0; r < 4; r++) acc[i][j][r] = 0.f;

    const int lr = lane & 7;
    const int lm = (lane >> 3) & 1;
    const int lc = lane >> 4;

    load_tile(0, 0);
    load_tile(1, 1);

    for (int i = 0; i < NITG; i++) {
        if (i == NITG - 1) cp_wait<0>(); else cp_wait<1>();
        __syncthreads();

        int buf = i % 3;
        uint32_t sa = sAb + (uint32_t)buf * A_BUF * 2;
        uint32_t sb = sBb + (uint32_t)buf * B_BUF * 2;
#pragma unroll
        for (int ks = 0; ks < 4; ks++) {
            uint32_t afr[4][4], bfr[4][4];
            const uint32_t coff = ((uint32_t)(ks * 16 + lc * 8)) * 2;
#pragma unroll
            for (int mt = 0; mt < 4; mt++)
                ldm_x4(afr[mt],
                       sa + ((uint32_t)(wm * 64 + mt * 16 + lr + lm * 8) * STR) * 2 + coff);
#pragma unroll
            for (int nt2 = 0; nt2 < 4; nt2++)
                ldm_x4(bfr[nt2],
                       sb + ((uint32_t)(wn * 64 + nt2 * 16 + lr + lm * 8) * STR) * 2 + coff);
#pragma unroll
            for (int mt = 0; mt < 4; mt++)
#pragma unroll
                for (int nt = 0; nt < 8; nt++)
                    mma_16816(acc[mt][nt], afr[mt],
                              bfr[nt >> 1][nt & 1], bfr[nt >> 1][(nt & 1) + 2]);
        }

        if (i + 2 < NITG) load_tile((i + 2) % 3, i + 2);
    }

    // epilogue
    const int g = lane >> 2, c2 = (lane & 3) * 2;
#pragma unroll
    for (int mt = 0; mt < 4; mt++) {
#pragma unroll
        for (int half = 0; half < 2; half++) {
            int m = m0 + wm * 64 + mt * 16 + g + half * 8;
            float* dst;
            if (mode == 0) {
                int b = m >> 11, s = m & 2047;
                int ht = n0 >> 7;
                if (ht < 16)
                    dst = g_q + (((size_t)(b * NH + ht)) * SEQL + s) * HD;
                else if (ht < 24)
                    dst = g_k + (((size_t)(b * NKV + (ht - 16))) * SEQL + s) * HD;
                else
                    dst = g_v + (((size_t)(b * NKV + (ht - 24))) * SEQL + s) * HD;
            } else {
                dst = C + (size_t)m * DIMN + n0;
            }
#pragma unroll
            for (int nt = 0; nt < 8; nt++) {
                int col = wn * 64 + nt * 8 + c2;
                float2 v2 = make_float2(acc[mt][nt][half * 2],
                                        acc[mt][nt][half * 2 + 1]);
                *(float2*)(dst + col) = v2;
            }
        }
    }
}

// ---------------------------------------------------------------------------
// zero colsum
// ---------------------------------------------------------------------------
__global__ void k_zero()
{
    int i = blockIdx.x * 1024 + threadIdx.x;
    if (i < BATCHN * NKV * HD) g_colsum[i] = 0.f;
}

// ---------------------------------------------------------------------------
// K3: k <- exp(rope(k)) in-place; accumulate column sums.
// ---------------------------------------------------------------------------
__global__ __launch_bounds__(256) void k_rope_k(const float* __restrict__ fc)
{
    __shared__ float s_part[8][128];
    int bhk = blockIdx.x;
    int w   = threadIdx.x >> 5;
    int l   = threadIdx.x & 31;
    float sum0 = 0.f, sum1 = 0.f, sum2 = 0.f, sum3 = 0.f;
#pragma unroll
    for (int r = 0; r < 8; r++) {
        int s = blockIdx.y * 64 + w * 8 + r;
        float* rowp = g_k + ((size_t)bhk * SEQL + s) * HD + l * 4;
        float4 v = *(float4*)rowp;
        float4 f = *(const float4*)(fc + (size_t)s * HD + l * 4);
        float o0 = v.x * f.x - v.y * f.y;
        float o1 = v.x * f.y + v.y * f.x;
        float o2 = v.z * f.z - v.w * f.w;
        float o3 = v.z * f.w + v.w * f.z;
        float e0 = expf(o0), e1 = expf(o1), e2 = expf(o2), e3 = expf(o3);
        *(float4*)rowp = make_float4(e0, e1, e2, e3);
        sum0 += e0; sum1 += e1; sum2 += e2; sum3 += e3;
    }
    s_part[w][l * 4 + 0] = sum0;
    s_part[w][l * 4 + 1] = sum1;
    s_part[w][l * 4 + 2] = sum2;
    s_part[w][l * 4 + 3] = sum3;
    __syncthreads();
    if (threadIdx.x < 128) {
        float a = 0.f;
#pragma unroll
        for (int w2 = 0; w2 < 8; w2++) a += s_part[w2][threadIdx.x];
        atomicAdd(&g_colsum[bhk * HD + threadIdx.x], a);
    }
}

// ---------------------------------------------------------------------------
// K2: q <- softmax(rope(q) * D^-1/2) / colsum[hk]  in-place.
// ---------------------------------------------------------------------------
__global__ __launch_bounds__(256) void k_rope_q(const float* __restrict__ fc)
{
    int r = blockIdx.x * 8 + (threadIdx.x >> 5);
    int l = threadIdx.x & 31;
    int s  = r & 2047;
    int bh = r >> 11;
    int h  = bh & 15;
    int b  = bh >> 4;

    float* rowp = g_q + (size_t)r * HD + l * 4;
    float4 v = *(float4*)rowp;
    float4 f = *(const float4*)(fc + (size_t)s * HD + l * 4);
    const float scale = 0.08838834764831845f;
    float o0 = (v.x * f.x - v.y * f.y) * scale;
    float o1 = (v.x * f.y + v.y * f.x) * scale;
    float o2 = (v.z * f.z - v.w * f.w) * scale;
    float o3 = (v.z * f.w + v.w * f.z) * scale;

    float mx = fmaxf(fmaxf(o0, o1), fmaxf(o2, o3));
#pragma unroll
    for (int off = 16; off; off >>= 1) mx = fmaxf(mx, __shfl_xor_sync(0xffffffffu, mx, off));
    float e0 = expf(o0 - mx), e1 = expf(o1 - mx), e2 = expf(o2 - mx), e3 = expf(o3 - mx);
    float ss = e0 + e1 + e2 + e3;
#pragma unroll
    for (int off = 16; off; off >>= 1) ss += __shfl_xor_sync(0xffffffffu, ss, off);
    float inv = 1.f / ss;

    const float* csp = g_colsum + ((b * NKV + (h >> 1)) * HD) + l * 4;
    float4 cs = *(const float4*)csp;
    *(float4*)rowp = make_float4(e0 * inv / cs.x, e1 * inv / cs.y,
                                 e2 * inv / cs.z, e3 * inv / cs.w);
}

// ---------------------------------------------------------------------------
// K4: per-chunk kv = ek_c^T @ v_c  (128x128, K=128).
// ---------------------------------------------------------------------------
__global__ __launch_bounds__(256) void k_kvchunk()
{
    __shared__ float As[16][128];
    __shared__ float Bs[16][128];
    int bhk = blockIdx.x >> 4;
    int n   = blockIdx.x & 15;
    const float* ekc = g_k + ((size_t)bhk * SEQL + n * CHK) * HD;
    const float* vc  = g_v + ((size_t)bhk * SEQL + n * CHK) * HD;
    int t = threadIdx.x, ty = t >> 4, tx = t & 15;
    float acc[8][8];
#pragma unroll
    for (int i = 0; i < 8; i++)
#pragma unroll
        for (int j = 0; j < 8; j++) acc[i][j] = 0.f;

    for (int s0 = 0; s0 < 128; s0 += 16) {
#pragma unroll
        for (int it = 0; it < 2; it++) {
            int p = it * 256 + t;
            int row = p >> 5, c4 = (p & 31) * 4;
            *(float4*)&As[row][c4] = *(const float4*)(ekc + (size_t)(s0 + row) * HD + c4);
            *(float4*)&Bs[row][c4] = *(const float4*)(vc  + (size_t)(s0 + row) * HD + c4);
        }
        __syncthreads();
#pragma unroll
        for (int kk = 0; kk < 16; kk++) {
            float a[8], b[8];
            float4 t0 = *(const float4*)&As[kk][ty * 8];
            float4 t1 = *(const float4*)&As[kk][ty * 8 + 4];
            a[0]=t0.x; a[1]=t0.y; a[2]=t0.z; a[3]=t0.w;
            a[4]=t1.x; a[5]=t1.y; a[6]=t1.z; a[7]=t1.w;
            float4 u0 = *(const float4*)&Bs[kk][tx * 8];
            float4 u1 = *(const float4*)&Bs[kk][tx * 8 + 4];
            b[0]=u0.x; b[1]=u0.y; b[2]=u0.z; b[3]=u0.w;
            b[4]=u1.x; b[5]=u1.y; b[6]=u1.z; b[7]=u1.w;
#pragma unroll
            for (int i = 0; i < 8; i++)
#pragma unroll
                for (int j = 0; j < 8; j++) acc[i][j] += a[i] * b[j];
        }
        __syncthreads();
    }
    size_t base = ((size_t)bhk * NCH + n) * HD * HD;
#pragma unroll
    for (int i = 0; i < 8; i++) {
        float* rp = g_kv + base + (size_t)(ty * 8 + i) * HD + tx * 8;
        *(float4*)(rp)     = make_float4(acc[i][0], acc[i][1], acc[i][2], acc[i][3]);
        *(float4*)(rp + 4) = make_float4(acc[i][4], acc[i][5], acc[i][6], acc[i][7]);
    }
}

// ---------------------------------------------------------------------------
// K5: exclusive prefix sum over chunks.
// ---------------------------------------------------------------------------
__global__ void k_prefix()
{
    int bhk  = blockIdx.x;
    int elem = blockIdx.y * 256 + threadIdx.x;
    size_t base = (size_t)bhk * NCH * (HD * HD) + elem;
    float acc = 0.f;
#pragma unroll
    for (int n = 0; n < NCH; n++) {
        g_cum[base + (size_t)n * (HD * HD)] = acc;
        acc += g_kv[base + (size_t)n * (HD * HD)];
    }
}

// ---------------------------------------------------------------------------
// K6: per-(b,h,chunk) attention. Epilogue writes A-style 3-term bf16 directly
// into g_a2 (skips the fp32 g_attn round-trip).
// ---------------------------------------------------------------------------
#define QSTR 132
#define ATTN_SMEM ((2 * 128 * QSTR + 16 * 128) * 4)

__global__ __launch_bounds__(256) void k_attn()
{
    extern __shared__ float sm[];
    float* qsT = sm;
    float* scT = sm + 128 * QSTR;
    float* Bst = sm + 2 * 128 * QSTR;

    int bid = blockIdx.x;
    int b = bid >> 8;
    int h = (bid >> 4) & 15;
    int n = bid & 15;
    int hk = h >> 1;
    int t = threadIdx.x, ty = t >> 4, tx = t & 15;

    const float* qb  = g_q + (((size_t)(b * NH  + h ) * SEQL) + n * CHK) * HD;
    const float* ekb = g_k + (((size_t)(b * NKV + hk) * SEQL) + n * CHK) * HD;
    const float* vb  = g_v + (((size_t)(b * NKV + hk) * SEQL) + n * CHK) * HD;
    const float* cb  = g_cum + ((size_t)(b * NKV + hk) * NCH + n) * (HD * HD);

#pragma unroll
    for (int it = 0; it < 16; it++) {
        int p = it * 256 + t;
        int c = p >> 5;
        int d4 = (p & 31) * 4;
        float4 v4 = *(const float4*)(qb + (size_t)c * HD + d4);
        qsT[(d4 + 0) * QSTR + c] = v4.x;
        qsT[(d4 + 1) * QSTR + c] = v4.y;
        qsT[(d4 + 2) * QSTR + c] = v4.z;
        qsT[(d4 + 3) * QSTR + c] = v4.w;
    }
    __syncthreads();

    float acc[8][8];
#pragma unroll
    for (int i = 0; i < 8; i++)
#pragma unroll
        for (int j = 0; j < 8; j++) acc[i][j] = 0.f;

    for (int d0 = 0; d0 < 128; d0 += 16) {
#pragma unroll
        for (int it = 0; it < 2; it++) {
            int p = it * 256 + t;
            int m = p >> 2;
            int dq = (p & 3) * 4;
            float4 v4 = *(const float4*)(ekb + (size_t)m * HD + d0 + dq);
            Bst[(dq + 0) * 128 + m] = v4.x;
            Bst[(dq + 1) * 128 + m] = v4.y;
            Bst[(dq + 2) * 128 + m] = v4.z;
            Bst[(dq + 3) * 128 + m] = v4.w;
        }
        __syncthreads();
#pragma unroll
        for (int kk = 0; kk < 16; kk++) {
            float a[8], b[8];
            float4 t0 = *(const float4*)&Bst[kk * 128 + ty * 8];
            float4 t1 = *(const float4*)&Bst[kk * 128 + ty * 8 + 4];
            a[0]=t0.x; a[1]=t0.y; a[2]=t0.z; a[3]=t0.w;
            a[4]=t1.x; a[5]=t1.y; a[6]=t1.z; a[7]=t1.w;
            float4 u0 = *(const float4*)&qsT[(d0 + kk) * QSTR + tx * 8];
            float4 u1 = *(const float4*)&qsT[(d0 + kk) * QSTR + tx * 8 + 4];
            b[0]=u0.x; b[1]=u0.y; b[2]=u0.z; b[3]=u0.w;
            b[4]=u1.x; b[5]=u1.y; b[6]=u1.z; b[7]=u1.w;
#pragma unroll
            for (int i = 0; i < 8; i++)
#pragma unroll
                for (int j = 0; j < 8; j++) acc[i][j] += a[i] * b[j];
        }
        __syncthreads();
    }

#pragma unroll
    for (int i = 0; i < 8; i++) {
        int m = ty * 8 + i;
        float r[8];
#pragma unroll
        for (int j = 0; j < 8; j++) {
            int c = tx * 8 + j;
            r[j] = (m <= c) ? acc[i][j] : 0.f;
            acc[i][j] = 0.f;
        }
        *(float4*)&scT[m * QSTR + tx * 8]     = make_float4(r[0], r[1], r[2], r[3]);
        *(float4*)&scT[m * QSTR + tx * 8 + 4] = make_float4(r[4], r[5], r[6], r[7]);
    }
    __syncthreads();

    for (int m0 = 0; m0 < 128; m0 += 16) {
#pragma unroll
        for (int it = 0; it < 2; it++) {
            int p = it * 256 + t;
            int row = p >> 5, e4 = (p & 31) * 4;
            *(float4*)&Bst[row * 128 + e4] =
                *(const float4*)(vb + (size_t)(m0 + row) * HD + e4);
        }
        __syncthreads();
#pragma unroll
        for (int kk = 0; kk < 16; kk++) {
            float a[8], b[8];
            float4 t0 = *(const float4*)&scT[(m0 + kk) * QSTR + ty * 8];
            float4 t1 = *(const float4*)&scT[(m0 + kk) * QSTR + ty * 8 + 4];
            a[0]=t0.x; a[1]=t0.y; a[2]=t0.z; a[3]=t0.w;
            a[4]=t1.x; a[5]=t1.y; a[6]=t1.z; a[7]=t1.w;
            float4 u0 = *(const float4*)&Bst[kk * 128 + tx * 8];
            float4 u1 = *(const float4*)&Bst[kk * 128 + tx * 8 + 4];
            b[0]=u0.x; b[1]=u0.y; b[2]=u0.z; b[3]=u0.w;
            b[4]=u1.x; b[5]=u1.y; b[6]=u1.z; b[7]=u1.w;
#pragma unroll
            for (int i = 0; i < 8; i++)
#pragma unroll
                for (int j = 0; j < 8; j++) acc[i][j] += a[i] * b[j];
        }
        __syncthreads();
    }

    for (int d0 = 0; d0 < 128; d0 += 16) {
#pragma unroll
        for (int it = 0; it < 2; it++) {
            int p = it * 256 + t;
            int row = p >> 5, e4 = (p & 31) * 4;
            *(float4*)&Bst[row * 128 + e4] =
                *(const float4*)(cb + (size_t)(d0 + row) * HD + e4);
        }
        __syncthreads();
#pragma unroll
        for (int kk = 0; kk < 16; kk++) {
            float a[8], b[8];
            float4 t0 = *(const float4*)&qsT[(d0 + kk) * QSTR + ty * 8];
            float4 t1 = *(const float4*)&qsT[(d0 + kk) * QSTR + ty * 8 + 4];
            a[0]=t0.x; a[1]=t0.y; a[2]=t0.z; a[3]=t0.w;
            a[4]=t1.x; a[5]=t1.y; a[6]=t1.z; a[7]=t1.w;
            float4 u0 = *(const float4*)&Bst[kk * 128 + tx * 8];
            float4 u1 = *(const float4*)&Bst[kk * 128 + tx * 8 + 4];
            b[0]=u0.x; b[1]=u0.y; b[2]=u0.z; b[3]=u0.w;
            b[4]=u1.x; b[5]=u1.y; b[6]=u1.z; b[7]=u1.w;
#pragma unroll
            for (int i = 0; i < 8; i++)
#pragma unroll
                for (int j = 0; j < 8; j++) acc[i][j] += a[i] * b[j];
        }
        __syncthreads();
    }

    // epilogue: split to 3-term bf16 (A-style) directly into g_a2
#pragma unroll
    for (int i = 0; i < 8; i++) {
        int c = ty * 8 + i;
        int s = n * CHK + c;
        unsigned short* op = g_a2 + (size_t)(b * SEQL + s) * KP
                                  + (size_t)3 * (h * HD + tx * 8);
        __align__(16) __nv_bfloat16 o[24];
#pragma unroll
        for (int j = 0; j < 8; j++) {
            float f = acc[i][j];
            __nv_bfloat16 hh = __float2bfloat16(f);
            __nv_bfloat16 ll = __float2bfloat16(f - __bfloat162float(hh));
            o[3 * j]     = hh;
            o[3 * j + 1] = ll;
            o[3 * j + 2] = hh;
        }
        uint4* d = (uint4*)op;
        d[0] = ((const uint4*)o)[0];
        d[1] = ((const uint4*)o)[1];
        d[2] = ((const uint4*)o)[2];
    }
}

// ---------------------------------------------------------------------------
extern "C" void kernel_launch(void* const* d_in, const int* in_sizes, int n_in,
                              void* d_out, int out_size)
{
    const float* x  = (const float*)d_in[0];
    const float* fc = (const float*)d_in[1];
    const float* wq = (const float*)d_in[2];
    const float* wk = (const float*)d_in[3];
    const float* wv = (const float*)d_in[4];
    const float* wo = (const float*)d_in[5];
    float* out = (float*)d_out;

    cudaFuncSetAttribute(k_attn, cudaFuncAttributeMaxDynamicSharedMemorySize, ATTN_SMEM);
    cudaFuncSetAttribute(k_gemm_mma, cudaFuncAttributeMaxDynamicSharedMemorySize, GEMM_SMEM);

    void *p_x2, *p_w2, *p_a2, *p_wo2;
    cudaGetSymbolAddress(&p_x2, g_x2);
    cudaGetSymbolAddress(&p_w2, g_w2);
    cudaGetSymbolAddress(&p_a2, g_a2);
    cudaGetSymbolAddress(&p_wo2, g_wo2);
    unsigned short* x2  = (unsigned short*)p_x2;
    unsigned short* w2  = (unsigned short*)p_w2;
    unsigned short* a2  = (unsigned short*)p_a2;
    unsigned short* wo2 = (unsigned short*)p_wo2;

    // fp32 -> 3-term bf16 conversions
    k_cvt_a<<<4096, 256>>>(x,  x2);
    k_cvt_b<<<2048, 256>>>(wq, w2);
    k_cvt_b<<<1024, 256>>>(wk, w2 + (size_t)2048 * KP);
    k_cvt_b<<<1024, 256>>>(wv, w2 + (size_t)3072 * KP);

    // QKV projection on HMMA (scatter epilogue). grid: N=4096/128, M=4096/256
    k_gemm_mma<<<dim3(32, 16), 256, GEMM_SMEM>>>(
        (const __nv_bfloat16*)x2, (const __nv_bfloat16*)w2, nullptr, 0);

    // RoPE + softmaxes
    k_zero<<<2, 1024>>>();
    k_rope_k<<<dim3(16, 32), 256>>>(fc);
    k_rope_q<<<8192, 256>>>(fc);

    // chunked linear attention (fp32), writes split-bf16 a2 directly
    k_kvchunk<<<256, 256>>>();
    k_prefix<<<dim3(16, 64), 256>>>();
    k_attn<<<512, 256, ATTN_SMEM>>>();

    // output projection on HMMA. grid: N=2048/128, M=4096/256
    k_cvt_b<<<2048, 256>>>(wo, wo2);
    k_gemm_mma<<<dim3(16, 16), 256, GEMM_SMEM>>>(
        (const __nv_bfloat16*)a2, (const __nv_bfloat16*)wo2, out, 1);
}

// round 6
// speedup vs baseline: 2.7101x; 1.4807x over previous
#include <cuda_runtime.h>
#include <cuda_fp16.h>
#include <cstdint>

// Problem constants
#define BATCHN 2
#define SEQL   2048
#define DIMN   2048
#define NH     16
#define NKV    8
#define HD     128
#define NCH    16
#define CHK    128
#define KP     4096   // fp16 2-term split-K': 2*DIMN
#define BKC    64     // k-chunk (fp16 elems)
#define STR    72     // smem row stride in elems (conflict-free ldmatrix)
#define NITG   (KP / BKC)   // 64

// ---------------------------------------------------------------------------
// Scratch (static device globals — no allocation allowed)
// ---------------------------------------------------------------------------
__device__ float g_q[(size_t)BATCHN * NH * SEQL * HD];
__device__ float g_k[(size_t)BATCHN * NKV * SEQL * HD];
__device__ float g_v[(size_t)BATCHN * NKV * SEQL * HD];
__device__ float g_kv[(size_t)BATCHN * NKV * NCH * HD * HD];
__device__ float g_cum[(size_t)BATCHN * NKV * NCH * HD * HD];
__device__ float g_colsum[BATCHN * NKV * HD];

// fp16 2-term operands (K' = 4096)
__device__ unsigned short g_x2[(size_t)4096 * KP];   // A-style: [hi, lo]
__device__ unsigned short g_w2[(size_t)4096 * KP];   // B-style: [hi, hi]
__device__ unsigned short g_a2[(size_t)4096 * KP];   // A-style (written by k_attn)
__device__ unsigned short g_wo2[(size_t)2048 * KP];  // B-style

// ---------------------------------------------------------------------------
// PTX helpers
// ---------------------------------------------------------------------------
__device__ __forceinline__ uint32_t smem_u32(const void* p) {
    uint32_t a;
    asm("{ .reg .u64 t; cvta.to.shared.u64 t, %1; cvt.u32.u64 %0, t; }"
        : "=r"(a) : "l"(p));
    return a;
}
__device__ __forceinline__ void ldm_x4(uint32_t* r, uint32_t addr) {
    asm volatile("ldmatrix.sync.aligned.m8n8.x4.shared.b16 {%0,%1,%2,%3}, [%4];"
                 : "=r"(r[0]), "=r"(r[1]), "=r"(r[2]), "=r"(r[3]) : "r"(addr));
}
__device__ __forceinline__ void mma_16816(float* c, const uint32_t* a,
                                          uint32_t b0, uint32_t b1) {
    asm volatile(
        "mma.sync.aligned.m16n8k16.row.col.f32.f16.f16.f32 "
        "{%0,%1,%2,%3}, {%4,%5,%6,%7}, {%8,%9}, {%0,%1,%2,%3};"
        : "+f"(c[0]), "+f"(c[1]), "+f"(c[2]), "+f"(c[3])
        : "r"(a[0]), "r"(a[1]), "r"(a[2]), "r"(a[3]), "r"(b0), "r"(b1));
}
__device__ __forceinline__ void cp16(uint32_t s, const void* g) {
    asm volatile("cp.async.cg.shared.global [%0], [%1], 16;" :: "r"(s), "l"(g));
}
__device__ __forceinline__ void cp_commit() {
    asm volatile("cp.async.commit_group;" ::: "memory");
}
template <int N> __device__ __forceinline__ void cp_wait() {
    asm volatile("cp.async.wait_group %0;" :: "n"(N) : "memory");
}

// ---------------------------------------------------------------------------
// fp32 -> fp16 2-term splits.
//   A-style: [hi, lo]  (hi = fp16(x), lo = fp16(x - hi); hi+lo == x to 2^-22)
//   B-style: [hi, hi]
// Aligned dot = a_hi*b_hi + a_lo*b_hi = a * b_hi  (error = a*(b-b_hi) ~ 2^-11)
// ---------------------------------------------------------------------------
__global__ __launch_bounds__(256) void k_cvt_a(const float* __restrict__ src,
                                               unsigned short* __restrict__ dst)
{
    size_t i = ((size_t)blockIdx.x * 256 + threadIdx.x) * 8;
    float4 v0 = *(const float4*)(src + i);
    float4 v1 = *(const float4*)(src + i + 4);
    float f[8] = {v0.x, v0.y, v0.z, v0.w, v1.x, v1.y, v1.z, v1.w};
    __align__(16) __half o[16];
#pragma unroll
    for (int j = 0; j < 8; j++) {
        __half hh = __float2half(f[j]);
        __half ll = __float2half(f[j] - __half2float(hh));
        o[2 * j]     = hh;
        o[2 * j + 1] = ll;
    }
    uint4* d = (uint4*)(dst + i * 2);
    d[0] = ((const uint4*)o)[0];
    d[1] = ((const uint4*)o)[1];
}

__global__ __launch_bounds__(256) void k_cvt_b(const float* __restrict__ src,
                                               unsigned short* __restrict__ dst)
{
    size_t i = ((size_t)blockIdx.x * 256 + threadIdx.x) * 8;
    float4 v0 = *(const float4*)(src + i);
    float4 v1 = *(const float4*)(src + i + 4);
    float f[8] = {v0.x, v0.y, v0.z, v0.w, v1.x, v1.y, v1.z, v1.w};
    __align__(16) __half o[16];
#pragma unroll
    for (int j = 0; j < 8; j++) {
        __half hh = __float2half(f[j]);
        o[2 * j]     = hh;
        o[2 * j + 1] = hh;
    }
    uint4* d = (uint4*)(dst + i * 2);
    d[0] = ((const uint4*)o)[0];
    d[1] = ((const uint4*)o)[1];
}

// ---------------------------------------------------------------------------
// HMMA fp16 GEMM: C[M,N] = A2[M,K'] @ B2[N,K']^T, fp32 accum.
// 128x128 CTA tile, 128 threads (4 warps, 2x2), 64x64 warp tile, BK=64,
// 3-stage cp.async pipeline, single __syncthreads per iteration, 2 CTAs/SM.
// mode 0: scatter into g_q/g_k/g_v.  mode 1: row-major C (ldc = DIMN).
// ---------------------------------------------------------------------------
#define A_BUF (128 * STR)
#define B_BUF (128 * STR)
#define GEMM_SMEM ((3 * (A_BUF + B_BUF)) * 2)   // 110592 bytes

__global__ __launch_bounds__(128, 2) void k_gemm_mma(
    const __half* __restrict__ A, const __half* __restrict__ B,
    float* __restrict__ C, int mode)
{
    extern __shared__ char smraw[];
    __half* sA = (__half*)smraw;
    __half* sB = sA + 3 * A_BUF;

    const int t = threadIdx.x, lane = t & 31, wid = t >> 5;
    const int wm = wid >> 1, wn = wid & 1;          // warp grid 2 x 2
    const int m0 = blockIdx.y * 128, n0 = blockIdx.x * 128;

    uint32_t sAb = smem_u32(sA);
    uint32_t sBb = smem_u32(sB);

    const __half* ga = A + (size_t)(m0 + (t >> 3)) * KP + (t & 7) * 8;
    const __half* gb = B + (size_t)(n0 + (t >> 3)) * KP + (t & 7) * 8;
    const uint32_t so = ((uint32_t)(t >> 3) * STR + (t & 7) * 8) * 2;

    auto load_tile = [&](int buf, int i) {
        uint32_t sa = sAb + (uint32_t)buf * A_BUF * 2 + so;
        uint32_t sb = sBb + (uint32_t)buf * B_BUF * 2 + so;
        int ko = i * BKC;
#pragma unroll
        for (int j = 0; j < 8; j++)
            cp16(sa + j * 16 * STR * 2, ga + (size_t)j * 16 * KP + ko);
#pragma unroll
        for (int j = 0; j < 8; j++)
            cp16(sb + j * 16 * STR * 2, gb + (size_t)j * 16 * KP + ko);
        cp_commit();
    };

    float acc[4][8][4];
#pragma unroll
    for (int i = 0; i < 4; i++)
#pragma unroll
        for (int j = 0; j < 8; j++)
#pragma unroll
            for (int r = 0; r < 4; r++) acc[i][j][r] = 0.f;

    const int lr = lane & 7;
    const int lm = (lane >> 3) & 1;
    const int lc = lane >> 4;

    load_tile(0, 0);
    load_tile(1, 1);

    for (int i = 0; i < NITG; i++) {
        if (i == NITG - 1) cp_wait<0>(); else cp_wait<1>();
        __syncthreads();

        int buf = i % 3;
        uint32_t sa = sAb + (uint32_t)buf * A_BUF * 2;
        uint32_t sb = sBb + (uint32_t)buf * B_BUF * 2;
#pragma unroll
        for (int ks = 0; ks < 4; ks++) {
            uint32_t afr[4][4], bfr[4][4];
            const uint32_t coff = ((uint32_t)(ks * 16 + lc * 8)) * 2;
#pragma unroll
            for (int mt = 0; mt < 4; mt++)
                ldm_x4(afr[mt],
                       sa + ((uint32_t)(wm * 64 + mt * 16 + lr + lm * 8) * STR) * 2 + coff);
#pragma unroll
            for (int nt2 = 0; nt2 < 4; nt2++)
                ldm_x4(bfr[nt2],
                       sb + ((uint32_t)(wn * 64 + nt2 * 16 + lr + lm * 8) * STR) * 2 + coff);
#pragma unroll
            for (int mt = 0; mt < 4; mt++)
#pragma unroll
                for (int nt = 0; nt < 8; nt++)
                    mma_16816(acc[mt][nt], afr[mt],
                              bfr[nt >> 1][nt & 1], bfr[nt >> 1][(nt & 1) + 2]);
        }

        if (i + 2 < NITG) load_tile((i + 2) % 3, i + 2);
    }

    // epilogue
    const int g = lane >> 2, c2 = (lane & 3) * 2;
#pragma unroll
    for (int mt = 0; mt < 4; mt++) {
#pragma unroll
        for (int half = 0; half < 2; half++) {
            int m = m0 + wm * 64 + mt * 16 + g + half * 8;
            float* dst;
            if (mode == 0) {
                int b = m >> 11, s = m & 2047;
                int ht = n0 >> 7;
                if (ht < 16)
                    dst = g_q + (((size_t)(b * NH + ht)) * SEQL + s) * HD;
                else if (ht < 24)
                    dst = g_k + (((size_t)(b * NKV + (ht - 16))) * SEQL + s) * HD;
                else
                    dst = g_v + (((size_t)(b * NKV + (ht - 24))) * SEQL + s) * HD;
            } else {
                dst = C + (size_t)m * DIMN + n0;
            }
#pragma unroll
            for (int nt = 0; nt < 8; nt++) {
                int col = wn * 64 + nt * 8 + c2;
                float2 v2 = make_float2(acc[mt][nt][half * 2],
                                        acc[mt][nt][half * 2 + 1]);
                *(float2*)(dst + col) = v2;
            }
        }
    }
}

// ---------------------------------------------------------------------------
// zero colsum
// ---------------------------------------------------------------------------
__global__ void k_zero()
{
    int i = blockIdx.x * 1024 + threadIdx.x;
    if (i < BATCHN * NKV * HD) g_colsum[i] = 0.f;
}

// ---------------------------------------------------------------------------
// K3: k <- exp(rope(k)) in-place; accumulate column sums.
// ---------------------------------------------------------------------------
__global__ __launch_bounds__(256) void k_rope_k(const float* __restrict__ fc)
{
    __shared__ float s_part[8][128];
    int bhk = blockIdx.x;
    int w   = threadIdx.x >> 5;
    int l   = threadIdx.x & 31;
    float sum0 = 0.f, sum1 = 0.f, sum2 = 0.f, sum3 = 0.f;
#pragma unroll
    for (int r = 0; r < 8; r++) {
        int s = blockIdx.y * 64 + w * 8 + r;
        float* rowp = g_k + ((size_t)bhk * SEQL + s) * HD + l * 4;
        float4 v = *(float4*)rowp;
        float4 f = *(const float4*)(fc + (size_t)s * HD + l * 4);
        float o0 = v.x * f.x - v.y * f.y;
        float o1 = v.x * f.y + v.y * f.x;
        float o2 = v.z * f.z - v.w * f.w;
        float o3 = v.z * f.w + v.w * f.z;
        float e0 = expf(o0), e1 = expf(o1), e2 = expf(o2), e3 = expf(o3);
        *(float4*)rowp = make_float4(e0, e1, e2, e3);
        sum0 += e0; sum1 += e1; sum2 += e2; sum3 += e3;
    }
    s_part[w][l * 4 + 0] = sum0;
    s_part[w][l * 4 + 1] = sum1;
    s_part[w][l * 4 + 2] = sum2;
    s_part[w][l * 4 + 3] = sum3;
    __syncthreads();
    if (threadIdx.x < 128) {
        float a = 0.f;
#pragma unroll
        for (int w2 = 0; w2 < 8; w2++) a += s_part[w2][threadIdx.x];
        atomicAdd(&g_colsum[bhk * HD + threadIdx.x], a);
    }
}

// ---------------------------------------------------------------------------
// K2: q <- softmax(rope(q) * D^-1/2) / colsum[hk]  in-place.
// ---------------------------------------------------------------------------
__global__ __launch_bounds__(256) void k_rope_q(const float* __restrict__ fc)
{
    int r = blockIdx.x * 8 + (threadIdx.x >> 5);
    int l = threadIdx.x & 31;
    int s  = r & 2047;
    int bh = r >> 11;
    int h  = bh & 15;
    int b  = bh >> 4;

    float* rowp = g_q + (size_t)r * HD + l * 4;
    float4 v = *(float4*)rowp;
    float4 f = *(const float4*)(fc + (size_t)s * HD + l * 4);
    const float scale = 0.08838834764831845f;
    float o0 = (v.x * f.x - v.y * f.y) * scale;
    float o1 = (v.x * f.y + v.y * f.x) * scale;
    float o2 = (v.z * f.z - v.w * f.w) * scale;
    float o3 = (v.z * f.w + v.w * f.z) * scale;

    float mx = fmaxf(fmaxf(o0, o1), fmaxf(o2, o3));
#pragma unroll
    for (int off = 16; off; off >>= 1) mx = fmaxf(mx, __shfl_xor_sync(0xffffffffu, mx, off));
    float e0 = expf(o0 - mx), e1 = expf(o1 - mx), e2 = expf(o2 - mx), e3 = expf(o3 - mx);
    float ss = e0 + e1 + e2 + e3;
#pragma unroll
    for (int off = 16; off; off >>= 1) ss += __shfl_xor_sync(0xffffffffu, ss, off);
    float inv = 1.f / ss;

    const float* csp = g_colsum + ((b * NKV + (h >> 1)) * HD) + l * 4;
    float4 cs = *(const float4*)csp;
    *(float4*)rowp = make_float4(e0 * inv / cs.x, e1 * inv / cs.y,
                                 e2 * inv / cs.z, e3 * inv / cs.w);
}

// ---------------------------------------------------------------------------
// K4: per-chunk kv = ek_c^T @ v_c  (128x128, K=128).
// ---------------------------------------------------------------------------
__global__ __launch_bounds__(256) void k_kvchunk()
{
    __shared__ float As[16][128];
    __shared__ float Bs[16][128];
    int bhk = blockIdx.x >> 4;
    int n   = blockIdx.x & 15;
    const float* ekc = g_k + ((size_t)bhk * SEQL + n * CHK) * HD;
    const float* vc  = g_v + ((size_t)bhk * SEQL + n * CHK) * HD;
    int t = threadIdx.x, ty = t >> 4, tx = t & 15;
    float acc[8][8];
#pragma unroll
    for (int i = 0; i < 8; i++)
#pragma unroll
        for (int j = 0; j < 8; j++) acc[i][j] = 0.f;

    for (int s0 = 0; s0 < 128; s0 += 16) {
#pragma unroll
        for (int it = 0; it < 2; it++) {
            int p = it * 256 + t;
            int row = p >> 5, c4 = (p & 31) * 4;
            *(float4*)&As[row][c4] = *(const float4*)(ekc + (size_t)(s0 + row) * HD + c4);
            *(float4*)&Bs[row][c4] = *(const float4*)(vc  + (size_t)(s0 + row) * HD + c4);
        }
        __syncthreads();
#pragma unroll
        for (int kk = 0; kk < 16; kk++) {
            float a[8], b[8];
            float4 t0 = *(const float4*)&As[kk][ty * 8];
            float4 t1 = *(const float4*)&As[kk][ty * 8 + 4];
            a[0]=t0.x; a[1]=t0.y; a[2]=t0.z; a[3]=t0.w;
            a[4]=t1.x; a[5]=t1.y; a[6]=t1.z; a[7]=t1.w;
            float4 u0 = *(const float4*)&Bs[kk][tx * 8];
            float4 u1 = *(const float4*)&Bs[kk][tx * 8 + 4];
            b[0]=u0.x; b[1]=u0.y; b[2]=u0.z; b[3]=u0.w;
            b[4]=u1.x; b[5]=u1.y; b[6]=u1.z; b[7]=u1.w;
#pragma unroll
            for (int i = 0; i < 8; i++)
#pragma unroll
                for (int j = 0; j < 8; j++) acc[i][j] += a[i] * b[j];
        }
        __syncthreads();
    }
    size_t base = ((size_t)bhk * NCH + n) * HD * HD;
#pragma unroll
    for (int i = 0; i < 8; i++) {
        float* rp = g_kv + base + (size_t)(ty * 8 + i) * HD + tx * 8;
        *(float4*)(rp)     = make_float4(acc[i][0], acc[i][1], acc[i][2], acc[i][3]);
        *(float4*)(rp + 4) = make_float4(acc[i][4], acc[i][5], acc[i][6], acc[i][7]);
    }
}

// ---------------------------------------------------------------------------
// K5: exclusive prefix sum over chunks.
// ---------------------------------------------------------------------------
__global__ void k_prefix()
{
    int bhk  = blockIdx.x;
    int elem = blockIdx.y * 256 + threadIdx.x;
    size_t base = (size_t)bhk * NCH * (HD * HD) + elem;
    float acc = 0.f;
#pragma unroll
    for (int n = 0; n < NCH; n++) {
        g_cum[base + (size_t)n * (HD * HD)] = acc;
        acc += g_kv[base + (size_t)n * (HD * HD)];
    }
}

// ---------------------------------------------------------------------------
// K6: per-(b,h,chunk) attention. Epilogue writes A-style fp16 [hi,lo] pairs
// directly into g_a2.
// ---------------------------------------------------------------------------
#define QSTR 132
#define ATTN_SMEM ((2 * 128 * QSTR + 16 * 128) * 4)

__global__ __launch_bounds__(256) void k_attn()
{
    extern __shared__ float sm[];
    float* qsT = sm;
    float* scT = sm + 128 * QSTR;
    float* Bst = sm + 2 * 128 * QSTR;

    int bid = blockIdx.x;
    int b = bid >> 8;
    int h = (bid >> 4) & 15;
    int n = bid & 15;
    int hk = h >> 1;
    int t = threadIdx.x, ty = t >> 4, tx = t & 15;

    const float* qb  = g_q + (((size_t)(b * NH  + h ) * SEQL) + n * CHK) * HD;
    const float* ekb = g_k + (((size_t)(b * NKV + hk) * SEQL) + n * CHK) * HD;
    const float* vb  = g_v + (((size_t)(b * NKV + hk) * SEQL) + n * CHK) * HD;
    const float* cb  = g_cum + ((size_t)(b * NKV + hk) * NCH + n) * (HD * HD);

#pragma unroll
    for (int it = 0; it < 16; it++) {
        int p = it * 256 + t;
        int c = p >> 5;
        int d4 = (p & 31) * 4;
        float4 v4 = *(const float4*)(qb + (size_t)c * HD + d4);
        qsT[(d4 + 0) * QSTR + c] = v4.x;
        qsT[(d4 + 1) * QSTR + c] = v4.y;
        qsT[(d4 + 2) * QSTR + c] = v4.z;
        qsT[(d4 + 3) * QSTR + c] = v4.w;
    }
    __syncthreads();

    float acc[8][8];
#pragma unroll
    for (int i = 0; i < 8; i++)
#pragma unroll
        for (int j = 0; j < 8; j++) acc[i][j] = 0.f;

    for (int d0 = 0; d0 < 128; d0 += 16) {
#pragma unroll
        for (int it = 0; it < 2; it++) {
            int p = it * 256 + t;
            int m = p >> 2;
            int dq = (p & 3) * 4;
            float4 v4 = *(const float4*)(ekb + (size_t)m * HD + d0 + dq);
            Bst[(dq + 0) * 128 + m] = v4.x;
            Bst[(dq + 1) * 128 + m] = v4.y;
            Bst[(dq + 2) * 128 + m] = v4.z;
            Bst[(dq + 3) * 128 + m] = v4.w;
        }
        __syncthreads();
#pragma unroll
        for (int kk = 0; kk < 16; kk++) {
            float a[8], b[8];
            float4 t0 = *(const float4*)&Bst[kk * 128 + ty * 8];
            float4 t1 = *(const float4*)&Bst[kk * 128 + ty * 8 + 4];
            a[0]=t0.x; a[1]=t0.y; a[2]=t0.z; a[3]=t0.w;
            a[4]=t1.x; a[5]=t1.y; a[6]=t1.z; a[7]=t1.w;
            float4 u0 = *(const float4*)&qsT[(d0 + kk) * QSTR + tx * 8];
            float4 u1 = *(const float4*)&qsT[(d0 + kk) * QSTR + tx * 8 + 4];
            b[0]=u0.x; b[1]=u0.y; b[2]=u0.z; b[3]=u0.w;
            b[4]=u1.x; b[5]=u1.y; b[6]=u1.z; b[7]=u1.w;
#pragma unroll
            for (int i = 0; i < 8; i++)
#pragma unroll
                for (int j = 0; j < 8; j++) acc[i][j] += a[i] * b[j];
        }
        __syncthreads();
    }

#pragma unroll
    for (int i = 0; i < 8; i++) {
        int m = ty * 8 + i;
        float r[8];
#pragma unroll
        for (int j = 0; j < 8; j++) {
            int c = tx * 8 + j;
            r[j] = (m <= c) ? acc[i][j] : 0.f;
            acc[i][j] = 0.f;
        }
        *(float4*)&scT[m * QSTR + tx * 8]     = make_float4(r[0], r[1], r[2], r[3]);
        *(float4*)&scT[m * QSTR + tx * 8 + 4] = make_float4(r[4], r[5], r[6], r[7]);
    }
    __syncthreads();

    for (int m0 = 0; m0 < 128; m0 += 16) {
#pragma unroll
        for (int it = 0; it < 2; it++) {
            int p = it * 256 + t;
            int row = p >> 5, e4 = (p & 31) * 4;
            *(float4*)&Bst[row * 128 + e4] =
                *(const float4*)(vb + (size_t)(m0 + row) * HD + e4);
        }
        __syncthreads();
#pragma unroll
        for (int kk = 0; kk < 16; kk++) {
            float a[8], b[8];
            float4 t0 = *(const float4*)&scT[(m0 + kk) * QSTR + ty * 8];
            float4 t1 = *(const float4*)&scT[(m0 + kk) * QSTR + ty * 8 + 4];
            a[0]=t0.x; a[1]=t0.y; a[2]=t0.z; a[3]=t0.w;
            a[4]=t1.x; a[5]=t1.y; a[6]=t1.z; a[7]=t1.w;
            float4 u0 = *(const float4*)&Bst[kk * 128 + tx * 8];
            float4 u1 = *(const float4*)&Bst[kk * 128 + tx * 8 + 4];
            b[0]=u0.x; b[1]=u0.y; b[2]=u0.z; b[3]=u0.w;
            b[4]=u1.x; b[5]=u1.y; b[6]=u1.z; b[7]=u1.w;
#pragma unroll
            for (int i = 0; i < 8; i++)
#pragma unroll
                for (int j = 0; j < 8; j++) acc[i][j] += a[i] * b[j];
        }
        __syncthreads();
    }

    for (int d0 = 0; d0 < 128; d0 += 16) {
#pragma unroll
        for (int it = 0; it < 2; it++) {
            int p = it * 256 + t;
            int row = p >> 5, e4 = (p & 31) * 4;
            *(float4*)&Bst[row * 128 + e4] =
                *(const float4*)(cb + (size_t)(d0 + row) * HD + e4);
        }
        __syncthreads();
#pragma unroll
        for (int kk = 0; kk < 16; kk++) {
            float a[8], b[8];
            float4 t0 = *(const float4*)&qsT[(d0 + kk) * QSTR + ty * 8];
            float4 t1 = *(const float4*)&qsT[(d0 + kk) * QSTR + ty * 8 + 4];
            a[0]=t0.x; a[1]=t0.y; a[2]=t0.z; a[3]=t0.w;
            a[4]=t1.x; a[5]=t1.y; a[6]=t1.z; a[7]=t1.w;
            float4 u0 = *(const float4*)&Bst[kk * 128 + tx * 8];
            float4 u1 = *(const float4*)&Bst[kk * 128 + tx * 8 + 4];
            b[0]=u0.x; b[1]=u0.y; b[2]=u0.z; b[3]=u0.w;
            b[4]=u1.x; b[5]=u1.y; b[6]=u1.z; b[7]=u1.w;
#pragma unroll
            for (int i = 0; i < 8; i++)
#pragma unroll
                for (int j = 0; j < 8; j++) acc[i][j] += a[i] * b[j];
        }
        __syncthreads();
    }

    // epilogue: fp16 [hi, lo] pairs directly into g_a2
#pragma unroll
    for (int i = 0; i < 8; i++) {
        int c = ty * 8 + i;
        int s = n * CHK + c;
        unsigned short* op = g_a2 + (size_t)(b * SEQL + s) * KP
                                  + (size_t)2 * (h * HD + tx * 8);
        __align__(16) __half o[16];
#pragma unroll
        for (int j = 0; j < 8; j++) {
            float f = acc[i][j];
            __half hh = __float2half(f);
            __half ll = __float2half(f - __half2float(hh));
            o[2 * j]     = hh;
            o[2 * j + 1] = ll;
        }
        uint4* d = (uint4*)op;
        d[0] = ((const uint4*)o)[0];
        d[1] = ((const uint4*)o)[1];
    }
}

// ---------------------------------------------------------------------------
extern "C" void kernel_launch(void* const* d_in, const int* in_sizes, int n_in,
                              void* d_out, int out_size)
{
    const float* x  = (const float*)d_in[0];
    const float* fc = (const float*)d_in[1];
    const float* wq = (const float*)d_in[2];
    const float* wk = (const float*)d_in[3];
    const float* wv = (const float*)d_in[4];
    const float* wo = (const float*)d_in[5];
    float* out = (float*)d_out;

    cudaFuncSetAttribute(k_attn, cudaFuncAttributeMaxDynamicSharedMemorySize, ATTN_SMEM);
    cudaFuncSetAttribute(k_gemm_mma, cudaFuncAttributeMaxDynamicSharedMemorySize, GEMM_SMEM);

    void *p_x2, *p_w2, *p_a2, *p_wo2;
    cudaGetSymbolAddress(&p_x2, g_x2);
    cudaGetSymbolAddress(&p_w2, g_w2);
    cudaGetSymbolAddress(&p_a2, g_a2);
    cudaGetSymbolAddress(&p_wo2, g_wo2);
    unsigned short* x2  = (unsigned short*)p_x2;
    unsigned short* w2  = (unsigned short*)p_w2;
    unsigned short* a2  = (unsigned short*)p_a2;
    unsigned short* wo2 = (unsigned short*)p_wo2;

    // fp32 -> fp16 2-term conversions
    k_cvt_a<<<4096, 256>>>(x,  x2);
    k_cvt_b<<<2048, 256>>>(wq, w2);
    k_cvt_b<<<1024, 256>>>(wk, w2 + (size_t)2048 * KP);
    k_cvt_b<<<1024, 256>>>(wv, w2 + (size_t)3072 * KP);
    k_cvt_b<<<2048, 256>>>(wo, wo2);

    // QKV projection on HMMA (scatter epilogue). grid: N=4096/128, M=4096/128
    k_gemm_mma<<<dim3(32, 32), 128, GEMM_SMEM>>>(
        (const __half*)x2, (const __half*)w2, nullptr, 0);

    // RoPE + softmaxes
    k_zero<<<2, 1024>>>();
    k_rope_k<<<dim3(16, 32), 256>>>(fc);
    k_rope_q<<<8192, 256>>>(fc);

    // chunked linear attention (fp32), writes fp16 a2 directly
    k_kvchunk<<<256, 256>>>();
    k_prefix<<<dim3(16, 64), 256>>>();
    k_attn<<<512, 256, ATTN_SMEM>>>();

    // output projection on HMMA. grid: N=2048/128, M=4096/128
    k_gemm_mma<<<dim3(16, 32), 128, GEMM_SMEM>>>(
        (const __half*)a2, (const __half*)wo2, out, 1);
}

// round 7
// speedup vs baseline: 4.1207x; 1.5205x over previous
#include <cuda_runtime.h>
#include <cuda_fp16.h>
#include <cstdint>

// Problem constants
#define BATCHN 2
#define SEQL   2048
#define DIMN   2048
#define NH     16
#define NKV    8
#define HD     128
#define NCH    16
#define CHK    128
#define KP     2048   // plain fp16, K' = K
#define BKC    64     // k-chunk (fp16 elems)
#define STR    72     // smem row stride in elems (conflict-free ldmatrix)
#define NITG   (KP / BKC)   // 32

// ---------------------------------------------------------------------------
// Scratch (static device globals — no allocation allowed)
// ---------------------------------------------------------------------------
__device__ float g_q[(size_t)BATCHN * NH * SEQL * HD];
__device__ float g_k[(size_t)BATCHN * NKV * SEQL * HD];
__device__ float g_v[(size_t)BATCHN * NKV * SEQL * HD];
__device__ float g_kv[(size_t)BATCHN * NKV * NCH * HD * HD];
__device__ float g_cum[(size_t)BATCHN * NKV * NCH * HD * HD];
__device__ float g_colsum[BATCHN * NKV * HD];

// fp16 operands
__device__ unsigned short g_x2[(size_t)4096 * KP];
__device__ unsigned short g_w2[(size_t)4096 * KP];
__device__ unsigned short g_a2[(size_t)4096 * KP];   // written by k_attn
__device__ unsigned short g_wo2[(size_t)2048 * KP];

// ---------------------------------------------------------------------------
// PTX helpers
// ---------------------------------------------------------------------------
__device__ __forceinline__ uint32_t smem_u32(const void* p) {
    uint32_t a;
    asm("{ .reg .u64 t; cvta.to.shared.u64 t, %1; cvt.u32.u64 %0, t; }"
        : "=r"(a) : "l"(p));
    return a;
}
__device__ __forceinline__ void ldm_x4(uint32_t* r, uint32_t addr) {
    asm volatile("ldmatrix.sync.aligned.m8n8.x4.shared.b16 {%0,%1,%2,%3}, [%4];"
                 : "=r"(r[0]), "=r"(r[1]), "=r"(r[2]), "=r"(r[3]) : "r"(addr));
}
__device__ __forceinline__ void mma_16816(float* c, const uint32_t* a,
                                          uint32_t b0, uint32_t b1) {
    asm volatile(
        "mma.sync.aligned.m16n8k16.row.col.f32.f16.f16.f32 "
        "{%0,%1,%2,%3}, {%4,%5,%6,%7}, {%8,%9}, {%0,%1,%2,%3};"
        : "+f"(c[0]), "+f"(c[1]), "+f"(c[2]), "+f"(c[3])
        : "r"(a[0]), "r"(a[1]), "r"(a[2]), "r"(a[3]), "r"(b0), "r"(b1));
}
__device__ __forceinline__ void cp16(uint32_t s, const void* g) {
    asm volatile("cp.async.cg.shared.global [%0], [%1], 16;" :: "r"(s), "l"(g));
}
__device__ __forceinline__ void cp_commit() {
    asm volatile("cp.async.commit_group;" ::: "memory");
}
template <int N> __device__ __forceinline__ void cp_wait() {
    asm volatile("cp.async.wait_group %0;" :: "n"(N) : "memory");
}

// ---------------------------------------------------------------------------
// fp32 -> fp16 conversion (plain). Each thread: 8 floats -> 8 halves.
// ---------------------------------------------------------------------------
__global__ __launch_bounds__(256) void k_cvt(const float* __restrict__ src,
                                             unsigned short* __restrict__ dst)
{
    size_t i = ((size_t)blockIdx.x * 256 + threadIdx.x) * 8;
    float4 v0 = *(const float4*)(src + i);
    float4 v1 = *(const float4*)(src + i + 4);
    float f[8] = {v0.x, v0.y, v0.z, v0.w, v1.x, v1.y, v1.z, v1.w};
    __align__(16) __half o[8];
#pragma unroll
    for (int j = 0; j < 8; j++) o[j] = __float2half(f[j]);
    *(uint4*)(dst + i) = *(const uint4*)o;
}

// ---------------------------------------------------------------------------
// HMMA fp16 GEMM: C[M,N] = A2[M,K] @ B2[N,K]^T, fp32 accum.
// 128x128 CTA tile, 128 threads (4 warps, 2x2), 64x64 warp tile, BK=64,
// 3-stage cp.async pipeline, single __syncthreads per iteration, 2 CTAs/SM.
// mode 0: scatter into g_q/g_k/g_v.  mode 1: row-major C (ldc = DIMN).
// ---------------------------------------------------------------------------
#define A_BUF (128 * STR)
#define B_BUF (128 * STR)
#define GEMM_SMEM ((3 * (A_BUF + B_BUF)) * 2)   // 110592 bytes

__global__ __launch_bounds__(128, 2) void k_gemm_mma(
    const __half* __restrict__ A, const __half* __restrict__ B,
    float* __restrict__ C, int mode)
{
    extern __shared__ char smraw[];
    __half* sA = (__half*)smraw;
    __half* sB = sA + 3 * A_BUF;

    const int t = threadIdx.x, lane = t & 31, wid = t >> 5;
    const int wm = wid >> 1, wn = wid & 1;          // warp grid 2 x 2
    const int m0 = blockIdx.y * 128, n0 = blockIdx.x * 128;

    uint32_t sAb = smem_u32(sA);
    uint32_t sBb = smem_u32(sB);

    const __half* ga = A + (size_t)(m0 + (t >> 3)) * KP + (t & 7) * 8;
    const __half* gb = B + (size_t)(n0 + (t >> 3)) * KP + (t & 7) * 8;
    const uint32_t so = ((uint32_t)(t >> 3) * STR + (t & 7) * 8) * 2;

    auto load_tile = [&](int buf, int i) {
        uint32_t sa = sAb + (uint32_t)buf * A_BUF * 2 + so;
        uint32_t sb = sBb + (uint32_t)buf * B_BUF * 2 + so;
        int ko = i * BKC;
#pragma unroll
        for (int j = 0; j < 8; j++)
            cp16(sa + j * 16 * STR * 2, ga + (size_t)j * 16 * KP + ko);
#pragma unroll
        for (int j = 0; j < 8; j++)
            cp16(sb + j * 16 * STR * 2, gb + (size_t)j * 16 * KP + ko);
        cp_commit();
    };

    float acc[4][8][4];
#pragma unroll
    for (int i = 0; i < 4; i++)
#pragma unroll
        for (int j = 0; j < 8; j++)
#pragma unroll
            for (int r = 0; r < 4; r++) acc[i][j][r] = 0.f;

    const int lr = lane & 7;
    const int lm = (lane >> 3) & 1;
    const int lc = lane >> 4;

    load_tile(0, 0);
    load_tile(1, 1);

    for (int i = 0; i < NITG; i++) {
        if (i == NITG - 1) cp_wait<0>(); else cp_wait<1>();
        __syncthreads();

        int buf = i % 3;
        uint32_t sa = sAb + (uint32_t)buf * A_BUF * 2;
        uint32_t sb = sBb + (uint32_t)buf * B_BUF * 2;
#pragma unroll
        for (int ks = 0; ks < 4; ks++) {
            uint32_t afr[4][4], bfr[4][4];
            const uint32_t coff = ((uint32_t)(ks * 16 + lc * 8)) * 2;
#pragma unroll
            for (int mt = 0; mt < 4; mt++)
                ldm_x4(afr[mt],
                       sa + ((uint32_t)(wm * 64 + mt * 16 + lr + lm * 8) * STR) * 2 + coff);
#pragma unroll
            for (int nt2 = 0; nt2 < 4; nt2++)
                ldm_x4(bfr[nt2],
                       sb + ((uint32_t)(wn * 64 + nt2 * 16 + lr + lm * 8) * STR) * 2 + coff);
#pragma unroll
            for (int mt = 0; mt < 4; mt++)
#pragma unroll
                for (int nt = 0; nt < 8; nt++)
                    mma_16816(acc[mt][nt], afr[mt],
                              bfr[nt >> 1][nt & 1], bfr[nt >> 1][(nt & 1) + 2]);
        }

        if (i + 2 < NITG) load_tile((i + 2) % 3, i + 2);
    }

    // epilogue
    const int g = lane >> 2, c2 = (lane & 3) * 2;
#pragma unroll
    for (int mt = 0; mt < 4; mt++) {
#pragma unroll
        for (int half = 0; half < 2; half++) {
            int m = m0 + wm * 64 + mt * 16 + g + half * 8;
            float* dst;
            if (mode == 0) {
                int b = m >> 11, s = m & 2047;
                int ht = n0 >> 7;
                if (ht < 16)
                    dst = g_q + (((size_t)(b * NH + ht)) * SEQL + s) * HD;
                else if (ht < 24)
                    dst = g_k + (((size_t)(b * NKV + (ht - 16))) * SEQL + s) * HD;
                else
                    dst = g_v + (((size_t)(b * NKV + (ht - 24))) * SEQL + s) * HD;
            } else {
                dst = C + (size_t)m * DIMN + n0;
            }
#pragma unroll
            for (int nt = 0; nt < 8; nt++) {
                int col = wn * 64 + nt * 8 + c2;
                float2 v2 = make_float2(acc[mt][nt][half * 2],
                                        acc[mt][nt][half * 2 + 1]);
                *(float2*)(dst + col) = v2;
            }
        }
    }
}

// ---------------------------------------------------------------------------
// zero colsum
// ---------------------------------------------------------------------------
__global__ void k_zero()
{
    int i = blockIdx.x * 1024 + threadIdx.x;
    if (i < BATCHN * NKV * HD) g_colsum[i] = 0.f;
}

// ---------------------------------------------------------------------------
// K3: k <- exp(rope(k)) in-place; accumulate column sums.
// ---------------------------------------------------------------------------
__global__ __launch_bounds__(256) void k_rope_k(const float* __restrict__ fc)
{
    __shared__ float s_part[8][128];
    int bhk = blockIdx.x;
    int w   = threadIdx.x >> 5;
    int l   = threadIdx.x & 31;
    float sum0 = 0.f, sum1 = 0.f, sum2 = 0.f, sum3 = 0.f;
#pragma unroll
    for (int r = 0; r < 8; r++) {
        int s = blockIdx.y * 64 + w * 8 + r;
        float* rowp = g_k + ((size_t)bhk * SEQL + s) * HD + l * 4;
        float4 v = *(float4*)rowp;
        float4 f = *(const float4*)(fc + (size_t)s * HD + l * 4);
        float o0 = v.x * f.x - v.y * f.y;
        float o1 = v.x * f.y + v.y * f.x;
        float o2 = v.z * f.z - v.w * f.w;
        float o3 = v.z * f.w + v.w * f.z;
        float e0 = expf(o0), e1 = expf(o1), e2 = expf(o2), e3 = expf(o3);
        *(float4*)rowp = make_float4(e0, e1, e2, e3);
        sum0 += e0; sum1 += e1; sum2 += e2; sum3 += e3;
    }
    s_part[w][l * 4 + 0] = sum0;
    s_part[w][l * 4 + 1] = sum1;
    s_part[w][l * 4 + 2] = sum2;
    s_part[w][l * 4 + 3] = sum3;
    __syncthreads();
    if (threadIdx.x < 128) {
        float a = 0.f;
#pragma unroll
        for (int w2 = 0; w2 < 8; w2++) a += s_part[w2][threadIdx.x];
        atomicAdd(&g_colsum[bhk * HD + threadIdx.x], a);
    }
}

// ---------------------------------------------------------------------------
// K2: q <- softmax(rope(q) * D^-1/2) / colsum[hk]  in-place.
// ---------------------------------------------------------------------------
__global__ __launch_bounds__(256) void k_rope_q(const float* __restrict__ fc)
{
    int r = blockIdx.x * 8 + (threadIdx.x >> 5);
    int l = threadIdx.x & 31;
    int s  = r & 2047;
    int bh = r >> 11;
    int h  = bh & 15;
    int b  = bh >> 4;

    float* rowp = g_q + (size_t)r * HD + l * 4;
    float4 v = *(float4*)rowp;
    float4 f = *(const float4*)(fc + (size_t)s * HD + l * 4);
    const float scale = 0.08838834764831845f;
    float o0 = (v.x * f.x - v.y * f.y) * scale;
    float o1 = (v.x * f.y + v.y * f.x) * scale;
    float o2 = (v.z * f.z - v.w * f.w) * scale;
    float o3 = (v.z * f.w + v.w * f.z) * scale;

    float mx = fmaxf(fmaxf(o0, o1), fmaxf(o2, o3));
#pragma unroll
    for (int off = 16; off; off >>= 1) mx = fmaxf(mx, __shfl_xor_sync(0xffffffffu, mx, off));
    float e0 = expf(o0 - mx), e1 = expf(o1 - mx), e2 = expf(o2 - mx), e3 = expf(o3 - mx);
    float ss = e0 + e1 + e2 + e3;
#pragma unroll
    for (int off = 16; off; off >>= 1) ss += __shfl_xor_sync(0xffffffffu, ss, off);
    float inv = 1.f / ss;

    const float* csp = g_colsum + ((b * NKV + (h >> 1)) * HD) + l * 4;
    float4 cs = *(const float4*)csp;
    *(float4*)rowp = make_float4(e0 * inv / cs.x, e1 * inv / cs.y,
                                 e2 * inv / cs.z, e3 * inv / cs.w);
}

// ---------------------------------------------------------------------------
// K4: per-chunk kv = ek_c^T @ v_c  (128x128, K=128).
// ---------------------------------------------------------------------------
__global__ __launch_bounds__(256) void k_kvchunk()
{
    __shared__ float As[16][128];
    __shared__ float Bs[16][128];
    int bhk = blockIdx.x >> 4;
    int n   = blockIdx.x & 15;
    const float* ekc = g_k + ((size_t)bhk * SEQL + n * CHK) * HD;
    const float* vc  = g_v + ((size_t)bhk * SEQL + n * CHK) * HD;
    int t = threadIdx.x, ty = t >> 4, tx = t & 15;
    float acc[8][8];
#pragma unroll
    for (int i = 0; i < 8; i++)
#pragma unroll
        for (int j = 0; j < 8; j++) acc[i][j] = 0.f;

    for (int s0 = 0; s0 < 128; s0 += 16) {
#pragma unroll
        for (int it = 0; it < 2; it++) {
            int p = it * 256 + t;
            int row = p >> 5, c4 = (p & 31) * 4;
            *(float4*)&As[row][c4] = *(const float4*)(ekc + (size_t)(s0 + row) * HD + c4);
            *(float4*)&Bs[row][c4] = *(const float4*)(vc  + (size_t)(s0 + row) * HD + c4);
        }
        __syncthreads();
#pragma unroll
        for (int kk = 0; kk < 16; kk++) {
            float a[8], b[8];
            float4 t0 = *(const float4*)&As[kk][ty * 8];
            float4 t1 = *(const float4*)&As[kk][ty * 8 + 4];
            a[0]=t0.x; a[1]=t0.y; a[2]=t0.z; a[3]=t0.w;
            a[4]=t1.x; a[5]=t1.y; a[6]=t1.z; a[7]=t1.w;
            float4 u0 = *(const float4*)&Bs[kk][tx * 8];
            float4 u1 = *(const float4*)&Bs[kk][tx * 8 + 4];
            b[0]=u0.x; b[1]=u0.y; b[2]=u0.z; b[3]=u0.w;
            b[4]=u1.x; b[5]=u1.y; b[6]=u1.z; b[7]=u1.w;
#pragma unroll
            for (int i = 0; i < 8; i++)
#pragma unroll
                for (int j = 0; j < 8; j++) acc[i][j] += a[i] * b[j];
        }
        __syncthreads();
    }
    size_t base = ((size_t)bhk * NCH + n) * HD * HD;
#pragma unroll
    for (int i = 0; i < 8; i++) {
        float* rp = g_kv + base + (size_t)(ty * 8 + i) * HD + tx * 8;
        *(float4*)(rp)     = make_float4(acc[i][0], acc[i][1], acc[i][2], acc[i][3]);
        *(float4*)(rp + 4) = make_float4(acc[i][4], acc[i][5], acc[i][6], acc[i][7]);
    }
}

// ---------------------------------------------------------------------------
// K5: exclusive prefix sum over chunks.
// ---------------------------------------------------------------------------
__global__ void k_prefix()
{
    int bhk  = blockIdx.x;
    int elem = blockIdx.y * 256 + threadIdx.x;
    size_t base = (size_t)bhk * NCH * (HD * HD) + elem;
    float acc = 0.f;
#pragma unroll
    for (int n = 0; n < NCH; n++) {
        g_cum[base + (size_t)n * (HD * HD)] = acc;
        acc += g_kv[base + (size_t)n * (HD * HD)];
    }
}

// ---------------------------------------------------------------------------
// K6: per-(b,h,chunk) attention. Epilogue writes fp16 directly into g_a2.
// ---------------------------------------------------------------------------
#define QSTR 132
#define ATTN_SMEM ((2 * 128 * QSTR + 16 * 128) * 4)

__global__ __launch_bounds__(256) void k_attn()
{
    extern __shared__ float sm[];
    float* qsT = sm;
    float* scT = sm + 128 * QSTR;
    float* Bst = sm + 2 * 128 * QSTR;

    int bid = blockIdx.x;
    int b = bid >> 8;
    int h = (bid >> 4) & 15;
    int n = bid & 15;
    int hk = h >> 1;
    int t = threadIdx.x, ty = t >> 4, tx = t & 15;

    const float* qb  = g_q + (((size_t)(b * NH  + h ) * SEQL) + n * CHK) * HD;
    const float* ekb = g_k + (((size_t)(b * NKV + hk) * SEQL) + n * CHK) * HD;
    const float* vb  = g_v + (((size_t)(b * NKV + hk) * SEQL) + n * CHK) * HD;
    const float* cb  = g_cum + ((size_t)(b * NKV + hk) * NCH + n) * (HD * HD);

#pragma unroll
    for (int it = 0; it < 16; it++) {
        int p = it * 256 + t;
        int c = p >> 5;
        int d4 = (p & 31) * 4;
        float4 v4 = *(const float4*)(qb + (size_t)c * HD + d4);
        qsT[(d4 + 0) * QSTR + c] = v4.x;
        qsT[(d4 + 1) * QSTR + c] = v4.y;
        qsT[(d4 + 2) * QSTR + c] = v4.z;
        qsT[(d4 + 3) * QSTR + c] = v4.w;
    }
    __syncthreads();

    float acc[8][8];
#pragma unroll
    for (int i = 0; i < 8; i++)
#pragma unroll
        for (int j = 0; j < 8; j++) acc[i][j] = 0.f;

    for (int d0 = 0; d0 < 128; d0 += 16) {
#pragma unroll
        for (int it = 0; it < 2; it++) {
            int p = it * 256 + t;
            int m = p >> 2;
            int dq = (p & 3) * 4;
            float4 v4 = *(const float4*)(ekb + (size_t)m * HD + d0 + dq);
            Bst[(dq + 0) * 128 + m] = v4.x;
            Bst[(dq + 1) * 128 + m] = v4.y;
            Bst[(dq + 2) * 128 + m] = v4.z;
            Bst[(dq + 3) * 128 + m] = v4.w;
        }
        __syncthreads();
#pragma unroll
        for (int kk = 0; kk < 16; kk++) {
            float a[8], b[8];
            float4 t0 = *(const float4*)&Bst[kk * 128 + ty * 8];
            float4 t1 = *(const float4*)&Bst[kk * 128 + ty * 8 + 4];
            a[0]=t0.x; a[1]=t0.y; a[2]=t0.z; a[3]=t0.w;
            a[4]=t1.x; a[5]=t1.y; a[6]=t1.z; a[7]=t1.w;
            float4 u0 = *(const float4*)&qsT[(d0 + kk) * QSTR + tx * 8];
            float4 u1 = *(const float4*)&qsT[(d0 + kk) * QSTR + tx * 8 + 4];
            b[0]=u0.x; b[1]=u0.y; b[2]=u0.z; b[3]=u0.w;
            b[4]=u1.x; b[5]=u1.y; b[6]=u1.z; b[7]=u1.w;
#pragma unroll
            for (int i = 0; i < 8; i++)
#pragma unroll
                for (int j = 0; j < 8; j++) acc[i][j] += a[i] * b[j];
        }
        __syncthreads();
    }

#pragma unroll
    for (int i = 0; i < 8; i++) {
        int m = ty * 8 + i;
        float r[8];
#pragma unroll
        for (int j = 0; j < 8; j++) {
            int c = tx * 8 + j;
            r[j] = (m <= c) ? acc[i][j] : 0.f;
            acc[i][j] = 0.f;
        }
        *(float4*)&scT[m * QSTR + tx * 8]     = make_float4(r[0], r[1], r[2], r[3]);
        *(float4*)&scT[m * QSTR + tx * 8 + 4] = make_float4(r[4], r[5], r[6], r[7]);
    }
    __syncthreads();

    for (int m0 = 0; m0 < 128; m0 += 16) {
#pragma unroll
        for (int it = 0; it < 2; it++) {
            int p = it * 256 + t;
            int row = p >> 5, e4 = (p & 31) * 4;
            *(float4*)&Bst[row * 128 + e4] =
                *(const float4*)(vb + (size_t)(m0 + row) * HD + e4);
        }
        __syncthreads();
#pragma unroll
        for (int kk = 0; kk < 16; kk++) {
            float a[8], b[8];
            float4 t0 = *(const float4*)&scT[(m0 + kk) * QSTR + ty * 8];
            float4 t1 = *(const float4*)&scT[(m0 + kk) * QSTR + ty * 8 + 4];
            a[0]=t0.x; a[1]=t0.y; a[2]=t0.z; a[3]=t0.w;
            a[4]=t1.x; a[5]=t1.y; a[6]=t1.z; a[7]=t1.w;
            float4 u0 = *(const float4*)&Bst[kk * 128 + tx * 8];
            float4 u1 = *(const float4*)&Bst[kk * 128 + tx * 8 + 4];
            b[0]=u0.x; b[1]=u0.y; b[2]=u0.z; b[3]=u0.w;
            b[4]=u1.x; b[5]=u1.y; b[6]=u1.z; b[7]=u1.w;
#pragma unroll
            for (int i = 0; i < 8; i++)
#pragma unroll
                for (int j = 0; j < 8; j++) acc[i][j] += a[i] * b[j];
        }
        __syncthreads();
    }

    for (int d0 = 0; d0 < 128; d0 += 16) {
#pragma unroll
        for (int it = 0; it < 2; it++) {
            int p = it * 256 + t;
            int row = p >> 5, e4 = (p & 31) * 4;
            *(float4*)&Bst[row * 128 + e4] =
                *(const float4*)(cb + (size_t)(d0 + row) * HD + e4);
        }
        __syncthreads();
#pragma unroll
        for (int kk = 0; kk < 16; kk++) {
            float a[8], b[8];
            float4 t0 = *(const float4*)&qsT[(d0 + kk) * QSTR + ty * 8];
            float4 t1 = *(const float4*)&qsT[(d0 + kk) * QSTR + ty * 8 + 4];
            a[0]=t0.x; a[1]=t0.y; a[2]=t0.z; a[3]=t0.w;
            a[4]=t1.x; a[5]=t1.y; a[6]=t1.z; a[7]=t1.w;
            float4 u0 = *(const float4*)&Bst[kk * 128 + tx * 8];
            float4 u1 = *(const float4*)&Bst[kk * 128 + tx * 8 + 4];
            b[0]=u0.x; b[1]=u0.y; b[2]=u0.z; b[3]=u0.w;
            b[4]=u1.x; b[5]=u1.y; b[6]=u1.z; b[7]=u1.w;
#pragma unroll
            for (int i = 0; i < 8; i++)
#pragma unroll
                for (int j = 0; j < 8; j++) acc[i][j] += a[i] * b[j];
        }
        __syncthreads();
    }

    // epilogue: fp16 directly into g_a2
#pragma unroll
    for (int i = 0; i < 8; i++) {
        int c = ty * 8 + i;
        int s = n * CHK + c;
        unsigned short* op = g_a2 + (size_t)(b * SEQL + s) * KP + h * HD + tx * 8;
        __align__(16) __half o[8];
#pragma unroll
        for (int j = 0; j < 8; j++) o[j] = __float2half(acc[i][j]);
        *(uint4*)op = *(const uint4*)o;
    }
}

// ---------------------------------------------------------------------------
extern "C" void kernel_launch(void* const* d_in, const int* in_sizes, int n_in,
                              void* d_out, int out_size)
{
    const float* x  = (const float*)d_in[0];
    const float* fc = (const float*)d_in[1];
    const float* wq = (const float*)d_in[2];
    const float* wk = (const float*)d_in[3];
    const float* wv = (const float*)d_in[4];
    const float* wo = (const float*)d_in[5];
    float* out = (float*)d_out;

    cudaFuncSetAttribute(k_attn, cudaFuncAttributeMaxDynamicSharedMemorySize, ATTN_SMEM);
    cudaFuncSetAttribute(k_gemm_mma, cudaFuncAttributeMaxDynamicSharedMemorySize, GEMM_SMEM);

    void *p_x2, *p_w2, *p_a2, *p_wo2;
    cudaGetSymbolAddress(&p_x2, g_x2);
    cudaGetSymbolAddress(&p_w2, g_w2);
    cudaGetSymbolAddress(&p_a2, g_a2);
    cudaGetSymbolAddress(&p_wo2, g_wo2);
    unsigned short* x2  = (unsigned short*)p_x2;
    unsigned short* w2  = (unsigned short*)p_w2;
    unsigned short* a2  = (unsigned short*)p_a2;
    unsigned short* wo2 = (unsigned short*)p_wo2;

    // fp32 -> fp16 conversions
    k_cvt<<<4096, 256>>>(x,  x2);                       // 4096x2048
    k_cvt<<<2048, 256>>>(wq, w2);
    k_cvt<<<1024, 256>>>(wk, w2 + (size_t)2048 * KP);
    k_cvt<<<1024, 256>>>(wv, w2 + (size_t)3072 * KP);
    k_cvt<<<2048, 256>>>(wo, wo2);

    // QKV projection on HMMA (scatter epilogue). grid: N=4096/128, M=4096/128
    k_gemm_mma<<<dim3(32, 32), 128, GEMM_SMEM>>>(
        (const __half*)x2, (const __half*)w2, nullptr, 0);

    // RoPE + softmaxes
    k_zero<<<2, 1024>>>();
    k_rope_k<<<dim3(16, 32), 256>>>(fc);
    k_rope_q<<<8192, 256>>>(fc);

    // chunked linear attention (fp32), writes fp16 a2 directly
    k_kvchunk<<<256, 256>>>();
    k_prefix<<<dim3(16, 64), 256>>>();
    k_attn<<<512, 256, ATTN_SMEM>>>();

    // output projection on HMMA. grid: N=2048/128, M=4096/128
    k_gemm_mma<<<dim3(16, 32), 128, GEMM_SMEM>>>(
        (const __half*)a2, (const __half*)wo2, out, 1);
}

// round 8
// speedup vs baseline: 5.6911x; 1.3811x over previous
#include <cuda_runtime.h>
#include <cuda_fp16.h>
#include <cstdint>

// Problem constants
#define BATCHN 2
#define SEQL   2048
#define DIMN   2048
#define NH     16
#define NKV    8
#define HD     128
#define NCH    16
#define CHK    128
#define KP     2048   // plain fp16, K' = K
#define BKC    64     // k-chunk (fp16 elems)
#define STR    72     // smem row stride (GEMM)
#define NITG   (KP / BKC)   // 32

#define QSCALE   4096.0f
#define QDESCALE (1.0f / 4096.0f)

// ---------------------------------------------------------------------------
// Scratch (static device globals — no allocation allowed)
// ---------------------------------------------------------------------------
__device__ float g_q[(size_t)BATCHN * NH * SEQL * HD];    // raw q (pre-rope)
__device__ float g_k[(size_t)BATCHN * NKV * SEQL * HD];   // ek fp32 (for kvchunk)
__device__ float g_v[(size_t)BATCHN * NKV * SEQL * HD];   // v fp32 (for kvchunk)
__device__ float g_kv[(size_t)BATCHN * NKV * NCH * HD * HD];
__device__ float g_colsum[BATCHN * NKV * HD];

// fp16 operands
__device__ unsigned short g_x2[(size_t)4096 * KP];
__device__ unsigned short g_w2[(size_t)4096 * KP];
__device__ unsigned short g_a2[(size_t)4096 * KP];   // attn out (by k_attn_tc)
__device__ unsigned short g_wo2[(size_t)2048 * KP];

// fp16 attention operands
__device__ __half g_qh[(size_t)BATCHN * NH * SEQL * HD];    // q' * QSCALE
__device__ __half g_ekh[(size_t)BATCHN * NKV * SEQL * HD];  // exp(rope(k))
__device__ __half g_vh[(size_t)BATCHN * NKV * SEQL * HD];   // v
__device__ __half g_cumh[(size_t)BATCHN * NKV * NCH * HD * HD]; // cum_excl

// ---------------------------------------------------------------------------
// PTX helpers
// ---------------------------------------------------------------------------
__device__ __forceinline__ uint32_t smem_u32(const void* p) {
    uint32_t a;
    asm("{ .reg .u64 t; cvta.to.shared.u64 t, %1; cvt.u32.u64 %0, t; }"
        : "=r"(a) : "l"(p));
    return a;
}
__device__ __forceinline__ void ldm_x4(uint32_t* r, uint32_t addr) {
    asm volatile("ldmatrix.sync.aligned.m8n8.x4.shared.b16 {%0,%1,%2,%3}, [%4];"
                 : "=r"(r[0]), "=r"(r[1]), "=r"(r[2]), "=r"(r[3]) : "r"(addr));
}
__device__ __forceinline__ void ldm_x4_t(uint32_t* r, uint32_t addr) {
    asm volatile("ldmatrix.sync.aligned.m8n8.x4.trans.shared.b16 {%0,%1,%2,%3}, [%4];"
                 : "=r"(r[0]), "=r"(r[1]), "=r"(r[2]), "=r"(r[3]) : "r"(addr));
}
__device__ __forceinline__ void mma_16816(float* c, const uint32_t* a,
                                          uint32_t b0, uint32_t b1) {
    asm volatile(
        "mma.sync.aligned.m16n8k16.row.col.f32.f16.f16.f32 "
        "{%0,%1,%2,%3}, {%4,%5,%6,%7}, {%8,%9}, {%0,%1,%2,%3};"
        : "+f"(c[0]), "+f"(c[1]), "+f"(c[2]), "+f"(c[3])
        : "r"(a[0]), "r"(a[1]), "r"(a[2]), "r"(a[3]), "r"(b0), "r"(b1));
}
__device__ __forceinline__ void cp16(uint32_t s, const void* g) {
    asm volatile("cp.async.cg.shared.global [%0], [%1], 16;" :: "r"(s), "l"(g));
}
__device__ __forceinline__ void cp_commit() {
    asm volatile("cp.async.commit_group;" ::: "memory");
}
template <int N> __device__ __forceinline__ void cp_wait() {
    asm volatile("cp.async.wait_group %0;" :: "n"(N) : "memory");
}

// ---------------------------------------------------------------------------
// fp32 -> fp16 conversion (plain).
// ---------------------------------------------------------------------------
__global__ __launch_bounds__(256) void k_cvt(const float* __restrict__ src,
                                             unsigned short* __restrict__ dst)
{
    size_t i = ((size_t)blockIdx.x * 256 + threadIdx.x) * 8;
    float4 v0 = *(const float4*)(src + i);
    float4 v1 = *(const float4*)(src + i + 4);
    float f[8] = {v0.x, v0.y, v0.z, v0.w, v1.x, v1.y, v1.z, v1.w};
    __align__(16) __half o[8];
#pragma unroll
    for (int j = 0; j < 8; j++) o[j] = __float2half(f[j]);
    *(uint4*)(dst + i) = *(const uint4*)o;
}

// ---------------------------------------------------------------------------
// HMMA fp16 GEMM (unchanged from R7 structure).
// mode 0: scatter into g_q/g_k/g_v (+ fp16 g_vh).  mode 1: row-major C.
// ---------------------------------------------------------------------------
#define A_BUF (128 * STR)
#define B_BUF (128 * STR)
#define GEMM_SMEM ((3 * (A_BUF + B_BUF)) * 2)   // 110592 bytes

__global__ __launch_bounds__(128, 2) void k_gemm_mma(
    const __half* __restrict__ A, const __half* __restrict__ B,
    float* __restrict__ C, int mode)
{
    extern __shared__ char smraw[];
    __half* sA = (__half*)smraw;
    __half* sB = sA + 3 * A_BUF;

    const int t = threadIdx.x, lane = t & 31, wid = t >> 5;
    const int wm = wid >> 1, wn = wid & 1;
    const int m0 = blockIdx.y * 128, n0 = blockIdx.x * 128;

    uint32_t sAb = smem_u32(sA);
    uint32_t sBb = smem_u32(sB);

    const __half* ga = A + (size_t)(m0 + (t >> 3)) * KP + (t & 7) * 8;
    const __half* gb = B + (size_t)(n0 + (t >> 3)) * KP + (t & 7) * 8;
    const uint32_t so = ((uint32_t)(t >> 3) * STR + (t & 7) * 8) * 2;

    auto load_tile = [&](int buf, int i) {
        uint32_t sa = sAb + (uint32_t)buf * A_BUF * 2 + so;
        uint32_t sb = sBb + (uint32_t)buf * B_BUF * 2 + so;
        int ko = i * BKC;
#pragma unroll
        for (int j = 0; j < 8; j++)
            cp16(sa + j * 16 * STR * 2, ga + (size_t)j * 16 * KP + ko);
#pragma unroll
        for (int j = 0; j < 8; j++)
            cp16(sb + j * 16 * STR * 2, gb + (size_t)j * 16 * KP + ko);
        cp_commit();
    };

    float acc[4][8][4];
#pragma unroll
    for (int i = 0; i < 4; i++)
#pragma unroll
        for (int j = 0; j < 8; j++)
#pragma unroll
            for (int r = 0; r < 4; r++) acc[i][j][r] = 0.f;

    const int lr = lane & 7;
    const int lm = (lane >> 3) & 1;
    const int lc = lane >> 4;

    load_tile(0, 0);
    load_tile(1, 1);

    for (int i = 0; i < NITG; i++) {
        if (i == NITG - 1) cp_wait<0>(); else cp_wait<1>();
        __syncthreads();

        int buf = i % 3;
        uint32_t sa = sAb + (uint32_t)buf * A_BUF * 2;
        uint32_t sb = sBb + (uint32_t)buf * B_BUF * 2;
#pragma unroll
        for (int ks = 0; ks < 4; ks++) {
            uint32_t afr[4][4], bfr[4][4];
            const uint32_t coff = ((uint32_t)(ks * 16 + lc * 8)) * 2;
#pragma unroll
            for (int mt = 0; mt < 4; mt++)
                ldm_x4(afr[mt],
                       sa + ((uint32_t)(wm * 64 + mt * 16 + lr + lm * 8) * STR) * 2 + coff);
#pragma unroll
            for (int nt2 = 0; nt2 < 4; nt2++)
                ldm_x4(bfr[nt2],
                       sb + ((uint32_t)(wn * 64 + nt2 * 16 + lr + lm * 8) * STR) * 2 + coff);
#pragma unroll
            for (int mt = 0; mt < 4; mt++)
#pragma unroll
                for (int nt = 0; nt < 8; nt++)
                    mma_16816(acc[mt][nt], afr[mt],
                              bfr[nt >> 1][nt & 1], bfr[nt >> 1][(nt & 1) + 2]);
        }

        if (i + 2 < NITG) load_tile((i + 2) % 3, i + 2);
    }

    // epilogue
    const int g = lane >> 2, c2 = (lane & 3) * 2;
#pragma unroll
    for (int mt = 0; mt < 4; mt++) {
#pragma unroll
        for (int half = 0; half < 2; half++) {
            int m = m0 + wm * 64 + mt * 16 + g + half * 8;
            float* dst;
            __half* dsth = nullptr;
            if (mode == 0) {
                int b = m >> 11, s = m & 2047;
                int ht = n0 >> 7;
                if (ht < 16)
                    dst = g_q + (((size_t)(b * NH + ht)) * SEQL + s) * HD;
                else if (ht < 24)
                    dst = g_k + (((size_t)(b * NKV + (ht - 16))) * SEQL + s) * HD;
                else {
                    size_t off = (((size_t)(b * NKV + (ht - 24))) * SEQL + s) * HD;
                    dst  = g_v + off;
                    dsth = g_vh + off;
                }
            } else {
                dst = C + (size_t)m * DIMN + n0;
            }
#pragma unroll
            for (int nt = 0; nt < 8; nt++) {
                int col = wn * 64 + nt * 8 + c2;
                float2 v2 = make_float2(acc[mt][nt][half * 2],
                                        acc[mt][nt][half * 2 + 1]);
                *(float2*)(dst + col) = v2;
                if (dsth) {
                    __half2 h2 = __floats2half2_rn(v2.x, v2.y);
                    *(__half2*)(dsth + col) = h2;
                }
            }
        }
    }
}

// ---------------------------------------------------------------------------
// zero colsum
// ---------------------------------------------------------------------------
__global__ void k_zero()
{
    int i = blockIdx.x * 1024 + threadIdx.x;
    if (i < BATCHN * NKV * HD) g_colsum[i] = 0.f;
}

// ---------------------------------------------------------------------------
// K3: k <- exp(rope(k)) in-place (fp32) + fp16 copy; accumulate column sums.
// ---------------------------------------------------------------------------
__global__ __launch_bounds__(256) void k_rope_k(const float* __restrict__ fc)
{
    __shared__ float s_part[8][128];
    int bhk = blockIdx.x;
    int w   = threadIdx.x >> 5;
    int l   = threadIdx.x & 31;
    float sum0 = 0.f, sum1 = 0.f, sum2 = 0.f, sum3 = 0.f;
#pragma unroll
    for (int r = 0; r < 8; r++) {
        int s = blockIdx.y * 64 + w * 8 + r;
        size_t off = ((size_t)bhk * SEQL + s) * HD + l * 4;
        float* rowp = g_k + off;
        float4 v = *(float4*)rowp;
        float4 f = *(const float4*)(fc + (size_t)s * HD + l * 4);
        float o0 = v.x * f.x - v.y * f.y;
        float o1 = v.x * f.y + v.y * f.x;
        float o2 = v.z * f.z - v.w * f.w;
        float o3 = v.z * f.w + v.w * f.z;
        float e0 = expf(o0), e1 = expf(o1), e2 = expf(o2), e3 = expf(o3);
        *(float4*)rowp = make_float4(e0, e1, e2, e3);
        __half2 h0 = __floats2half2_rn(e0, e1);
        __half2 h1 = __floats2half2_rn(e2, e3);
        *(__half2*)(g_ekh + off)     = h0;
        *(__half2*)(g_ekh + off + 2) = h1;
        sum0 += e0; sum1 += e1; sum2 += e2; sum3 += e3;
    }
    s_part[w][l * 4 + 0] = sum0;
    s_part[w][l * 4 + 1] = sum1;
    s_part[w][l * 4 + 2] = sum2;
    s_part[w][l * 4 + 3] = sum3;
    __syncthreads();
    if (threadIdx.x < 128) {
        float a = 0.f;
#pragma unroll
        for (int w2 = 0; w2 < 8; w2++) a += s_part[w2][threadIdx.x];
        atomicAdd(&g_colsum[bhk * HD + threadIdx.x], a);
    }
}

// ---------------------------------------------------------------------------
// K2: q' = softmax(rope(q)*s)/colsum, scaled by QSCALE, written as fp16.
// ---------------------------------------------------------------------------
__global__ __launch_bounds__(256) void k_rope_q(const float* __restrict__ fc)
{
    int r = blockIdx.x * 8 + (threadIdx.x >> 5);
    int l = threadIdx.x & 31;
    int s  = r & 2047;
    int bh = r >> 11;
    int h  = bh & 15;
    int b  = bh >> 4;

    const float* rowp = g_q + (size_t)r * HD + l * 4;
    float4 v = *(const float4*)rowp;
    float4 f = *(const float4*)(fc + (size_t)s * HD + l * 4);
    const float scale = 0.08838834764831845f;
    float o0 = (v.x * f.x - v.y * f.y) * scale;
    float o1 = (v.x * f.y + v.y * f.x) * scale;
    float o2 = (v.z * f.z - v.w * f.w) * scale;
    float o3 = (v.z * f.w + v.w * f.z) * scale;

    float mx = fmaxf(fmaxf(o0, o1), fmaxf(o2, o3));
#pragma unroll
    for (int off = 16; off; off >>= 1) mx = fmaxf(mx, __shfl_xor_sync(0xffffffffu, mx, off));
    float e0 = expf(o0 - mx), e1 = expf(o1 - mx), e2 = expf(o2 - mx), e3 = expf(o3 - mx);
    float ss = e0 + e1 + e2 + e3;
#pragma unroll
    for (int off = 16; off; off >>= 1) ss += __shfl_xor_sync(0xffffffffu, ss, off);
    float inv = QSCALE / ss;

    const float* csp = g_colsum + ((b * NKV + (h >> 1)) * HD) + l * 4;
    float4 cs = *(const float4*)csp;
    __half2 h0 = __floats2half2_rn(e0 * inv / cs.x, e1 * inv / cs.y);
    __half2 h1 = __floats2half2_rn(e2 * inv / cs.z, e3 * inv / cs.w);
    __half* qp = g_qh + (size_t)r * HD + l * 4;
    *(__half2*)(qp)     = h0;
    *(__half2*)(qp + 2) = h1;
}

// ---------------------------------------------------------------------------
// K4: per-chunk kv = ek_c^T @ v_c  (fp32, unchanged).
// ---------------------------------------------------------------------------
__global__ __launch_bounds__(256) void k_kvchunk()
{
    __shared__ float As[16][128];
    __shared__ float Bs[16][128];
    int bhk = blockIdx.x >> 4;
    int n   = blockIdx.x & 15;
    const float* ekc = g_k + ((size_t)bhk * SEQL + n * CHK) * HD;
    const float* vc  = g_v + ((size_t)bhk * SEQL + n * CHK) * HD;
    int t = threadIdx.x, ty = t >> 4, tx = t & 15;
    float acc[8][8];
#pragma unroll
    for (int i = 0; i < 8; i++)
#pragma unroll
        for (int j = 0; j < 8; j++) acc[i][j] = 0.f;

    for (int s0 = 0; s0 < 128; s0 += 16) {
#pragma unroll
        for (int it = 0; it < 2; it++) {
            int p = it * 256 + t;
            int row = p >> 5, c4 = (p & 31) * 4;
            *(float4*)&As[row][c4] = *(const float4*)(ekc + (size_t)(s0 + row) * HD + c4);
            *(float4*)&Bs[row][c4] = *(const float4*)(vc  + (size_t)(s0 + row) * HD + c4);
        }
        __syncthreads();
#pragma unroll
        for (int kk = 0; kk < 16; kk++) {
            float a[8], b[8];
            float4 t0 = *(const float4*)&As[kk][ty * 8];
            float4 t1 = *(const float4*)&As[kk][ty * 8 + 4];
            a[0]=t0.x; a[1]=t0.y; a[2]=t0.z; a[3]=t0.w;
            a[4]=t1.x; a[5]=t1.y; a[6]=t1.z; a[7]=t1.w;
            float4 u0 = *(const float4*)&Bs[kk][tx * 8];
            float4 u1 = *(const float4*)&Bs[kk][tx * 8 + 4];
            b[0]=u0.x; b[1]=u0.y; b[2]=u0.z; b[3]=u0.w;
            b[4]=u1.x; b[5]=u1.y; b[6]=u1.z; b[7]=u1.w;
#pragma unroll
            for (int i = 0; i < 8; i++)
#pragma unroll
                for (int j = 0; j < 8; j++) acc[i][j] += a[i] * b[j];
        }
        __syncthreads();
    }
    size_t base = ((size_t)bhk * NCH + n) * HD * HD;
#pragma unroll
    for (int i = 0; i < 8; i++) {
        float* rp = g_kv + base + (size_t)(ty * 8 + i) * HD + tx * 8;
        *(float4*)(rp)     = make_float4(acc[i][0], acc[i][1], acc[i][2], acc[i][3]);
        *(float4*)(rp + 4) = make_float4(acc[i][4], acc[i][5], acc[i][6], acc[i][7]);
    }
}

// ---------------------------------------------------------------------------
// K5: exclusive prefix sum over chunks -> fp16 g_cumh.
// ---------------------------------------------------------------------------
__global__ void k_prefix()
{
    int bhk  = blockIdx.x;
    int elem = blockIdx.y * 256 + threadIdx.x;
    size_t base = (size_t)bhk * NCH * (HD * HD) + elem;
    float acc = 0.f;
#pragma unroll
    for (int n = 0; n < NCH; n++) {
        g_cumh[base + (size_t)n * (HD * HD)] = __float2half(acc);
        acc += g_kv[base + (size_t)n * (HD * HD)];
    }
}

// ---------------------------------------------------------------------------
// K6: per-(b,h,chunk) attention on HMMA.
//   S = q'h @ ekh^T (mask m<=c), O = S@V + q'h@cum, epilogue fp16*QDESCALE.
// 128 threads (4 warps), warp handles 32 rows (c).
// smem: qs[128][136], es[128][136] (ek, then cum), vs[128][136]  fp16.
// ---------------------------------------------------------------------------
#define ASTR 136
#define ATILE (128 * ASTR)                 // halves per tile
#define ATTN2_SMEM (3 * ATILE * 2)         // 104448 bytes

__global__ __launch_bounds__(128, 2) void k_attn_tc()
{
    extern __shared__ __half smh[];
    __half* qs = smh;
    __half* es = smh + ATILE;      // ek, later cum
    __half* vs = smh + 2 * ATILE;

    const int bid = blockIdx.x;
    const int b = bid >> 8;
    const int h = (bid >> 4) & 15;
    const int n = bid & 15;
    const int hk = h >> 1;
    const int t = threadIdx.x, lane = t & 31, w = t >> 5;

    const __half* qb = g_qh  + (((size_t)(b * NH  + h ) * SEQL) + n * CHK) * HD;
    const __half* eb = g_ekh + (((size_t)(b * NKV + hk) * SEQL) + n * CHK) * HD;
    const __half* vb = g_vh  + (((size_t)(b * NKV + hk) * SEQL) + n * CHK) * HD;
    const __half* cb = g_cumh + ((size_t)(b * NKV + hk) * NCH + n) * (HD * HD);

    uint32_t qsb = smem_u32(qs), esb = smem_u32(es), vsb = smem_u32(vs);

    // load q, ek, v tiles via cp.async (each: 2048 16B chunks, 128 thr x 16)
#pragma unroll
    for (int it = 0; it < 16; it++) {
        int idx = it * 128 + t;
        int r = idx >> 4, seg = idx & 15;
        uint32_t so = ((uint32_t)r * ASTR + seg * 8) * 2;
        cp16(qsb + so, qb + (size_t)r * HD + seg * 8);
        cp16(esb + so, eb + (size_t)r * HD + seg * 8);
        cp16(vsb + so, vb + (size_t)r * HD + seg * 8);
    }
    cp_commit();
    cp_wait<0>();
    __syncthreads();

    const int lr = lane & 7, lm = (lane >> 3) & 1, lc = lane >> 4;
    const int g = lane >> 2, qd = (lane & 3) * 2;

    // ---- pass 1: S[c][m] = q' . ek  (K = d = 128) ----
    float sacc[2][16][4];
#pragma unroll
    for (int i = 0; i < 2; i++)
#pragma unroll
        for (int j = 0; j < 16; j++)
#pragma unroll
            for (int r = 0; r < 4; r++) sacc[i][j][r] = 0.f;

#pragma unroll
    for (int ks = 0; ks < 8; ks++) {
        uint32_t afr[2][4], bfr[8][4];
        const uint32_t coff = ((uint32_t)(ks * 16 + lc * 8)) * 2;
#pragma unroll
        for (int mt = 0; mt < 2; mt++)
            ldm_x4(afr[mt], qsb + ((uint32_t)(w * 32 + mt * 16 + lr + lm * 8) * ASTR) * 2 + coff);
#pragma unroll
        for (int p = 0; p < 8; p++)
            ldm_x4(bfr[p], esb + ((uint32_t)(p * 16 + lr + lm * 8) * ASTR) * 2 + coff);
#pragma unroll
        for (int mt = 0; mt < 2; mt++)
#pragma unroll
            for (int nt = 0; nt < 16; nt++)
                mma_16816(sacc[mt][nt], afr[mt],
                          bfr[nt >> 1][nt & 1], bfr[nt >> 1][(nt & 1) + 2]);
    }

    // es buffer free after pass 1 -> load cum into it
    __syncthreads();
#pragma unroll
    for (int it = 0; it < 16; it++) {
        int idx = it * 128 + t;
        int r = idx >> 4, seg = idx & 15;
        cp16(esb + ((uint32_t)r * ASTR + seg * 8) * 2, cb + (size_t)r * HD + seg * 8);
    }
    cp_commit();

    // ---- mask + convert S to fp16 A-fragments ----
    // sfr[mt][j] = a-frag for (c-tile mt, k16 tile j over m)
    uint32_t sfr[2][8][4];
#pragma unroll
    for (int mt = 0; mt < 2; mt++) {
        int c0 = w * 32 + mt * 16 + g;
#pragma unroll
        for (int j = 0; j < 8; j++) {
            int mA = j * 16 + qd;        // tile 2j cols
            int mB = j * 16 + 8 + qd;    // tile 2j+1 cols
            float* e0 = sacc[mt][2 * j];
            float* e1 = sacc[mt][2 * j + 1];
            __half2 p0 = __floats2half2_rn(mA     <= c0     ? e0[0] : 0.f,
                                           mA + 1 <= c0     ? e0[1] : 0.f);
            __half2 p1 = __floats2half2_rn(mA     <= c0 + 8 ? e0[2] : 0.f,
                                           mA + 1 <= c0 + 8 ? e0[3] : 0.f);
            __half2 p2 = __floats2half2_rn(mB     <= c0     ? e1[0] : 0.f,
                                           mB + 1 <= c0     ? e1[1] : 0.f);
            __half2 p3 = __floats2half2_rn(mB     <= c0 + 8 ? e1[2] : 0.f,
                                           mB + 1 <= c0 + 8 ? e1[3] : 0.f);
            sfr[mt][j][0] = *(uint32_t*)&p0;
            sfr[mt][j][1] = *(uint32_t*)&p1;
            sfr[mt][j][2] = *(uint32_t*)&p2;
            sfr[mt][j][3] = *(uint32_t*)&p3;
        }
    }

    cp_wait<0>();
    __syncthreads();

    // ---- pass 2: O[c][e] = S @ V + q' @ cum, e in two halves of 64 ----
#pragma unroll
    for (int eh = 0; eh < 2; eh++) {
        float oacc[2][8][4];
#pragma unroll
        for (int i = 0; i < 2; i++)
#pragma unroll
            for (int j = 0; j < 8; j++)
#pragma unroll
                for (int r = 0; r < 4; r++) oacc[i][j][r] = 0.f;

        // S @ V  (k = m = 128)
#pragma unroll
        for (int j = 0; j < 8; j++) {
            uint32_t vfr[4][4];
#pragma unroll
            for (int ep = 0; ep < 4; ep++)
                ldm_x4_t(vfr[ep],
                         vsb + ((uint32_t)(j * 16 + lr + lm * 8) * ASTR
                                + eh * 64 + ep * 16 + lc * 8) * 2);
#pragma unroll
            for (int mt = 0; mt < 2; mt++)
#pragma unroll
                for (int nt = 0; nt < 8; nt++)
                    mma_16816(oacc[mt][nt], sfr[mt][j],
                              vfr[nt >> 1][(nt & 1) * 2], vfr[nt >> 1][(nt & 1) * 2 + 1]);
        }

        // q' @ cum  (k = d = 128)
#pragma unroll
        for (int ks = 0; ks < 8; ks++) {
            uint32_t afr[2][4], cfr[4][4];
            const uint32_t coff = ((uint32_t)(ks * 16 + lc * 8)) * 2;
#pragma unroll
            for (int mt = 0; mt < 2; mt++)
                ldm_x4(afr[mt], qsb + ((uint32_t)(w * 32 + mt * 16 + lr + lm * 8) * ASTR) * 2 + coff);
#pragma unroll
            for (int ep = 0; ep < 4; ep++)
                ldm_x4_t(cfr[ep],
                         esb + ((uint32_t)(ks * 16 + lr + lm * 8) * ASTR
                                + eh * 64 + ep * 16 + lc * 8) * 2);
#pragma unroll
            for (int mt = 0; mt < 2; mt++)
#pragma unroll
                for (int nt = 0; nt < 8; nt++)
                    mma_16816(oacc[mt][nt], afr[mt],
                              cfr[nt >> 1][(nt & 1) * 2], cfr[nt >> 1][(nt & 1) * 2 + 1]);
        }

        // write O (descaled) as fp16 into g_a2
#pragma unroll
        for (int mt = 0; mt < 2; mt++) {
#pragma unroll
            for (int half = 0; half < 2; half++) {
                int c = w * 32 + mt * 16 + g + half * 8;
                int s = n * CHK + c;
                unsigned short* orow = g_a2 + (size_t)(b * SEQL + s) * KP + h * HD;
#pragma unroll
                for (int nt = 0; nt < 8; nt++) {
                    int e = eh * 64 + nt * 8 + qd;
                    __half2 h2 = __floats2half2_rn(oacc[mt][nt][half * 2] * QDESCALE,
                                                   oacc[mt][nt][half * 2 + 1] * QDESCALE);
                    *(__half2*)(orow + e) = h2;
                }
            }
        }
    }
}

// ---------------------------------------------------------------------------
extern "C" void kernel_launch(void* const* d_in, const int* in_sizes, int n_in,
                              void* d_out, int out_size)
{
    const float* x  = (const float*)d_in[0];
    const float* fc = (const float*)d_in[1];
    const float* wq = (const float*)d_in[2];
    const float* wk = (const float*)d_in[3];
    const float* wv = (const float*)d_in[4];
    const float* wo = (const float*)d_in[5];
    float* out = (float*)d_out;

    cudaFuncSetAttribute(k_gemm_mma, cudaFuncAttributeMaxDynamicSharedMemorySize, GEMM_SMEM);
    cudaFuncSetAttribute(k_attn_tc, cudaFuncAttributeMaxDynamicSharedMemorySize, ATTN2_SMEM);

    void *p_x2, *p_w2, *p_a2, *p_wo2;
    cudaGetSymbolAddress(&p_x2, g_x2);
    cudaGetSymbolAddress(&p_w2, g_w2);
    cudaGetSymbolAddress(&p_a2, g_a2);
    cudaGetSymbolAddress(&p_wo2, g_wo2);
    unsigned short* x2  = (unsigned short*)p_x2;
    unsigned short* w2  = (unsigned short*)p_w2;
    unsigned short* a2  = (unsigned short*)p_a2;
    unsigned short* wo2 = (unsigned short*)p_wo2;

    // fp32 -> fp16 conversions
    k_cvt<<<4096, 256>>>(x,  x2);
    k_cvt<<<2048, 256>>>(wq, w2);
    k_cvt<<<1024, 256>>>(wk, w2 + (size_t)2048 * KP);
    k_cvt<<<1024, 256>>>(wv, w2 + (size_t)3072 * KP);
    k_cvt<<<2048, 256>>>(wo, wo2);

    // QKV projection on HMMA (scatter epilogue incl. fp16 v)
    k_gemm_mma<<<dim3(32, 32), 128, GEMM_SMEM>>>(
        (const __half*)x2, (const __half*)w2, nullptr, 0);

    // RoPE + softmaxes (q' written scaled fp16, ek written fp32+fp16)
    k_zero<<<2, 1024>>>();
    k_rope_k<<<dim3(16, 32), 256>>>(fc);
    k_rope_q<<<8192, 256>>>(fc);

    // chunked linear attention
    k_kvchunk<<<256, 256>>>();
    k_prefix<<<dim3(16, 64), 256>>>();
    k_attn_tc<<<512, 128, ATTN2_SMEM>>>();

    // output projection on HMMA
    k_gemm_mma<<<dim3(16, 32), 128, GEMM_SMEM>>>(
        (const __half*)a2, (const __half*)wo2, out, 1);
}

// round 9
// speedup vs baseline: 6.1400x; 1.0789x over previous
#include <cuda_runtime.h>
#include <cuda_fp16.h>
#include <cstdint>

// Problem constants
#define BATCHN 2
#define SEQL   2048
#define DIMN   2048
#define NH     16
#define NKV    8
#define HD     128
#define NCH    16
#define CHK    128
#define KP     2048
#define BKC    64
#define STR    72
#define NITG   (KP / BKC)   // 32

#define QSCALE   4096.0f
#define QDESCALE (1.0f / 4096.0f)

// ---------------------------------------------------------------------------
// Scratch
// ---------------------------------------------------------------------------
__device__ float g_q[(size_t)BATCHN * NH * SEQL * HD];    // raw q (pre-rope)
__device__ float g_k[(size_t)BATCHN * NKV * SEQL * HD];   // raw k (pre-rope)
__device__ float g_kv[(size_t)BATCHN * NKV * NCH * HD * HD];
__device__ float g_colsum[BATCHN * NKV * HD];

__device__ unsigned short g_x2[(size_t)4096 * KP];
__device__ unsigned short g_w2[(size_t)4096 * KP];
__device__ unsigned short g_a2[(size_t)4096 * KP];
__device__ unsigned short g_wo2[(size_t)2048 * KP];

__device__ __half g_qh[(size_t)BATCHN * NH * SEQL * HD];    // q' * QSCALE
__device__ __half g_ekh[(size_t)BATCHN * NKV * SEQL * HD];  // exp(rope(k))
__device__ __half g_vh[(size_t)BATCHN * NKV * SEQL * HD];   // v
__device__ __half g_cumh[(size_t)BATCHN * NKV * NCH * HD * HD];

// ---------------------------------------------------------------------------
// PTX helpers
// ---------------------------------------------------------------------------
__device__ __forceinline__ uint32_t smem_u32(const void* p) {
    uint32_t a;
    asm("{ .reg .u64 t; cvta.to.shared.u64 t, %1; cvt.u32.u64 %0, t; }"
        : "=r"(a) : "l"(p));
    return a;
}
__device__ __forceinline__ void ldm_x4(uint32_t* r, uint32_t addr) {
    asm volatile("ldmatrix.sync.aligned.m8n8.x4.shared.b16 {%0,%1,%2,%3}, [%4];"
                 : "=r"(r[0]), "=r"(r[1]), "=r"(r[2]), "=r"(r[3]) : "r"(addr));
}
__device__ __forceinline__ void ldm_x4_t(uint32_t* r, uint32_t addr) {
    asm volatile("ldmatrix.sync.aligned.m8n8.x4.trans.shared.b16 {%0,%1,%2,%3}, [%4];"
                 : "=r"(r[0]), "=r"(r[1]), "=r"(r[2]), "=r"(r[3]) : "r"(addr));
}
__device__ __forceinline__ void mma_16816(float* c, const uint32_t* a,
                                          uint32_t b0, uint32_t b1) {
    asm volatile(
        "mma.sync.aligned.m16n8k16.row.col.f32.f16.f16.f32 "
        "{%0,%1,%2,%3}, {%4,%5,%6,%7}, {%8,%9}, {%0,%1,%2,%3};"
        : "+f"(c[0]), "+f"(c[1]), "+f"(c[2]), "+f"(c[3])
        : "r"(a[0]), "r"(a[1]), "r"(a[2]), "r"(a[3]), "r"(b0), "r"(b1));
}
__device__ __forceinline__ void cp16(uint32_t s, const void* g) {
    asm volatile("cp.async.cg.shared.global [%0], [%1], 16;" :: "r"(s), "l"(g));
}
__device__ __forceinline__ void cp_commit() {
    asm volatile("cp.async.commit_group;" ::: "memory");
}
template <int N> __device__ __forceinline__ void cp_wait() {
    asm volatile("cp.async.wait_group %0;" :: "n"(N) : "memory");
}

// ---------------------------------------------------------------------------
// fp32 -> fp16 conversion
// ---------------------------------------------------------------------------
__global__ __launch_bounds__(256) void k_cvt(const float* __restrict__ src,
                                             unsigned short* __restrict__ dst)
{
    size_t i = ((size_t)blockIdx.x * 256 + threadIdx.x) * 8;
    float4 v0 = *(const float4*)(src + i);
    float4 v1 = *(const float4*)(src + i + 4);
    float f[8] = {v0.x, v0.y, v0.z, v0.w, v1.x, v1.y, v1.z, v1.w};
    __align__(16) __half o[8];
#pragma unroll
    for (int j = 0; j < 8; j++) o[j] = __float2half(f[j]);
    *(uint4*)(dst + i) = *(const uint4*)o;
}

// ---------------------------------------------------------------------------
// HMMA fp16 GEMM (R7 structure).
// mode 0: scatter q/k fp32, v fp16-only.  mode 1: row-major fp32 C.
// ---------------------------------------------------------------------------
#define A_BUF (128 * STR)
#define B_BUF (128 * STR)
#define GEMM_SMEM ((3 * (A_BUF + B_BUF)) * 2)   // 110592 bytes

__global__ __launch_bounds__(128, 2) void k_gemm_mma(
    const __half* __restrict__ A, const __half* __restrict__ B,
    float* __restrict__ C, int mode)
{
    extern __shared__ char smraw[];
    __half* sA = (__half*)smraw;
    __half* sB = sA + 3 * A_BUF;

    const int t = threadIdx.x, lane = t & 31, wid = t >> 5;
    const int wm = wid >> 1, wn = wid & 1;
    const int m0 = blockIdx.y * 128, n0 = blockIdx.x * 128;

    uint32_t sAb = smem_u32(sA);
    uint32_t sBb = smem_u32(sB);

    const __half* ga = A + (size_t)(m0 + (t >> 3)) * KP + (t & 7) * 8;
    const __half* gb = B + (size_t)(n0 + (t >> 3)) * KP + (t & 7) * 8;
    const uint32_t so = ((uint32_t)(t >> 3) * STR + (t & 7) * 8) * 2;

    auto load_tile = [&](int buf, int i) {
        uint32_t sa = sAb + (uint32_t)buf * A_BUF * 2 + so;
        uint32_t sb = sBb + (uint32_t)buf * B_BUF * 2 + so;
        int ko = i * BKC;
#pragma unroll
        for (int j = 0; j < 8; j++)
            cp16(sa + j * 16 * STR * 2, ga + (size_t)j * 16 * KP + ko);
#pragma unroll
        for (int j = 0; j < 8; j++)
            cp16(sb + j * 16 * STR * 2, gb + (size_t)j * 16 * KP + ko);
        cp_commit();
    };

    float acc[4][8][4];
#pragma unroll
    for (int i = 0; i < 4; i++)
#pragma unroll
        for (int j = 0; j < 8; j++)
#pragma unroll
            for (int r = 0; r < 4; r++) acc[i][j][r] = 0.f;

    const int lr = lane & 7;
    const int lm = (lane >> 3) & 1;
    const int lc = lane >> 4;

    load_tile(0, 0);
    load_tile(1, 1);

    for (int i = 0; i < NITG; i++) {
        if (i == NITG - 1) cp_wait<0>(); else cp_wait<1>();
        __syncthreads();

        int buf = i % 3;
        uint32_t sa = sAb + (uint32_t)buf * A_BUF * 2;
        uint32_t sb = sBb + (uint32_t)buf * B_BUF * 2;
#pragma unroll
        for (int ks = 0; ks < 4; ks++) {
            uint32_t afr[4][4], bfr[4][4];
            const uint32_t coff = ((uint32_t)(ks * 16 + lc * 8)) * 2;
#pragma unroll
            for (int mt = 0; mt < 4; mt++)
                ldm_x4(afr[mt],
                       sa + ((uint32_t)(wm * 64 + mt * 16 + lr + lm * 8) * STR) * 2 + coff);
#pragma unroll
            for (int nt2 = 0; nt2 < 4; nt2++)
                ldm_x4(bfr[nt2],
                       sb + ((uint32_t)(wn * 64 + nt2 * 16 + lr + lm * 8) * STR) * 2 + coff);
#pragma unroll
            for (int mt = 0; mt < 4; mt++)
#pragma unroll
                for (int nt = 0; nt < 8; nt++)
                    mma_16816(acc[mt][nt], afr[mt],
                              bfr[nt >> 1][nt & 1], bfr[nt >> 1][(nt & 1) + 2]);
        }

        if (i + 2 < NITG) load_tile((i + 2) % 3, i + 2);
    }

    // epilogue
    const int g = lane >> 2, c2 = (lane & 3) * 2;
#pragma unroll
    for (int mt = 0; mt < 4; mt++) {
#pragma unroll
        for (int half = 0; half < 2; half++) {
            int m = m0 + wm * 64 + mt * 16 + g + half * 8;
            float* dst = nullptr;
            __half* dsth = nullptr;
            if (mode == 0) {
                int b = m >> 11, s = m & 2047;
                int ht = n0 >> 7;
                if (ht < 16)
                    dst = g_q + (((size_t)(b * NH + ht)) * SEQL + s) * HD;
                else if (ht < 24)
                    dst = g_k + (((size_t)(b * NKV + (ht - 16))) * SEQL + s) * HD;
                else
                    dsth = g_vh + (((size_t)(b * NKV + (ht - 24))) * SEQL + s) * HD;
            } else {
                dst = C + (size_t)m * DIMN + n0;
            }
#pragma unroll
            for (int nt = 0; nt < 8; nt++) {
                int col = wn * 64 + nt * 8 + c2;
                float2 v2 = make_float2(acc[mt][nt][half * 2],
                                        acc[mt][nt][half * 2 + 1]);
                if (dst) *(float2*)(dst + col) = v2;
                if (dsth) {
                    __half2 h2 = __floats2half2_rn(v2.x, v2.y);
                    *(__half2*)(dsth + col) = h2;
                }
            }
        }
    }
}

// ---------------------------------------------------------------------------
// zero colsum
// ---------------------------------------------------------------------------
__global__ void k_zero()
{
    int i = blockIdx.x * 1024 + threadIdx.x;
    if (i < BATCHN * NKV * HD) g_colsum[i] = 0.f;
}

// ---------------------------------------------------------------------------
// K3: ekh = exp(rope(k)) fp16; accumulate column sums (fp32).
// ---------------------------------------------------------------------------
__global__ __launch_bounds__(256) void k_rope_k(const float* __restrict__ fc)
{
    __shared__ float s_part[8][128];
    int bhk = blockIdx.x;
    int w   = threadIdx.x >> 5;
    int l   = threadIdx.x & 31;
    float sum0 = 0.f, sum1 = 0.f, sum2 = 0.f, sum3 = 0.f;
#pragma unroll
    for (int r = 0; r < 8; r++) {
        int s = blockIdx.y * 64 + w * 8 + r;
        size_t off = ((size_t)bhk * SEQL + s) * HD + l * 4;
        float4 v = *(const float4*)(g_k + off);
        float4 f = *(const float4*)(fc + (size_t)s * HD + l * 4);
        float o0 = v.x * f.x - v.y * f.y;
        float o1 = v.x * f.y + v.y * f.x;
        float o2 = v.z * f.z - v.w * f.w;
        float o3 = v.z * f.w + v.w * f.z;
        float e0 = expf(o0), e1 = expf(o1), e2 = expf(o2), e3 = expf(o3);
        *(__half2*)(g_ekh + off)     = __floats2half2_rn(e0, e1);
        *(__half2*)(g_ekh + off + 2) = __floats2half2_rn(e2, e3);
        sum0 += e0; sum1 += e1; sum2 += e2; sum3 += e3;
    }
    s_part[w][l * 4 + 0] = sum0;
    s_part[w][l * 4 + 1] = sum1;
    s_part[w][l * 4 + 2] = sum2;
    s_part[w][l * 4 + 3] = sum3;
    __syncthreads();
    if (threadIdx.x < 128) {
        float a = 0.f;
#pragma unroll
        for (int w2 = 0; w2 < 8; w2++) a += s_part[w2][threadIdx.x];
        atomicAdd(&g_colsum[bhk * HD + threadIdx.x], a);
    }
}

// ---------------------------------------------------------------------------
// K2: q' = softmax(rope(q)*s)/colsum * QSCALE -> fp16.
// ---------------------------------------------------------------------------
__global__ __launch_bounds__(256) void k_rope_q(const float* __restrict__ fc)
{
    int r = blockIdx.x * 8 + (threadIdx.x >> 5);
    int l = threadIdx.x & 31;
    int s  = r & 2047;
    int bh = r >> 11;
    int h  = bh & 15;
    int b  = bh >> 4;

    const float* rowp = g_q + (size_t)r * HD + l * 4;
    float4 v = *(const float4*)rowp;
    float4 f = *(const float4*)(fc + (size_t)s * HD + l * 4);
    const float scale = 0.08838834764831845f;
    float o0 = (v.x * f.x - v.y * f.y) * scale;
    float o1 = (v.x * f.y + v.y * f.x) * scale;
    float o2 = (v.z * f.z - v.w * f.w) * scale;
    float o3 = (v.z * f.w + v.w * f.z) * scale;

    float mx = fmaxf(fmaxf(o0, o1), fmaxf(o2, o3));
#pragma unroll
    for (int off = 16; off; off >>= 1) mx = fmaxf(mx, __shfl_xor_sync(0xffffffffu, mx, off));
    float e0 = expf(o0 - mx), e1 = expf(o1 - mx), e2 = expf(o2 - mx), e3 = expf(o3 - mx);
    float ss = e0 + e1 + e2 + e3;
#pragma unroll
    for (int off = 16; off; off >>= 1) ss += __shfl_xor_sync(0xffffffffu, ss, off);
    float inv = QSCALE / ss;

    const float* csp = g_colsum + ((b * NKV + (h >> 1)) * HD) + l * 4;
    float4 cs = *(const float4*)csp;
    __half* qp = g_qh + (size_t)r * HD + l * 4;
    *(__half2*)(qp)     = __floats2half2_rn(e0 * inv / cs.x, e1 * inv / cs.y);
    *(__half2*)(qp + 2) = __floats2half2_rn(e2 * inv / cs.z, e3 * inv / cs.w);
}

// ---------------------------------------------------------------------------
// K4: per-chunk kv = ek^T @ v on HMMA (fp16 in, fp32 out).
// C[d][e] = sum_m ek[m][d] * v[m][e].
// A = ek^T via ldmatrix.trans (frag order {r0, r2, r1, r3}); B = v via trans.
// 128 threads (4 warps); warp w owns d rows w*32..w*32+31.
// ---------------------------------------------------------------------------
#define KVSTR 136
#define KV_SMEM (2 * 128 * KVSTR * 2)   // 69632 bytes

__global__ __launch_bounds__(128, 2) void k_kvchunk_tc()
{
    extern __shared__ __half smkv[];
    __half* es = smkv;                  // ek [m][d]
    __half* vs = smkv + 128 * KVSTR;    // v  [m][e]

    const int bhk = blockIdx.x >> 4;
    const int n   = blockIdx.x & 15;
    const __half* eb = g_ekh + ((size_t)bhk * SEQL + n * CHK) * HD;
    const __half* vb = g_vh  + ((size_t)bhk * SEQL + n * CHK) * HD;
    const int t = threadIdx.x, lane = t & 31, w = t >> 5;
    uint32_t esb = smem_u32(es), vsb = smem_u32(vs);

#pragma unroll
    for (int it = 0; it < 16; it++) {
        int idx = it * 128 + t;
        int r = idx >> 4, seg = idx & 15;
        uint32_t so = ((uint32_t)r * KVSTR + seg * 8) * 2;
        cp16(esb + so, eb + (size_t)r * HD + seg * 8);
        cp16(vsb + so, vb + (size_t)r * HD + seg * 8);
    }
    cp_commit();
    cp_wait<0>();
    __syncthreads();

    const int lr = lane & 7, lm = (lane >> 3) & 1, lc = lane >> 4;
    const int g = lane >> 2, qd = (lane & 3) * 2;

    float acc[2][16][4];
#pragma unroll
    for (int i = 0; i < 2; i++)
#pragma unroll
        for (int j = 0; j < 16; j++)
#pragma unroll
            for (int r = 0; r < 4; r++) acc[i][j][r] = 0.f;

#pragma unroll
    for (int ks = 0; ks < 8; ks++) {         // m-chunks of 16
        uint32_t afr[2][4], tmp[4], bfr[8][4];
        const uint32_t rowb = ((uint32_t)(ks * 16 + lr + lm * 8)) * KVSTR;
#pragma unroll
        for (int mt = 0; mt < 2; mt++) {
            ldm_x4_t(tmp, esb + (rowb + w * 32 + mt * 16 + lc * 8) * 2);
            afr[mt][0] = tmp[0]; afr[mt][1] = tmp[2];
            afr[mt][2] = tmp[1]; afr[mt][3] = tmp[3];
        }
#pragma unroll
        for (int p = 0; p < 8; p++)
            ldm_x4_t(bfr[p], vsb + (rowb + p * 16 + lc * 8) * 2);
#pragma unroll
        for (int mt = 0; mt < 2; mt++)
#pragma unroll
            for (int nt = 0; nt < 16; nt++)
                mma_16816(acc[mt][nt], afr[mt],
                          bfr[nt >> 1][(nt & 1) * 2], bfr[nt >> 1][(nt & 1) * 2 + 1]);
    }

    size_t base = ((size_t)bhk * NCH + n) * (HD * HD);
#pragma unroll
    for (int mt = 0; mt < 2; mt++) {
#pragma unroll
        for (int half = 0; half < 2; half++) {
            int d = w * 32 + mt * 16 + g + half * 8;
#pragma unroll
            for (int nt = 0; nt < 16; nt++) {
                float2 v2 = make_float2(acc[mt][nt][half * 2],
                                        acc[mt][nt][half * 2 + 1]);
                *(float2*)(g_kv + base + (size_t)d * HD + nt * 8 + qd) = v2;
            }
        }
    }
}

// ---------------------------------------------------------------------------
// K5: exclusive prefix sum over chunks -> fp16 g_cumh.
// ---------------------------------------------------------------------------
__global__ void k_prefix()
{
    int bhk  = blockIdx.x;
    int elem = blockIdx.y * 256 + threadIdx.x;
    size_t base = (size_t)bhk * NCH * (HD * HD) + elem;
    float acc = 0.f;
#pragma unroll
    for (int n = 0; n < NCH; n++) {
        g_cumh[base + (size_t)n * (HD * HD)] = __float2half(acc);
        acc += g_kv[base + (size_t)n * (HD * HD)];
    }
}

// ---------------------------------------------------------------------------
// K6: per-(b,h,chunk) attention on HMMA (unchanged from R8).
// ---------------------------------------------------------------------------
#define ASTR 136
#define ATILE (128 * ASTR)
#define ATTN2_SMEM (3 * ATILE * 2)   // 104448 bytes

__global__ __launch_bounds__(128, 2) void k_attn_tc()
{
    extern __shared__ __half smh[];
    __half* qs = smh;
    __half* es = smh + ATILE;
    __half* vs = smh + 2 * ATILE;

    const int bid = blockIdx.x;
    const int b = bid >> 8;
    const int h = (bid >> 4) & 15;
    const int n = bid & 15;
    const int hk = h >> 1;
    const int t = threadIdx.x, lane = t & 31, w = t >> 5;

    const __half* qb = g_qh  + (((size_t)(b * NH  + h ) * SEQL) + n * CHK) * HD;
    const __half* eb = g_ekh + (((size_t)(b * NKV + hk) * SEQL) + n * CHK) * HD;
    const __half* vb = g_vh  + (((size_t)(b * NKV + hk) * SEQL) + n * CHK) * HD;
    const __half* cb = g_cumh + ((size_t)(b * NKV + hk) * NCH + n) * (HD * HD);

    uint32_t qsb = smem_u32(qs), esb = smem_u32(es), vsb = smem_u32(vs);

#pragma unroll
    for (int it = 0; it < 16; it++) {
        int idx = it * 128 + t;
        int r = idx >> 4, seg = idx & 15;
        uint32_t so = ((uint32_t)r * ASTR + seg * 8) * 2;
        cp16(qsb + so, qb + (size_t)r * HD + seg * 8);
        cp16(esb + so, eb + (size_t)r * HD + seg * 8);
        cp16(vsb + so, vb + (size_t)r * HD + seg * 8);
    }
    cp_commit();
    cp_wait<0>();
    __syncthreads();

    const int lr = lane & 7, lm = (lane >> 3) & 1, lc = lane >> 4;
    const int g = lane >> 2, qd = (lane & 3) * 2;

    float sacc[2][16][4];
#pragma unroll
    for (int i = 0; i < 2; i++)
#pragma unroll
        for (int j = 0; j < 16; j++)
#pragma unroll
            for (int r = 0; r < 4; r++) sacc[i][j][r] = 0.f;

#pragma unroll
    for (int ks = 0; ks < 8; ks++) {
        uint32_t afr[2][4], bfr[8][4];
        const uint32_t coff = ((uint32_t)(ks * 16 + lc * 8)) * 2;
#pragma unroll
        for (int mt = 0; mt < 2; mt++)
            ldm_x4(afr[mt], qsb + ((uint32_t)(w * 32 + mt * 16 + lr + lm * 8) * ASTR) * 2 + coff);
#pragma unroll
        for (int p = 0; p < 8; p++)
            ldm_x4(bfr[p], esb + ((uint32_t)(p * 16 + lr + lm * 8) * ASTR) * 2 + coff);
#pragma unroll
        for (int mt = 0; mt < 2; mt++)
#pragma unroll
            for (int nt = 0; nt < 16; nt++)
                mma_16816(sacc[mt][nt], afr[mt],
                          bfr[nt >> 1][nt & 1], bfr[nt >> 1][(nt & 1) + 2]);
    }

    __syncthreads();
#pragma unroll
    for (int it = 0; it < 16; it++) {
        int idx = it * 128 + t;
        int r = idx >> 4, seg = idx & 15;
        cp16(esb + ((uint32_t)r * ASTR + seg * 8) * 2, cb + (size_t)r * HD + seg * 8);
    }
    cp_commit();

    uint32_t sfr[2][8][4];
#pragma unroll
    for (int mt = 0; mt < 2; mt++) {
        int c0 = w * 32 + mt * 16 + g;
#pragma unroll
        for (int j = 0; j < 8; j++) {
            int mA = j * 16 + qd;
            int mB = j * 16 + 8 + qd;
            float* e0 = sacc[mt][2 * j];
            float* e1 = sacc[mt][2 * j + 1];
            __half2 p0 = __floats2half2_rn(mA     <= c0     ? e0[0] : 0.f,
                                           mA + 1 <= c0     ? e0[1] : 0.f);
            __half2 p1 = __floats2half2_rn(mA     <= c0 + 8 ? e0[2] : 0.f,
                                           mA + 1 <= c0 + 8 ? e0[3] : 0.f);
            __half2 p2 = __floats2half2_rn(mB     <= c0     ? e1[0] : 0.f,
                                           mB + 1 <= c0     ? e1[1] : 0.f);
            __half2 p3 = __floats2half2_rn(mB     <= c0 + 8 ? e1[2] : 0.f,
                                           mB + 1 <= c0 + 8 ? e1[3] : 0.f);
            sfr[mt][j][0] = *(uint32_t*)&p0;
            sfr[mt][j][1] = *(uint32_t*)&p1;
            sfr[mt][j][2] = *(uint32_t*)&p2;
            sfr[mt][j][3] = *(uint32_t*)&p3;
        }
    }

    cp_wait<0>();
    __syncthreads();

#pragma unroll
    for (int eh = 0; eh < 2; eh++) {
        float oacc[2][8][4];
#pragma unroll
        for (int i = 0; i < 2; i++)
#pragma unroll
            for (int j = 0; j < 8; j++)
#pragma unroll
                for (int r = 0; r < 4; r++) oacc[i][j][r] = 0.f;

#pragma unroll
        for (int j = 0; j < 8; j++) {
            uint32_t vfr[4][4];
#pragma unroll
            for (int ep = 0; ep < 4; ep++)
                ldm_x4_t(vfr[ep],
                         vsb + ((uint32_t)(j * 16 + lr + lm * 8) * ASTR
                                + eh * 64 + ep * 16 + lc * 8) * 2);
#pragma unroll
            for (int mt = 0; mt < 2; mt++)
#pragma unroll
                for (int nt = 0; nt < 8; nt++)
                    mma_16816(oacc[mt][nt], sfr[mt][j],
                              vfr[nt >> 1][(nt & 1) * 2], vfr[nt >> 1][(nt & 1) * 2 + 1]);
        }

#pragma unroll
        for (int ks = 0; ks < 8; ks++) {
            uint32_t afr[2][4], cfr[4][4];
            const uint32_t coff = ((uint32_t)(ks * 16 + lc * 8)) * 2;
#pragma unroll
            for (int mt = 0; mt < 2; mt++)
                ldm_x4(afr[mt], qsb + ((uint32_t)(w * 32 + mt * 16 + lr + lm * 8) * ASTR) * 2 + coff);
#pragma unroll
            for (int ep = 0; ep < 4; ep++)
                ldm_x4_t(cfr[ep],
                         esb + ((uint32_t)(ks * 16 + lr + lm * 8) * ASTR
                                + eh * 64 + ep * 16 + lc * 8) * 2);
#pragma unroll
            for (int mt = 0; mt < 2; mt++)
#pragma unroll
                for (int nt = 0; nt < 8; nt++)
                    mma_16816(oacc[mt][nt], afr[mt],
                              cfr[nt >> 1][(nt & 1) * 2], cfr[nt >> 1][(nt & 1) * 2 + 1]);
        }

#pragma unroll
        for (int mt = 0; mt < 2; mt++) {
#pragma unroll
            for (int half = 0; half < 2; half++) {
                int c = w * 32 + mt * 16 + g + half * 8;
                int s = n * CHK + c;
                unsigned short* orow = g_a2 + (size_t)(b * SEQL + s) * KP + h * HD;
#pragma unroll
                for (int nt = 0; nt < 8; nt++) {
                    int e = eh * 64 + nt * 8 + qd;
                    __half2 h2 = __floats2half2_rn(oacc[mt][nt][half * 2] * QDESCALE,
                                                   oacc[mt][nt][half * 2 + 1] * QDESCALE);
                    *(__half2*)(orow + e) = h2;
                }
            }
        }
    }
}

// ---------------------------------------------------------------------------
extern "C" void kernel_launch(void* const* d_in, const int* in_sizes, int n_in,
                              void* d_out, int out_size)
{
    const float* x  = (const float*)d_in[0];
    const float* fc = (const float*)d_in[1];
    const float* wq = (const float*)d_in[2];
    const float* wk = (const float*)d_in[3];
    const float* wv = (const float*)d_in[4];
    const float* wo = (const float*)d_in[5];
    float* out = (float*)d_out;

    cudaFuncSetAttribute(k_gemm_mma, cudaFuncAttributeMaxDynamicSharedMemorySize, GEMM_SMEM);
    cudaFuncSetAttribute(k_attn_tc, cudaFuncAttributeMaxDynamicSharedMemorySize, ATTN2_SMEM);
    cudaFuncSetAttribute(k_kvchunk_tc, cudaFuncAttributeMaxDynamicSharedMemorySize, KV_SMEM);

    void *p_x2, *p_w2, *p_a2, *p_wo2;
    cudaGetSymbolAddress(&p_x2, g_x2);
    cudaGetSymbolAddress(&p_w2, g_w2);
    cudaGetSymbolAddress(&p_a2, g_a2);
    cudaGetSymbolAddress(&p_wo2, g_wo2);
    unsigned short* x2  = (unsigned short*)p_x2;
    unsigned short* w2  = (unsigned short*)p_w2;
    unsigned short* a2  = (unsigned short*)p_a2;
    unsigned short* wo2 = (unsigned short*)p_wo2;

    // fp32 -> fp16 conversions
    k_cvt<<<4096, 256>>>(x,  x2);
    k_cvt<<<2048, 256>>>(wq, w2);
    k_cvt<<<1024, 256>>>(wk, w2 + (size_t)2048 * KP);
    k_cvt<<<1024, 256>>>(wv, w2 + (size_t)3072 * KP);
    k_cvt<<<2048, 256>>>(wo, wo2);

    // QKV projection (q/k fp32 scatter, v fp16)
    k_gemm_mma<<<dim3(32, 32), 128, GEMM_SMEM>>>(
        (const __half*)x2, (const __half*)w2, nullptr, 0);

    // RoPE + softmaxes
    k_zero<<<2, 1024>>>();
    k_rope_k<<<dim3(16, 32), 256>>>(fc);
    k_rope_q<<<8192, 256>>>(fc);

    // chunked linear attention (all tensor-core now)
    k_kvchunk_tc<<<256, 128, KV_SMEM>>>();
    k_prefix<<<dim3(16, 64), 256>>>();
    k_attn_tc<<<512, 128, ATTN2_SMEM>>>();

    // output projection
    k_gemm_mma<<<dim3(16, 32), 128, GEMM_SMEM>>>(
        (const __half*)a2, (const __half*)wo2, out, 1);
}

// round 10
// speedup vs baseline: 6.2633x; 1.0201x over previous
#include <cuda_runtime.h>
#include <cuda_fp16.h>
#include <cstdint>

// Problem constants
#define BATCHN 2
#define SEQL   2048
#define DIMN   2048
#define NH     16
#define NKV    8
#define HD     128
#define NCH    16
#define CHK    128
#define KP     2048
#define BKC    64
#define STR    72
#define NITG   (KP / BKC)   // 32

#define QSCALE   4096.0f
#define QDESCALE (1.0f / 4096.0f)

// ---------------------------------------------------------------------------
// Scratch
// ---------------------------------------------------------------------------
__device__ float g_kv[(size_t)BATCHN * NKV * NCH * HD * HD];
__device__ float g_colsum[BATCHN * NKV * HD];

__device__ unsigned short g_x2[(size_t)4096 * KP];
__device__ unsigned short g_w2[(size_t)4096 * KP];
__device__ unsigned short g_a2[(size_t)4096 * KP];
__device__ unsigned short g_wo2[(size_t)2048 * KP];

__device__ __half g_qh0[(size_t)BATCHN * NH * SEQL * HD];   // raw q (pre-rope) fp16
__device__ __half g_kh[(size_t)BATCHN * NKV * SEQL * HD];   // raw k (pre-rope) fp16
__device__ __half g_qh[(size_t)BATCHN * NH * SEQL * HD];    // q' * QSCALE
__device__ __half g_ekh[(size_t)BATCHN * NKV * SEQL * HD];  // exp(rope(k))
__device__ __half g_vh[(size_t)BATCHN * NKV * SEQL * HD];   // v
__device__ __half g_cumh[(size_t)BATCHN * NKV * NCH * HD * HD];

// ---------------------------------------------------------------------------
// PTX helpers
// ---------------------------------------------------------------------------
__device__ __forceinline__ uint32_t smem_u32(const void* p) {
    uint32_t a;
    asm("{ .reg .u64 t; cvta.to.shared.u64 t, %1; cvt.u32.u64 %0, t; }"
        : "=r"(a) : "l"(p));
    return a;
}
__device__ __forceinline__ void ldm_x4(uint32_t* r, uint32_t addr) {
    asm volatile("ldmatrix.sync.aligned.m8n8.x4.shared.b16 {%0,%1,%2,%3}, [%4];"
                 : "=r"(r[0]), "=r"(r[1]), "=r"(r[2]), "=r"(r[3]) : "r"(addr));
}
__device__ __forceinline__ void ldm_x4_t(uint32_t* r, uint32_t addr) {
    asm volatile("ldmatrix.sync.aligned.m8n8.x4.trans.shared.b16 {%0,%1,%2,%3}, [%4];"
                 : "=r"(r[0]), "=r"(r[1]), "=r"(r[2]), "=r"(r[3]) : "r"(addr));
}
__device__ __forceinline__ void mma_16816(float* c, const uint32_t* a,
                                          uint32_t b0, uint32_t b1) {
    asm volatile(
        "mma.sync.aligned.m16n8k16.row.col.f32.f16.f16.f32 "
        "{%0,%1,%2,%3}, {%4,%5,%6,%7}, {%8,%9}, {%0,%1,%2,%3};"
        : "+f"(c[0]), "+f"(c[1]), "+f"(c[2]), "+f"(c[3])
        : "r"(a[0]), "r"(a[1]), "r"(a[2]), "r"(a[3]), "r"(b0), "r"(b1));
}
__device__ __forceinline__ void cp16(uint32_t s, const void* g) {
    asm volatile("cp.async.cg.shared.global [%0], [%1], 16;" :: "r"(s), "l"(g));
}
__device__ __forceinline__ void cp_commit() {
    asm volatile("cp.async.commit_group;" ::: "memory");
}
template <int N> __device__ __forceinline__ void cp_wait() {
    asm volatile("cp.async.wait_group %0;" :: "n"(N) : "memory");
}

// ---------------------------------------------------------------------------
// Fused fp32 -> fp16 conversion for all inputs. Block ranges:
//   [0,4096)      x  -> g_x2      (8M elems)
//   [4096,6144)   wq -> g_w2[0]   (4M)
//   [6144,7168)   wk -> g_w2+2048*KP (2M)
//   [7168,8192)   wv -> g_w2+3072*KP (2M)
//   [8192,10240)  wo -> g_wo2     (4M)
// Each block converts 2048 elems (256 thr x 8).
// ---------------------------------------------------------------------------
__global__ __launch_bounds__(256) void k_cvt_all(
    const float* __restrict__ x,  const float* __restrict__ wq,
    const float* __restrict__ wk, const float* __restrict__ wv,
    const float* __restrict__ wo)
{
    int blk = blockIdx.x;
    const float* src;
    unsigned short* dst;
    size_t base;
    if (blk < 4096)      { src = x;  dst = g_x2;  base = (size_t)blk * 2048; }
    else if (blk < 6144) { src = wq; dst = g_w2;  base = (size_t)(blk - 4096) * 2048; }
    else if (blk < 7168) { src = wk; dst = g_w2 + (size_t)2048 * KP; base = (size_t)(blk - 6144) * 2048; }
    else if (blk < 8192) { src = wv; dst = g_w2 + (size_t)3072 * KP; base = (size_t)(blk - 7168) * 2048; }
    else                 { src = wo; dst = g_wo2; base = (size_t)(blk - 8192) * 2048; }

    size_t i = base + (size_t)threadIdx.x * 8;
    float4 v0 = *(const float4*)(src + i);
    float4 v1 = *(const float4*)(src + i + 4);
    float f[8] = {v0.x, v0.y, v0.z, v0.w, v1.x, v1.y, v1.z, v1.w};
    __align__(16) __half o[8];
#pragma unroll
    for (int j = 0; j < 8; j++) o[j] = __float2half(f[j]);
    *(uint4*)(dst + i) = *(const uint4*)o;
}

// ---------------------------------------------------------------------------
// HMMA fp16 GEMM.
// mode 0: scatter q/k/v all fp16 (g_qh0 / g_kh / g_vh).  mode 1: fp32 C.
// ---------------------------------------------------------------------------
#define A_BUF (128 * STR)
#define B_BUF (128 * STR)
#define GEMM_SMEM ((3 * (A_BUF + B_BUF)) * 2)   // 110592 bytes

__global__ __launch_bounds__(128, 2) void k_gemm_mma(
    const __half* __restrict__ A, const __half* __restrict__ B,
    float* __restrict__ C, int mode)
{
    extern __shared__ char smraw[];
    __half* sA = (__half*)smraw;
    __half* sB = sA + 3 * A_BUF;

    const int t = threadIdx.x, lane = t & 31, wid = t >> 5;
    const int wm = wid >> 1, wn = wid & 1;
    const int m0 = blockIdx.y * 128, n0 = blockIdx.x * 128;

    uint32_t sAb = smem_u32(sA);
    uint32_t sBb = smem_u32(sB);

    const __half* ga = A + (size_t)(m0 + (t >> 3)) * KP + (t & 7) * 8;
    const __half* gb = B + (size_t)(n0 + (t >> 3)) * KP + (t & 7) * 8;
    const uint32_t so = ((uint32_t)(t >> 3) * STR + (t & 7) * 8) * 2;

    auto load_tile = [&](int buf, int i) {
        uint32_t sa = sAb + (uint32_t)buf * A_BUF * 2 + so;
        uint32_t sb = sBb + (uint32_t)buf * B_BUF * 2 + so;
        int ko = i * BKC;
#pragma unroll
        for (int j = 0; j < 8; j++)
            cp16(sa + j * 16 * STR * 2, ga + (size_t)j * 16 * KP + ko);
#pragma unroll
        for (int j = 0; j < 8; j++)
            cp16(sb + j * 16 * STR * 2, gb + (size_t)j * 16 * KP + ko);
        cp_commit();
    };

    float acc[4][8][4];
#pragma unroll
    for (int i = 0; i < 4; i++)
#pragma unroll
        for (int j = 0; j < 8; j++)
#pragma unroll
            for (int r = 0; r < 4; r++) acc[i][j][r] = 0.f;

    const int lr = lane & 7;
    const int lm = (lane >> 3) & 1;
    const int lc = lane >> 4;

    load_tile(0, 0);
    load_tile(1, 1);

    for (int i = 0; i < NITG; i++) {
        if (i == NITG - 1) cp_wait<0>(); else cp_wait<1>();
        __syncthreads();

        int buf = i % 3;
        uint32_t sa = sAb + (uint32_t)buf * A_BUF * 2;
        uint32_t sb = sBb + (uint32_t)buf * B_BUF * 2;
#pragma unroll
        for (int ks = 0; ks < 4; ks++) {
            uint32_t afr[4][4], bfr[4][4];
            const uint32_t coff = ((uint32_t)(ks * 16 + lc * 8)) * 2;
#pragma unroll
            for (int mt = 0; mt < 4; mt++)
                ldm_x4(afr[mt],
                       sa + ((uint32_t)(wm * 64 + mt * 16 + lr + lm * 8) * STR) * 2 + coff);
#pragma unroll
            for (int nt2 = 0; nt2 < 4; nt2++)
                ldm_x4(bfr[nt2],
                       sb + ((uint32_t)(wn * 64 + nt2 * 16 + lr + lm * 8) * STR) * 2 + coff);
#pragma unroll
            for (int mt = 0; mt < 4; mt++)
#pragma unroll
                for (int nt = 0; nt < 8; nt++)
                    mma_16816(acc[mt][nt], afr[mt],
                              bfr[nt >> 1][nt & 1], bfr[nt >> 1][(nt & 1) + 2]);
        }

        if (i + 2 < NITG) load_tile((i + 2) % 3, i + 2);
    }

    // epilogue
    const int g = lane >> 2, c2 = (lane & 3) * 2;
#pragma unroll
    for (int mt = 0; mt < 4; mt++) {
#pragma unroll
        for (int half = 0; half < 2; half++) {
            int m = m0 + wm * 64 + mt * 16 + g + half * 8;
            if (mode == 0) {
                int b = m >> 11, s = m & 2047;
                int ht = n0 >> 7;
                __half* dsth;
                if (ht < 16)
                    dsth = g_qh0 + (((size_t)(b * NH + ht)) * SEQL + s) * HD;
                else if (ht < 24)
                    dsth = g_kh + (((size_t)(b * NKV + (ht - 16))) * SEQL + s) * HD;
                else
                    dsth = g_vh + (((size_t)(b * NKV + (ht - 24))) * SEQL + s) * HD;
#pragma unroll
                for (int nt = 0; nt < 8; nt++) {
                    int col = wn * 64 + nt * 8 + c2;
                    __half2 h2 = __floats2half2_rn(acc[mt][nt][half * 2],
                                                   acc[mt][nt][half * 2 + 1]);
                    *(__half2*)(dsth + col) = h2;
                }
            } else {
                float* dst = C + (size_t)m * DIMN + n0;
#pragma unroll
                for (int nt = 0; nt < 8; nt++) {
                    int col = wn * 64 + nt * 8 + c2;
                    float2 v2 = make_float2(acc[mt][nt][half * 2],
                                            acc[mt][nt][half * 2 + 1]);
                    *(float2*)(dst + col) = v2;
                }
            }
        }
    }
}

// ---------------------------------------------------------------------------
// K3: ekh = exp(rope(kh)) fp16; accumulate column sums (fp32).
// ---------------------------------------------------------------------------
__global__ __launch_bounds__(256) void k_rope_k(const float* __restrict__ fc)
{
    __shared__ float s_part[8][128];
    int bhk = blockIdx.x;
    int w   = threadIdx.x >> 5;
    int l   = threadIdx.x & 31;
    float sum0 = 0.f, sum1 = 0.f, sum2 = 0.f, sum3 = 0.f;
#pragma unroll
    for (int r = 0; r < 8; r++) {
        int s = blockIdx.y * 64 + w * 8 + r;
        size_t off = ((size_t)bhk * SEQL + s) * HD + l * 4;
        __half2 a0 = *(const __half2*)(g_kh + off);
        __half2 a1 = *(const __half2*)(g_kh + off + 2);
        float vx = __low2float(a0), vy = __high2float(a0);
        float vz = __low2float(a1), vw = __high2float(a1);
        float4 f = *(const float4*)(fc + (size_t)s * HD + l * 4);
        float o0 = vx * f.x - vy * f.y;
        float o1 = vx * f.y + vy * f.x;
        float o2 = vz * f.z - vw * f.w;
        float o3 = vz * f.w + vw * f.z;
        float e0 = expf(o0), e1 = expf(o1), e2 = expf(o2), e3 = expf(o3);
        *(__half2*)(g_ekh + off)     = __floats2half2_rn(e0, e1);
        *(__half2*)(g_ekh + off + 2) = __floats2half2_rn(e2, e3);
        sum0 += e0; sum1 += e1; sum2 += e2; sum3 += e3;
    }
    s_part[w][l * 4 + 0] = sum0;
    s_part[w][l * 4 + 1] = sum1;
    s_part[w][l * 4 + 2] = sum2;
    s_part[w][l * 4 + 3] = sum3;
    __syncthreads();
    if (threadIdx.x < 128) {
        float a = 0.f;
#pragma unroll
        for (int w2 = 0; w2 < 8; w2++) a += s_part[w2][threadIdx.x];
        atomicAdd(&g_colsum[bhk * HD + threadIdx.x], a);
    }
}

// ---------------------------------------------------------------------------
// K2: q' = softmax(rope(qh0)*s)/colsum * QSCALE -> fp16.
// ---------------------------------------------------------------------------
__global__ __launch_bounds__(256) void k_rope_q(const float* __restrict__ fc)
{
    int r = blockIdx.x * 8 + (threadIdx.x >> 5);
    int l = threadIdx.x & 31;
    int s  = r & 2047;
    int bh = r >> 11;
    int h  = bh & 15;
    int b  = bh >> 4;

    size_t off = (size_t)r * HD + l * 4;
    __half2 a0 = *(const __half2*)(g_qh0 + off);
    __half2 a1 = *(const __half2*)(g_qh0 + off + 2);
    float vx = __low2float(a0), vy = __high2float(a0);
    float vz = __low2float(a1), vw = __high2float(a1);
    float4 f = *(const float4*)(fc + (size_t)s * HD + l * 4);
    const float scale = 0.08838834764831845f;
    float o0 = (vx * f.x - vy * f.y) * scale;
    float o1 = (vx * f.y + vy * f.x) * scale;
    float o2 = (vz * f.z - vw * f.w) * scale;
    float o3 = (vz * f.w + vw * f.z) * scale;

    float mx = fmaxf(fmaxf(o0, o1), fmaxf(o2, o3));
#pragma unroll
    for (int off2 = 16; off2; off2 >>= 1) mx = fmaxf(mx, __shfl_xor_sync(0xffffffffu, mx, off2));
    float e0 = expf(o0 - mx), e1 = expf(o1 - mx), e2 = expf(o2 - mx), e3 = expf(o3 - mx);
    float ss = e0 + e1 + e2 + e3;
#pragma unroll
    for (int off2 = 16; off2; off2 >>= 1) ss += __shfl_xor_sync(0xffffffffu, ss, off2);
    float inv = QSCALE / ss;

    const float* csp = g_colsum + ((b * NKV + (h >> 1)) * HD) + l * 4;
    float4 cs = *(const float4*)csp;
    __half* qp = g_qh + off;
    *(__half2*)(qp)     = __floats2half2_rn(e0 * inv / cs.x, e1 * inv / cs.y);
    *(__half2*)(qp + 2) = __floats2half2_rn(e2 * inv / cs.z, e3 * inv / cs.w);
}

// ---------------------------------------------------------------------------
// K4: per-chunk kv = ek^T @ v on HMMA (fp16 in, fp32 out).
// ---------------------------------------------------------------------------
#define KVSTR 136
#define KV_SMEM (2 * 128 * KVSTR * 2)   // 69632 bytes

__global__ __launch_bounds__(128, 2) void k_kvchunk_tc()
{
    extern __shared__ __half smkv[];
    __half* es = smkv;
    __half* vs = smkv + 128 * KVSTR;

    const int bhk = blockIdx.x >> 4;
    const int n   = blockIdx.x & 15;
    const __half* eb = g_ekh + ((size_t)bhk * SEQL + n * CHK) * HD;
    const __half* vb = g_vh  + ((size_t)bhk * SEQL + n * CHK) * HD;
    const int t = threadIdx.x, lane = t & 31, w = t >> 5;
    uint32_t esb = smem_u32(es), vsb = smem_u32(vs);

#pragma unroll
    for (int it = 0; it < 16; it++) {
        int idx = it * 128 + t;
        int r = idx >> 4, seg = idx & 15;
        uint32_t so = ((uint32_t)r * KVSTR + seg * 8) * 2;
        cp16(esb + so, eb + (size_t)r * HD + seg * 8);
        cp16(vsb + so, vb + (size_t)r * HD + seg * 8);
    }
    cp_commit();
    cp_wait<0>();
    __syncthreads();

    const int lr = lane & 7, lm = (lane >> 3) & 1, lc = lane >> 4;
    const int g = lane >> 2, qd = (lane & 3) * 2;

    float acc[2][16][4];
#pragma unroll
    for (int i = 0; i < 2; i++)
#pragma unroll
        for (int j = 0; j < 16; j++)
#pragma unroll
            for (int r = 0; r < 4; r++) acc[i][j][r] = 0.f;

#pragma unroll
    for (int ks = 0; ks < 8; ks++) {
        uint32_t afr[2][4], tmp[4], bfr[8][4];
        const uint32_t rowb = ((uint32_t)(ks * 16 + lr + lm * 8)) * KVSTR;
#pragma unroll
        for (int mt = 0; mt < 2; mt++) {
            ldm_x4_t(tmp, esb + (rowb + w * 32 + mt * 16 + lc * 8) * 2);
            afr[mt][0] = tmp[0]; afr[mt][1] = tmp[2];
            afr[mt][2] = tmp[1]; afr[mt][3] = tmp[3];
        }
#pragma unroll
        for (int p = 0; p < 8; p++)
            ldm_x4_t(bfr[p], vsb + (rowb + p * 16 + lc * 8) * 2);
#pragma unroll
        for (int mt = 0; mt < 2; mt++)
#pragma unroll
            for (int nt = 0; nt < 16; nt++)
                mma_16816(acc[mt][nt], afr[mt],
                          bfr[nt >> 1][(nt & 1) * 2], bfr[nt >> 1][(nt & 1) * 2 + 1]);
    }

    size_t base = ((size_t)bhk * NCH + n) * (HD * HD);
#pragma unroll
    for (int mt = 0; mt < 2; mt++) {
#pragma unroll
        for (int half = 0; half < 2; half++) {
            int d = w * 32 + mt * 16 + g + half * 8;
#pragma unroll
            for (int nt = 0; nt < 16; nt++) {
                float2 v2 = make_float2(acc[mt][nt][half * 2],
                                        acc[mt][nt][half * 2 + 1]);
                *(float2*)(g_kv + base + (size_t)d * HD + nt * 8 + qd) = v2;
            }
        }
    }
}

// ---------------------------------------------------------------------------
// K5: exclusive prefix sum over chunks -> fp16 g_cumh.
// ---------------------------------------------------------------------------
__global__ void k_prefix()
{
    int bhk  = blockIdx.x;
    int elem = blockIdx.y * 256 + threadIdx.x;
    size_t base = (size_t)bhk * NCH * (HD * HD) + elem;
    float acc = 0.f;
#pragma unroll
    for (int n = 0; n < NCH; n++) {
        g_cumh[base + (size_t)n * (HD * HD)] = __float2half(acc);
        acc += g_kv[base + (size_t)n * (HD * HD)];
    }
}

// ---------------------------------------------------------------------------
// K6: per-(b,h,chunk) attention on HMMA.
// ---------------------------------------------------------------------------
#define ASTR 136
#define ATILE (128 * ASTR)
#define ATTN2_SMEM (3 * ATILE * 2)   // 104448 bytes

__global__ __launch_bounds__(128, 2) void k_attn_tc()
{
    extern __shared__ __half smh[];
    __half* qs = smh;
    __half* es = smh + ATILE;
    __half* vs = smh + 2 * ATILE;

    const int bid = blockIdx.x;
    const int b = bid >> 8;
    const int h = (bid >> 4) & 15;
    const int n = bid & 15;
    const int hk = h >> 1;
    const int t = threadIdx.x, lane = t & 31, w = t >> 5;

    const __half* qb = g_qh  + (((size_t)(b * NH  + h ) * SEQL) + n * CHK) * HD;
    const __half* eb = g_ekh + (((size_t)(b * NKV + hk) * SEQL) + n * CHK) * HD;
    const __half* vb = g_vh  + (((size_t)(b * NKV + hk) * SEQL) + n * CHK) * HD;
    const __half* cb = g_cumh + ((size_t)(b * NKV + hk) * NCH + n) * (HD * HD);

    uint32_t qsb = smem_u32(qs), esb = smem_u32(es), vsb = smem_u32(vs);

#pragma unroll
    for (int it = 0; it < 16; it++) {
        int idx = it * 128 + t;
        int r = idx >> 4, seg = idx & 15;
        uint32_t so = ((uint32_t)r * ASTR + seg * 8) * 2;
        cp16(qsb + so, qb + (size_t)r * HD + seg * 8);
        cp16(esb + so, eb + (size_t)r * HD + seg * 8);
        cp16(vsb + so, vb + (size_t)r * HD + seg * 8);
    }
    cp_commit();
    cp_wait<0>();
    __syncthreads();

    const int lr = lane & 7, lm = (lane >> 3) & 1, lc = lane >> 4;
    const int g = lane >> 2, qd = (lane & 3) * 2;

    float sacc[2][16][4];
#pragma unroll
    for (int i = 0; i < 2; i++)
#pragma unroll
        for (int j = 0; j < 16; j++)
#pragma unroll
            for (int r = 0; r < 4; r++) sacc[i][j][r] = 0.f;

#pragma unroll
    for (int ks = 0; ks < 8; ks++) {
        uint32_t afr[2][4], bfr[8][4];
        const uint32_t coff = ((uint32_t)(ks * 16 + lc * 8)) * 2;
#pragma unroll
        for (int mt = 0; mt < 2; mt++)
            ldm_x4(afr[mt], qsb + ((uint32_t)(w * 32 + mt * 16 + lr + lm * 8) * ASTR) * 2 + coff);
#pragma unroll
        for (int p = 0; p < 8; p++)
            ldm_x4(bfr[p], esb + ((uint32_t)(p * 16 + lr + lm * 8) * ASTR) * 2 + coff);
#pragma unroll
        for (int mt = 0; mt < 2; mt++)
#pragma unroll
            for (int nt = 0; nt < 16; nt++)
                mma_16816(sacc[mt][nt], afr[mt],
                          bfr[nt >> 1][nt & 1], bfr[nt >> 1][(nt & 1) + 2]);
    }

    __syncthreads();
#pragma unroll
    for (int it = 0; it < 16; it++) {
        int idx = it * 128 + t;
        int r = idx >> 4, seg = idx & 15;
        cp16(esb + ((uint32_t)r * ASTR + seg * 8) * 2, cb + (size_t)r * HD + seg * 8);
    }
    cp_commit();

    uint32_t sfr[2][8][4];
#pragma unroll
    for (int mt = 0; mt < 2; mt++) {
        int c0 = w * 32 + mt * 16 + g;
#pragma unroll
        for (int j = 0; j < 8; j++) {
            int mA = j * 16 + qd;
            int mB = j * 16 + 8 + qd;
            float* e0 = sacc[mt][2 * j];
            float* e1 = sacc[mt][2 * j + 1];
            __half2 p0 = __floats2half2_rn(mA     <= c0     ? e0[0] : 0.f,
                                           mA + 1 <= c0     ? e0[1] : 0.f);
            __half2 p1 = __floats2half2_rn(mA     <= c0 + 8 ? e0[2] : 0.f,
                                           mA + 1 <= c0 + 8 ? e0[3] : 0.f);
            __half2 p2 = __floats2half2_rn(mB     <= c0     ? e1[0] : 0.f,
                                           mB + 1 <= c0     ? e1[1] : 0.f);
            __half2 p3 = __floats2half2_rn(mB     <= c0 + 8 ? e1[2] : 0.f,
                                           mB + 1 <= c0 + 8 ? e1[3] : 0.f);
            sfr[mt][j][0] = *(uint32_t*)&p0;
            sfr[mt][j][1] = *(uint32_t*)&p1;
            sfr[mt][j][2] = *(uint32_t*)&p2;
            sfr[mt][j][3] = *(uint32_t*)&p3;
        }
    }

    cp_wait<0>();
    __syncthreads();

#pragma unroll
    for (int eh = 0; eh < 2; eh++) {
        float oacc[2][8][4];
#pragma unroll
        for (int i = 0; i < 2; i++)
#pragma unroll
            for (int j = 0; j < 8; j++)
#pragma unroll
                for (int r = 0; r < 4; r++) oacc[i][j][r] = 0.f;

#pragma unroll
        for (int j = 0; j < 8; j++) {
            uint32_t vfr[4][4];
#pragma unroll
            for (int ep = 0; ep < 4; ep++)
                ldm_x4_t(vfr[ep],
                         vsb + ((uint32_t)(j * 16 + lr + lm * 8) * ASTR
                                + eh * 64 + ep * 16 + lc * 8) * 2);
#pragma unroll
            for (int mt = 0; mt < 2; mt++)
#pragma unroll
                for (int nt = 0; nt < 8; nt++)
                    mma_16816(oacc[mt][nt], sfr[mt][j],
                              vfr[nt >> 1][(nt & 1) * 2], vfr[nt >> 1][(nt & 1) * 2 + 1]);
        }

#pragma unroll
        for (int ks = 0; ks < 8; ks++) {
            uint32_t afr[2][4], cfr[4][4];
            const uint32_t coff = ((uint32_t)(ks * 16 + lc * 8)) * 2;
#pragma unroll
            for (int mt = 0; mt < 2; mt++)
                ldm_x4(afr[mt], qsb + ((uint32_t)(w * 32 + mt * 16 + lr + lm * 8) * ASTR) * 2 + coff);
#pragma unroll
            for (int ep = 0; ep < 4; ep++)
                ldm_x4_t(cfr[ep],
                         esb + ((uint32_t)(ks * 16 + lr + lm * 8) * ASTR
                                + eh * 64 + ep * 16 + lc * 8) * 2);
#pragma unroll
            for (int mt = 0; mt < 2; mt++)
#pragma unroll
                for (int nt = 0; nt < 8; nt++)
                    mma_16816(oacc[mt][nt], afr[mt],
                              cfr[nt >> 1][(nt & 1) * 2], cfr[nt >> 1][(nt & 1) * 2 + 1]);
        }

#pragma unroll
        for (int mt = 0; mt < 2; mt++) {
#pragma unroll
            for (int half = 0; half < 2; half++) {
                int c = w * 32 + mt * 16 + g + half * 8;
                int s = n * CHK + c;
                unsigned short* orow = g_a2 + (size_t)(b * SEQL + s) * KP + h * HD;
#pragma unroll
                for (int nt = 0; nt < 8; nt++) {
                    int e = eh * 64 + nt * 8 + qd;
                    __half2 h2 = __floats2half2_rn(oacc[mt][nt][half * 2] * QDESCALE,
                                                   oacc[mt][nt][half * 2 + 1] * QDESCALE);
                    *(__half2*)(orow + e) = h2;
                }
            }
        }
    }
}

// ---------------------------------------------------------------------------
extern "C" void kernel_launch(void* const* d_in, const int* in_sizes, int n_in,
                              void* d_out, int out_size)
{
    const float* x  = (const float*)d_in[0];
    const float* fc = (const float*)d_in[1];
    const float* wq = (const float*)d_in[2];
    const float* wk = (const float*)d_in[3];
    const float* wv = (const float*)d_in[4];
    const float* wo = (const float*)d_in[5];
    float* out = (float*)d_out;

    cudaFuncSetAttribute(k_gemm_mma, cudaFuncAttributeMaxDynamicSharedMemorySize, GEMM_SMEM);
    cudaFuncSetAttribute(k_attn_tc, cudaFuncAttributeMaxDynamicSharedMemorySize, ATTN2_SMEM);
    cudaFuncSetAttribute(k_kvchunk_tc, cudaFuncAttributeMaxDynamicSharedMemorySize, KV_SMEM);

    void *p_x2, *p_w2, *p_a2, *p_wo2, *p_cs;
    cudaGetSymbolAddress(&p_x2, g_x2);
    cudaGetSymbolAddress(&p_w2, g_w2);
    cudaGetSymbolAddress(&p_a2, g_a2);
    cudaGetSymbolAddress(&p_wo2, g_wo2);
    cudaGetSymbolAddress(&p_cs, g_colsum);
    unsigned short* x2  = (unsigned short*)p_x2;
    unsigned short* w2  = (unsigned short*)p_w2;
    unsigned short* a2  = (unsigned short*)p_a2;
    unsigned short* wo2 = (unsigned short*)p_wo2;

    // all conversions in one kernel; colsum zero as a memset node
    k_cvt_all<<<10240, 256>>>(x, wq, wk, wv, wo);
    cudaMemsetAsync(p_cs, 0, BATCHN * NKV * HD * sizeof(float));

    // QKV projection (q/k/v all fp16 scatter)
    k_gemm_mma<<<dim3(32, 32), 128, GEMM_SMEM>>>(
        (const __half*)x2, (const __half*)w2, nullptr, 0);

    // RoPE + softmaxes
    k_rope_k<<<dim3(16, 32), 256>>>(fc);
    k_rope_q<<<8192, 256>>>(fc);

    // chunked linear attention (all tensor-core)
    k_kvchunk_tc<<<256, 128, KV_SMEM>>>();
    k_prefix<<<dim3(16, 64), 256>>>();
    k_attn_tc<<<512, 128, ATTN2_SMEM>>>();

    // output projection
    k_gemm_mma<<<dim3(16, 32), 128, GEMM_SMEM>>>(
        (const __half*)a2, (const __half*)wo2, out, 1);
}

// round 11
// speedup vs baseline: 6.2942x; 1.0049x over previous
#include <cuda_runtime.h>
#include <cuda_fp16.h>
#include <cstdint>

// Problem constants
#define BATCHN 2
#define SEQL   2048
#define DIMN   2048
#define NH     16
#define NKV    8
#define HD     128
#define NCH    16
#define CHK    128
#define KP     2048
#define BKC    64
#define STR    72
#define NITG   (KP / BKC)   // 32

#define QSCALE   4096.0f
#define QDESCALE (1.0f / 4096.0f)

// ---------------------------------------------------------------------------
// Scratch
// ---------------------------------------------------------------------------
__device__ float g_kv[(size_t)BATCHN * NKV * NCH * HD * HD];
__device__ float g_colsum[BATCHN * NKV * HD];

__device__ unsigned short g_x2[(size_t)4096 * KP];
__device__ unsigned short g_w2[(size_t)4096 * KP];
__device__ unsigned short g_a2[(size_t)4096 * KP];
__device__ unsigned short g_wo2[(size_t)2048 * KP];

__device__ __half g_qh0[(size_t)BATCHN * NH * SEQL * HD];   // raw q (pre-rope) fp16
__device__ __half g_kh[(size_t)BATCHN * NKV * SEQL * HD];   // raw k (pre-rope) fp16
__device__ __half g_qh[(size_t)BATCHN * NH * SEQL * HD];    // q' * QSCALE
__device__ __half g_ekh[(size_t)BATCHN * NKV * SEQL * HD];  // exp(rope(k))
__device__ __half g_vh[(size_t)BATCHN * NKV * SEQL * HD];   // v
__device__ __half g_cumh[(size_t)BATCHN * NKV * NCH * HD * HD];

// ---------------------------------------------------------------------------
// PTX helpers
// ---------------------------------------------------------------------------
__device__ __forceinline__ uint32_t smem_u32(const void* p) {
    uint32_t a;
    asm("{ .reg .u64 t; cvta.to.shared.u64 t, %1; cvt.u32.u64 %0, t; }"
        : "=r"(a) : "l"(p));
    return a;
}
__device__ __forceinline__ void ldm_x4(uint32_t* r, uint32_t addr) {
    asm volatile("ldmatrix.sync.aligned.m8n8.x4.shared.b16 {%0,%1,%2,%3}, [%4];"
                 : "=r"(r[0]), "=r"(r[1]), "=r"(r[2]), "=r"(r[3]) : "r"(addr));
}
__device__ __forceinline__ void ldm_x4_t(uint32_t* r, uint32_t addr) {
    asm volatile("ldmatrix.sync.aligned.m8n8.x4.trans.shared.b16 {%0,%1,%2,%3}, [%4];"
                 : "=r"(r[0]), "=r"(r[1]), "=r"(r[2]), "=r"(r[3]) : "r"(addr));
}
__device__ __forceinline__ void mma_16816(float* c, const uint32_t* a,
                                          uint32_t b0, uint32_t b1) {
    asm volatile(
        "mma.sync.aligned.m16n8k16.row.col.f32.f16.f16.f32 "
        "{%0,%1,%2,%3}, {%4,%5,%6,%7}, {%8,%9}, {%0,%1,%2,%3};"
        : "+f"(c[0]), "+f"(c[1]), "+f"(c[2]), "+f"(c[3])
        : "r"(a[0]), "r"(a[1]), "r"(a[2]), "r"(a[3]), "r"(b0), "r"(b1));
}
__device__ __forceinline__ void cp16(uint32_t s, const void* g) {
    asm volatile("cp.async.cg.shared.global [%0], [%1], 16;" :: "r"(s), "l"(g));
}
__device__ __forceinline__ void cp_commit() {
    asm volatile("cp.async.commit_group;" ::: "memory");
}
template <int N> __device__ __forceinline__ void cp_wait() {
    asm volatile("cp.async.wait_group %0;" :: "n"(N) : "memory");
}

// ---------------------------------------------------------------------------
// Fused fp32 -> fp16 conversion for all inputs.
// ---------------------------------------------------------------------------
__global__ __launch_bounds__(256) void k_cvt_all(
    const float* __restrict__ x,  const float* __restrict__ wq,
    const float* __restrict__ wk, const float* __restrict__ wv,
    const float* __restrict__ wo)
{
    int blk = blockIdx.x;
    const float* src;
    unsigned short* dst;
    size_t base;
    if (blk < 4096)      { src = x;  dst = g_x2;  base = (size_t)blk * 2048; }
    else if (blk < 6144) { src = wq; dst = g_w2;  base = (size_t)(blk - 4096) * 2048; }
    else if (blk < 7168) { src = wk; dst = g_w2 + (size_t)2048 * KP; base = (size_t)(blk - 6144) * 2048; }
    else if (blk < 8192) { src = wv; dst = g_w2 + (size_t)3072 * KP; base = (size_t)(blk - 7168) * 2048; }
    else                 { src = wo; dst = g_wo2; base = (size_t)(blk - 8192) * 2048; }

    size_t i = base + (size_t)threadIdx.x * 8;
    float4 v0 = *(const float4*)(src + i);
    float4 v1 = *(const float4*)(src + i + 4);
    float f[8] = {v0.x, v0.y, v0.z, v0.w, v1.x, v1.y, v1.z, v1.w};
    __align__(16) __half o[8];
#pragma unroll
    for (int j = 0; j < 8; j++) o[j] = __float2half(f[j]);
    *(uint4*)(dst + i) = *(const uint4*)o;
}

// ---------------------------------------------------------------------------
// HMMA fp16 GEMM.
// ---------------------------------------------------------------------------
#define A_BUF (128 * STR)
#define B_BUF (128 * STR)
#define GEMM_SMEM ((3 * (A_BUF + B_BUF)) * 2)   // 110592 bytes

__global__ __launch_bounds__(128, 2) void k_gemm_mma(
    const __half* __restrict__ A, const __half* __restrict__ B,
    float* __restrict__ C, int mode)
{
    extern __shared__ char smraw[];
    __half* sA = (__half*)smraw;
    __half* sB = sA + 3 * A_BUF;

    const int t = threadIdx.x, lane = t & 31, wid = t >> 5;
    const int wm = wid >> 1, wn = wid & 1;
    const int m0 = blockIdx.y * 128, n0 = blockIdx.x * 128;

    uint32_t sAb = smem_u32(sA);
    uint32_t sBb = smem_u32(sB);

    const __half* ga = A + (size_t)(m0 + (t >> 3)) * KP + (t & 7) * 8;
    const __half* gb = B + (size_t)(n0 + (t >> 3)) * KP + (t & 7) * 8;
    const uint32_t so = ((uint32_t)(t >> 3) * STR + (t & 7) * 8) * 2;

    auto load_tile = [&](int buf, int i) {
        uint32_t sa = sAb + (uint32_t)buf * A_BUF * 2 + so;
        uint32_t sb = sBb + (uint32_t)buf * B_BUF * 2 + so;
        int ko = i * BKC;
#pragma unroll
        for (int j = 0; j < 8; j++)
            cp16(sa + j * 16 * STR * 2, ga + (size_t)j * 16 * KP + ko);
#pragma unroll
        for (int j = 0; j < 8; j++)
            cp16(sb + j * 16 * STR * 2, gb + (size_t)j * 16 * KP + ko);
        cp_commit();
    };

    float acc[4][8][4];
#pragma unroll
    for (int i = 0; i < 4; i++)
#pragma unroll
        for (int j = 0; j < 8; j++)
#pragma unroll
            for (int r = 0; r < 4; r++) acc[i][j][r] = 0.f;

    const int lr = lane & 7;
    const int lm = (lane >> 3) & 1;
    const int lc = lane >> 4;

    load_tile(0, 0);
    load_tile(1, 1);

    for (int i = 0; i < NITG; i++) {
        if (i == NITG - 1) cp_wait<0>(); else cp_wait<1>();
        __syncthreads();

        int buf = i % 3;
        uint32_t sa = sAb + (uint32_t)buf * A_BUF * 2;
        uint32_t sb = sBb + (uint32_t)buf * B_BUF * 2;
#pragma unroll
        for (int ks = 0; ks < 4; ks++) {
            uint32_t afr[4][4], bfr[4][4];
            const uint32_t coff = ((uint32_t)(ks * 16 + lc * 8)) * 2;
#pragma unroll
            for (int mt = 0; mt < 4; mt++)
                ldm_x4(afr[mt],
                       sa + ((uint32_t)(wm * 64 + mt * 16 + lr + lm * 8) * STR) * 2 + coff);
#pragma unroll
            for (int nt2 = 0; nt2 < 4; nt2++)
                ldm_x4(bfr[nt2],
                       sb + ((uint32_t)(wn * 64 + nt2 * 16 + lr + lm * 8) * STR) * 2 + coff);
#pragma unroll
            for (int mt = 0; mt < 4; mt++)
#pragma unroll
                for (int nt = 0; nt < 8; nt++)
                    mma_16816(acc[mt][nt], afr[mt],
                              bfr[nt >> 1][nt & 1], bfr[nt >> 1][(nt & 1) + 2]);
        }

        if (i + 2 < NITG) load_tile((i + 2) % 3, i + 2);
    }

    // epilogue
    const int g = lane >> 2, c2 = (lane & 3) * 2;
#pragma unroll
    for (int mt = 0; mt < 4; mt++) {
#pragma unroll
        for (int half = 0; half < 2; half++) {
            int m = m0 + wm * 64 + mt * 16 + g + half * 8;
            if (mode == 0) {
                int b = m >> 11, s = m & 2047;
                int ht = n0 >> 7;
                __half* dsth;
                if (ht < 16)
                    dsth = g_qh0 + (((size_t)(b * NH + ht)) * SEQL + s) * HD;
                else if (ht < 24)
                    dsth = g_kh + (((size_t)(b * NKV + (ht - 16))) * SEQL + s) * HD;
                else
                    dsth = g_vh + (((size_t)(b * NKV + (ht - 24))) * SEQL + s) * HD;
#pragma unroll
                for (int nt = 0; nt < 8; nt++) {
                    int col = wn * 64 + nt * 8 + c2;
                    __half2 h2 = __floats2half2_rn(acc[mt][nt][half * 2],
                                                   acc[mt][nt][half * 2 + 1]);
                    *(__half2*)(dsth + col) = h2;
                }
            } else {
                float* dst = C + (size_t)m * DIMN + n0;
#pragma unroll
                for (int nt = 0; nt < 8; nt++) {
                    int col = wn * 64 + nt * 8 + c2;
                    float2 v2 = make_float2(acc[mt][nt][half * 2],
                                            acc[mt][nt][half * 2 + 1]);
                    *(float2*)(dst + col) = v2;
                }
            }
        }
    }
}

// ---------------------------------------------------------------------------
// K3: ekh = exp(rope(kh)) fp16 via __expf; accumulate column sums (fp32).
// ---------------------------------------------------------------------------
__global__ __launch_bounds__(256) void k_rope_k(const float* __restrict__ fc)
{
    __shared__ float s_part[8][128];
    int bhk = blockIdx.x;
    int w   = threadIdx.x >> 5;
    int l   = threadIdx.x & 31;
    float sum0 = 0.f, sum1 = 0.f, sum2 = 0.f, sum3 = 0.f;
#pragma unroll
    for (int r = 0; r < 8; r++) {
        int s = blockIdx.y * 64 + w * 8 + r;
        size_t off = ((size_t)bhk * SEQL + s) * HD + l * 4;
        __half2 a0 = *(const __half2*)(g_kh + off);
        __half2 a1 = *(const __half2*)(g_kh + off + 2);
        float vx = __low2float(a0), vy = __high2float(a0);
        float vz = __low2float(a1), vw = __high2float(a1);
        float4 f = *(const float4*)(fc + (size_t)s * HD + l * 4);
        float o0 = vx * f.x - vy * f.y;
        float o1 = vx * f.y + vy * f.x;
        float o2 = vz * f.z - vw * f.w;
        float o3 = vz * f.w + vw * f.z;
        float e0 = __expf(o0), e1 = __expf(o1), e2 = __expf(o2), e3 = __expf(o3);
        *(__half2*)(g_ekh + off)     = __floats2half2_rn(e0, e1);
        *(__half2*)(g_ekh + off + 2) = __floats2half2_rn(e2, e3);
        sum0 += e0; sum1 += e1; sum2 += e2; sum3 += e3;
    }
    s_part[w][l * 4 + 0] = sum0;
    s_part[w][l * 4 + 1] = sum1;
    s_part[w][l * 4 + 2] = sum2;
    s_part[w][l * 4 + 3] = sum3;
    __syncthreads();
    if (threadIdx.x < 128) {
        float a = 0.f;
#pragma unroll
        for (int w2 = 0; w2 < 8; w2++) a += s_part[w2][threadIdx.x];
        atomicAdd(&g_colsum[bhk * HD + threadIdx.x], a);
    }
}

// ---------------------------------------------------------------------------
// tiny: colsum -> 1/colsum (between rope_k and rope_q)
// ---------------------------------------------------------------------------
__global__ void k_rcp()
{
    int i = blockIdx.x * 1024 + threadIdx.x;
    if (i < BATCHN * NKV * HD) g_colsum[i] = __frcp_rn(g_colsum[i]);
}

// ---------------------------------------------------------------------------
// K2: q' = softmax(rope(qh0)*s) * invcolsum * QSCALE -> fp16 (fast math).
// ---------------------------------------------------------------------------
__global__ __launch_bounds__(256) void k_rope_q(const float* __restrict__ fc)
{
    int r = blockIdx.x * 8 + (threadIdx.x >> 5);
    int l = threadIdx.x & 31;
    int s  = r & 2047;
    int bh = r >> 11;
    int h  = bh & 15;
    int b  = bh >> 4;

    size_t off = (size_t)r * HD + l * 4;
    __half2 a0 = *(const __half2*)(g_qh0 + off);
    __half2 a1 = *(const __half2*)(g_qh0 + off + 2);
    float vx = __low2float(a0), vy = __high2float(a0);
    float vz = __low2float(a1), vw = __high2float(a1);
    float4 f = *(const float4*)(fc + (size_t)s * HD + l * 4);
    const float scale = 0.08838834764831845f;
    float o0 = (vx * f.x - vy * f.y) * scale;
    float o1 = (vx * f.y + vy * f.x) * scale;
    float o2 = (vz * f.z - vw * f.w) * scale;
    float o3 = (vz * f.w + vw * f.z) * scale;

    float mx = fmaxf(fmaxf(o0, o1), fmaxf(o2, o3));
#pragma unroll
    for (int off2 = 16; off2; off2 >>= 1) mx = fmaxf(mx, __shfl_xor_sync(0xffffffffu, mx, off2));
    float e0 = __expf(o0 - mx), e1 = __expf(o1 - mx);
    float e2 = __expf(o2 - mx), e3 = __expf(o3 - mx);
    float ss = e0 + e1 + e2 + e3;
#pragma unroll
    for (int off2 = 16; off2; off2 >>= 1) ss += __shfl_xor_sync(0xffffffffu, ss, off2);
    float inv = __fdividef(QSCALE, ss);

    const float* csp = g_colsum + ((b * NKV + (h >> 1)) * HD) + l * 4;   // 1/colsum
    float4 cs = *(const float4*)csp;
    __half* qp = g_qh + off;
    *(__half2*)(qp)     = __floats2half2_rn(e0 * inv * cs.x, e1 * inv * cs.y);
    *(__half2*)(qp + 2) = __floats2half2_rn(e2 * inv * cs.z, e3 * inv * cs.w);
}

// ---------------------------------------------------------------------------
// K4: per-chunk kv = ek^T @ v on HMMA (fp16 in, fp32 out).
// ---------------------------------------------------------------------------
#define KVSTR 136
#define KV_SMEM (2 * 128 * KVSTR * 2)   // 69632 bytes

__global__ __launch_bounds__(128, 2) void k_kvchunk_tc()
{
    extern __shared__ __half smkv[];
    __half* es = smkv;
    __half* vs = smkv + 128 * KVSTR;

    const int bhk = blockIdx.x >> 4;
    const int n   = blockIdx.x & 15;
    const __half* eb = g_ekh + ((size_t)bhk * SEQL + n * CHK) * HD;
    const __half* vb = g_vh  + ((size_t)bhk * SEQL + n * CHK) * HD;
    const int t = threadIdx.x, lane = t & 31, w = t >> 5;
    uint32_t esb = smem_u32(es), vsb = smem_u32(vs);

#pragma unroll
    for (int it = 0; it < 16; it++) {
        int idx = it * 128 + t;
        int r = idx >> 4, seg = idx & 15;
        uint32_t so = ((uint32_t)r * KVSTR + seg * 8) * 2;
        cp16(esb + so, eb + (size_t)r * HD + seg * 8);
        cp16(vsb + so, vb + (size_t)r * HD + seg * 8);
    }
    cp_commit();
    cp_wait<0>();
    __syncthreads();

    const int lr = lane & 7, lm = (lane >> 3) & 1, lc = lane >> 4;
    const int g = lane >> 2, qd = (lane & 3) * 2;

    float acc[2][16][4];
#pragma unroll
    for (int i = 0; i < 2; i++)
#pragma unroll
        for (int j = 0; j < 16; j++)
#pragma unroll
            for (int r = 0; r < 4; r++) acc[i][j][r] = 0.f;

#pragma unroll
    for (int ks = 0; ks < 8; ks++) {
        uint32_t afr[2][4], tmp[4], bfr[8][4];
        const uint32_t rowb = ((uint32_t)(ks * 16 + lr + lm * 8)) * KVSTR;
#pragma unroll
        for (int mt = 0; mt < 2; mt++) {
            ldm_x4_t(tmp, esb + (rowb + w * 32 + mt * 16 + lc * 8) * 2);
            afr[mt][0] = tmp[0]; afr[mt][1] = tmp[2];
            afr[mt][2] = tmp[1]; afr[mt][3] = tmp[3];
        }
#pragma unroll
        for (int p = 0; p < 8; p++)
            ldm_x4_t(bfr[p], vsb + (rowb + p * 16 + lc * 8) * 2);
#pragma unroll
        for (int mt = 0; mt < 2; mt++)
#pragma unroll
            for (int nt = 0; nt < 16; nt++)
                mma_16816(acc[mt][nt], afr[mt],
                          bfr[nt >> 1][(nt & 1) * 2], bfr[nt >> 1][(nt & 1) * 2 + 1]);
    }

    size_t base = ((size_t)bhk * NCH + n) * (HD * HD);
#pragma unroll
    for (int mt = 0; mt < 2; mt++) {
#pragma unroll
        for (int half = 0; half < 2; half++) {
            int d = w * 32 + mt * 16 + g + half * 8;
#pragma unroll
            for (int nt = 0; nt < 16; nt++) {
                float2 v2 = make_float2(acc[mt][nt][half * 2],
                                        acc[mt][nt][half * 2 + 1]);
                *(float2*)(g_kv + base + (size_t)d * HD + nt * 8 + qd) = v2;
            }
        }
    }
}

// ---------------------------------------------------------------------------
// K5: exclusive prefix sum over chunks -> fp16 g_cumh.
// ---------------------------------------------------------------------------
__global__ void k_prefix()
{
    int bhk  = blockIdx.x;
    int elem = blockIdx.y * 256 + threadIdx.x;
    size_t base = (size_t)bhk * NCH * (HD * HD) + elem;
    float acc = 0.f;
#pragma unroll
    for (int n = 0; n < NCH; n++) {
        g_cumh[base + (size_t)n * (HD * HD)] = __float2half(acc);
        acc += g_kv[base + (size_t)n * (HD * HD)];
    }
}

// ---------------------------------------------------------------------------
// K6: per-(b,h,chunk) attention on HMMA.
// ---------------------------------------------------------------------------
#define ASTR 136
#define ATILE (128 * ASTR)
#define ATTN2_SMEM (3 * ATILE * 2)   // 104448 bytes

__global__ __launch_bounds__(128, 2) void k_attn_tc()
{
    extern __shared__ __half smh[];
    __half* qs = smh;
    __half* es = smh + ATILE;
    __half* vs = smh + 2 * ATILE;

    const int bid = blockIdx.x;
    const int b = bid >> 8;
    const int h = (bid >> 4) & 15;
    const int n = bid & 15;
    const int hk = h >> 1;
    const int t = threadIdx.x, lane = t & 31, w = t >> 5;

    const __half* qb = g_qh  + (((size_t)(b * NH  + h ) * SEQL) + n * CHK) * HD;
    const __half* eb = g_ekh + (((size_t)(b * NKV + hk) * SEQL) + n * CHK) * HD;
    const __half* vb = g_vh  + (((size_t)(b * NKV + hk) * SEQL) + n * CHK) * HD;
    const __half* cb = g_cumh + ((size_t)(b * NKV + hk) * NCH + n) * (HD * HD);

    uint32_t qsb = smem_u32(qs), esb = smem_u32(es), vsb = smem_u32(vs);

#pragma unroll
    for (int it = 0; it < 16; it++) {
        int idx = it * 128 + t;
        int r = idx >> 4, seg = idx & 15;
        uint32_t so = ((uint32_t)r * ASTR + seg * 8) * 2;
        cp16(qsb + so, qb + (size_t)r * HD + seg * 8);
        cp16(esb + so, eb + (size_t)r * HD + seg * 8);
        cp16(vsb + so, vb + (size_t)r * HD + seg * 8);
    }
    cp_commit();
    cp_wait<0>();
    __syncthreads();

    const int lr = lane & 7, lm = (lane >> 3) & 1, lc = lane >> 4;
    const int g = lane >> 2, qd = (lane & 3) * 2;

    float sacc[2][16][4];
#pragma unroll
    for (int i = 0; i < 2; i++)
#pragma unroll
        for (int j = 0; j < 16; j++)
#pragma unroll
            for (int r = 0; r < 4; r++) sacc[i][j][r] = 0.f;

#pragma unroll
    for (int ks = 0; ks < 8; ks++) {
        uint32_t afr[2][4], bfr[8][4];
        const uint32_t coff = ((uint32_t)(ks * 16 + lc * 8)) * 2;
#pragma unroll
        for (int mt = 0; mt < 2; mt++)
            ldm_x4(afr[mt], qsb + ((uint32_t)(w * 32 + mt * 16 + lr + lm * 8) * ASTR) * 2 + coff);
#pragma unroll
        for (int p = 0; p < 8; p++)
            ldm_x4(bfr[p], esb + ((uint32_t)(p * 16 + lr + lm * 8) * ASTR) * 2 + coff);
#pragma unroll
        for (int mt = 0; mt < 2; mt++)
#pragma unroll
            for (int nt = 0; nt < 16; nt++)
                mma_16816(sacc[mt][nt], afr[mt],
                          bfr[nt >> 1][nt & 1], bfr[nt >> 1][(nt & 1) + 2]);
    }

    __syncthreads();
#pragma unroll
    for (int it = 0; it < 16; it++) {
        int idx = it * 128 + t;
        int r = idx >> 4, seg = idx & 15;
        cp16(esb + ((uint32_t)r * ASTR + seg * 8) * 2, cb + (size_t)r * HD + seg * 8);
    }
    cp_commit();

    uint32_t sfr[2][8][4];
#pragma unroll
    for (int mt = 0; mt < 2; mt++) {
        int c0 = w * 32 + mt * 16 + g;
#pragma unroll
        for (int j = 0; j < 8; j++) {
            int mA = j * 16 + qd;
            int mB = j * 16 + 8 + qd;
            float* e0 = sacc[mt][2 * j];
            float* e1 = sacc[mt][2 * j + 1];
            __half2 p0 = __floats2half2_rn(mA     <= c0     ? e0[0] : 0.f,
                                           mA + 1 <= c0     ? e0[1] : 0.f);
            __half2 p1 = __floats2half2_rn(mA     <= c0 + 8 ? e0[2] : 0.f,
                                           mA + 1 <= c0 + 8 ? e0[3] : 0.f);
            __half2 p2 = __floats2half2_rn(mB     <= c0     ? e1[0] : 0.f,
                                           mB + 1 <= c0     ? e1[1] : 0.f);
            __half2 p3 = __floats2half2_rn(mB     <= c0 + 8 ? e1[2] : 0.f,
                                           mB + 1 <= c0 + 8 ? e1[3] : 0.f);
            sfr[mt][j][0] = *(uint32_t*)&p0;
            sfr[mt][j][1] = *(uint32_t*)&p1;
            sfr[mt][j][2] = *(uint32_t*)&p2;
            sfr[mt][j][3] = *(uint32_t*)&p3;
        }
    }

    cp_wait<0>();
    __syncthreads();

#pragma unroll
    for (int eh = 0; eh < 2; eh++) {
        float oacc[2][8][4];
#pragma unroll
        for (int i = 0; i < 2; i++)
#pragma unroll
            for (int j = 0; j < 8; j++)
#pragma unroll
                for (int r = 0; r < 4; r++) oacc[i][j][r] = 0.f;

#pragma unroll
        for (int j = 0; j < 8; j++) {
            uint32_t vfr[4][4];
#pragma unroll
            for (int ep = 0; ep < 4; ep++)
                ldm_x4_t(vfr[ep],
                         vsb + ((uint32_t)(j * 16 + lr + lm * 8) * ASTR
                                + eh * 64 + ep * 16 + lc * 8) * 2);
#pragma unroll
            for (int mt = 0; mt < 2; mt++)
#pragma unroll
                for (int nt = 0; nt < 8; nt++)
                    mma_16816(oacc[mt][nt], sfr[mt][j],
                              vfr[nt >> 1][(nt & 1) * 2], vfr[nt >> 1][(nt & 1) * 2 + 1]);
        }

#pragma unroll
        for (int ks = 0; ks < 8; ks++) {
            uint32_t afr[2][4], cfr[4][4];
            const uint32_t coff = ((uint32_t)(ks * 16 + lc * 8)) * 2;
#pragma unroll
            for (int mt = 0; mt < 2; mt++)
                ldm_x4(afr[mt], qsb + ((uint32_t)(w * 32 + mt * 16 + lr + lm * 8) * ASTR) * 2 + coff);
#pragma unroll
            for (int ep = 0; ep < 4; ep++)
                ldm_x4_t(cfr[ep],
                         esb + ((uint32_t)(ks * 16 + lr + lm * 8) * ASTR
                                + eh * 64 + ep * 16 + lc * 8) * 2);
#pragma unroll
            for (int mt = 0; mt < 2; mt++)
#pragma unroll
                for (int nt = 0; nt < 8; nt++)
                    mma_16816(oacc[mt][nt], afr[mt],
                              cfr[nt >> 1][(nt & 1) * 2], cfr[nt >> 1][(nt & 1) * 2 + 1]);
        }

#pragma unroll
        for (int mt = 0; mt < 2; mt++) {
#pragma unroll
            for (int half = 0; half < 2; half++) {
                int c = w * 32 + mt * 16 + g + half * 8;
                int s = n * CHK + c;
                unsigned short* orow = g_a2 + (size_t)(b * SEQL + s) * KP + h * HD;
#pragma unroll
                for (int nt = 0; nt < 8; nt++) {
                    int e = eh * 64 + nt * 8 + qd;
                    __half2 h2 = __floats2half2_rn(oacc[mt][nt][half * 2] * QDESCALE,
                                                   oacc[mt][nt][half * 2 + 1] * QDESCALE);
                    *(__half2*)(orow + e) = h2;
                }
            }
        }
    }
}

// ---------------------------------------------------------------------------
extern "C" void kernel_launch(void* const* d_in, const int* in_sizes, int n_in,
                              void* d_out, int out_size)
{
    const float* x  = (const float*)d_in[0];
    const float* fc = (const float*)d_in[1];
    const float* wq = (const float*)d_in[2];
    const float* wk = (const float*)d_in[3];
    const float* wv = (const float*)d_in[4];
    const float* wo = (const float*)d_in[5];
    float* out = (float*)d_out;

    cudaFuncSetAttribute(k_gemm_mma, cudaFuncAttributeMaxDynamicSharedMemorySize, GEMM_SMEM);
    cudaFuncSetAttribute(k_attn_tc, cudaFuncAttributeMaxDynamicSharedMemorySize, ATTN2_SMEM);
    cudaFuncSetAttribute(k_kvchunk_tc, cudaFuncAttributeMaxDynamicSharedMemorySize, KV_SMEM);

    void *p_x2, *p_w2, *p_a2, *p_wo2, *p_cs;
    cudaGetSymbolAddress(&p_x2, g_x2);
    cudaGetSymbolAddress(&p_w2, g_w2);
    cudaGetSymbolAddress(&p_a2, g_a2);
    cudaGetSymbolAddress(&p_wo2, g_wo2);
    cudaGetSymbolAddress(&p_cs, g_colsum);
    unsigned short* x2  = (unsigned short*)p_x2;
    unsigned short* w2  = (unsigned short*)p_w2;
    unsigned short* a2  = (unsigned short*)p_a2;
    unsigned short* wo2 = (unsigned short*)p_wo2;

    k_cvt_all<<<10240, 256>>>(x, wq, wk, wv, wo);
    cudaMemsetAsync(p_cs, 0, BATCHN * NKV * HD * sizeof(float));

    // QKV projection (q/k/v all fp16 scatter)
    k_gemm_mma<<<dim3(32, 32), 128, GEMM_SMEM>>>(
        (const __half*)x2, (const __half*)w2, nullptr, 0);

    // RoPE + softmaxes (fast exp; reciprocal colsum)
    k_rope_k<<<dim3(16, 32), 256>>>(fc);
    k_rcp<<<2, 1024>>>();
    k_rope_q<<<8192, 256>>>(fc);

    // chunked linear attention (all tensor-core)
    k_kvchunk_tc<<<256, 128, KV_SMEM>>>();
    k_prefix<<<dim3(16, 64), 256>>>();
    k_attn_tc<<<512, 128, ATTN2_SMEM>>>();

    // output projection
    k_gemm_mma<<<dim3(16, 32), 128, GEMM_SMEM>>>(
        (const __half*)a2, (const __half*)wo2, out, 1);
}

// round 12
// speedup vs baseline: 6.3672x; 1.0116x over previous
#include <cuda_runtime.h>
#include <cuda_fp16.h>
#include <cstdint>

// Problem constants
#define BATCHN 2
#define SEQL   2048
#define DIMN   2048
#define NH     16
#define NKV    8
#define HD     128
#define NCH    16
#define CHK    128
#define KP     2048
#define BKC    32
#define STR    40
#define NITG   (KP / BKC)   // 64

#define QSCALE   4096.0f
#define QDESCALE (1.0f / 4096.0f)

// ---------------------------------------------------------------------------
// Scratch
// ---------------------------------------------------------------------------
__device__ float g_kv[(size_t)BATCHN * NKV * NCH * HD * HD];
__device__ float g_colsum[BATCHN * NKV * HD];

__device__ unsigned short g_x2[(size_t)4096 * KP];
__device__ unsigned short g_w2[(size_t)4096 * KP];
__device__ unsigned short g_a2[(size_t)4096 * KP];
__device__ unsigned short g_wo2[(size_t)2048 * KP];

__device__ __half g_qh0[(size_t)BATCHN * NH * SEQL * HD];   // raw q (pre-rope) fp16
__device__ __half g_kh[(size_t)BATCHN * NKV * SEQL * HD];   // raw k (pre-rope) fp16
__device__ __half g_qh[(size_t)BATCHN * NH * SEQL * HD];    // q' * QSCALE
__device__ __half g_ekh[(size_t)BATCHN * NKV * SEQL * HD];  // exp(rope(k))
__device__ __half g_vh[(size_t)BATCHN * NKV * SEQL * HD];   // v
__device__ __half g_cumh[(size_t)BATCHN * NKV * NCH * HD * HD];

// ---------------------------------------------------------------------------
// PTX helpers
// ---------------------------------------------------------------------------
__device__ __forceinline__ uint32_t smem_u32(const void* p) {
    uint32_t a;
    asm("{ .reg .u64 t; cvta.to.shared.u64 t, %1; cvt.u32.u64 %0, t; }"
        : "=r"(a) : "l"(p));
    return a;
}
__device__ __forceinline__ void ldm_x4(uint32_t* r, uint32_t addr) {
    asm volatile("ldmatrix.sync.aligned.m8n8.x4.shared.b16 {%0,%1,%2,%3}, [%4];"
                 : "=r"(r[0]), "=r"(r[1]), "=r"(r[2]), "=r"(r[3]) : "r"(addr));
}
__device__ __forceinline__ void ldm_x4_t(uint32_t* r, uint32_t addr) {
    asm volatile("ldmatrix.sync.aligned.m8n8.x4.trans.shared.b16 {%0,%1,%2,%3}, [%4];"
                 : "=r"(r[0]), "=r"(r[1]), "=r"(r[2]), "=r"(r[3]) : "r"(addr));
}
__device__ __forceinline__ void mma_16816(float* c, const uint32_t* a,
                                          uint32_t b0, uint32_t b1) {
    asm volatile(
        "mma.sync.aligned.m16n8k16.row.col.f32.f16.f16.f32 "
        "{%0,%1,%2,%3}, {%4,%5,%6,%7}, {%8,%9}, {%0,%1,%2,%3};"
        : "+f"(c[0]), "+f"(c[1]), "+f"(c[2]), "+f"(c[3])
        : "r"(a[0]), "r"(a[1]), "r"(a[2]), "r"(a[3]), "r"(b0), "r"(b1));
}
__device__ __forceinline__ void cp16(uint32_t s, const void* g) {
    asm volatile("cp.async.cg.shared.global [%0], [%1], 16;" :: "r"(s), "l"(g));
}
__device__ __forceinline__ void cp_commit() {
    asm volatile("cp.async.commit_group;" ::: "memory");
}
template <int N> __device__ __forceinline__ void cp_wait() {
    asm volatile("cp.async.wait_group %0;" :: "n"(N) : "memory");
}

// ---------------------------------------------------------------------------
// Fused fp32 -> fp16 conversion for all inputs.
// ---------------------------------------------------------------------------
__global__ __launch_bounds__(256) void k_cvt_all(
    const float* __restrict__ x,  const float* __restrict__ wq,
    const float* __restrict__ wk, const float* __restrict__ wv,
    const float* __restrict__ wo)
{
    int blk = blockIdx.x;
    const float* src;
    unsigned short* dst;
    size_t base;
    if (blk < 4096)      { src = x;  dst = g_x2;  base = (size_t)blk * 2048; }
    else if (blk < 6144) { src = wq; dst = g_w2;  base = (size_t)(blk - 4096) * 2048; }
    else if (blk < 7168) { src = wk; dst = g_w2 + (size_t)2048 * KP; base = (size_t)(blk - 6144) * 2048; }
    else if (blk < 8192) { src = wv; dst = g_w2 + (size_t)3072 * KP; base = (size_t)(blk - 7168) * 2048; }
    else                 { src = wo; dst = g_wo2; base = (size_t)(blk - 8192) * 2048; }

    size_t i = base + (size_t)threadIdx.x * 8;
    float4 v0 = *(const float4*)(src + i);
    float4 v1 = *(const float4*)(src + i + 4);
    float f[8] = {v0.x, v0.y, v0.z, v0.w, v1.x, v1.y, v1.z, v1.w};
    __align__(16) __half o[8];
#pragma unroll
    for (int j = 0; j < 8; j++) o[j] = __float2half(f[j]);
    *(uint4*)(dst + i) = *(const uint4*)o;
}

// ---------------------------------------------------------------------------
// HMMA fp16 GEMM. 128x128 tile, 4 warps (2x2), BK=32, 3-stage, 3 CTAs/SM.
// mode 0: scatter q/k/v fp16.  mode 1: row-major fp32 C.
// ---------------------------------------------------------------------------
#define A_BUF (128 * STR)   // 5120 halves
#define B_BUF (128 * STR)
#define GEMM_SMEM ((3 * (A_BUF + B_BUF)) * 2)   // 61440 bytes

__global__ __launch_bounds__(128, 3) void k_gemm_mma(
    const __half* __restrict__ A, const __half* __restrict__ B,
    float* __restrict__ C, int mode)
{
    extern __shared__ char smraw[];
    __half* sA = (__half*)smraw;
    __half* sB = sA + 3 * A_BUF;

    const int t = threadIdx.x, lane = t & 31, wid = t >> 5;
    const int wm = wid >> 1, wn = wid & 1;
    const int m0 = blockIdx.y * 128, n0 = blockIdx.x * 128;

    uint32_t sAb = smem_u32(sA);
    uint32_t sBb = smem_u32(sB);

    // 128 threads: 32 rows/pass, 4 passes; each row: 4 x cp16 (64 B = 32 halves)
    const __half* ga = A + (size_t)(m0 + (t >> 2)) * KP + (t & 3) * 8;
    const __half* gb = B + (size_t)(n0 + (t >> 2)) * KP + (t & 3) * 8;
    const uint32_t so = ((uint32_t)(t >> 2) * STR + (t & 3) * 8) * 2;

    auto load_tile = [&](int buf, int i) {
        uint32_t sa = sAb + (uint32_t)buf * A_BUF * 2 + so;
        uint32_t sb = sBb + (uint32_t)buf * B_BUF * 2 + so;
        int ko = i * BKC;
#pragma unroll
        for (int j = 0; j < 4; j++)
            cp16(sa + j * 32 * STR * 2, ga + (size_t)j * 32 * KP + ko);
#pragma unroll
        for (int j = 0; j < 4; j++)
            cp16(sb + j * 32 * STR * 2, gb + (size_t)j * 32 * KP + ko);
        cp_commit();
    };

    float acc[4][8][4];
#pragma unroll
    for (int i = 0; i < 4; i++)
#pragma unroll
        for (int j = 0; j < 8; j++)
#pragma unroll
            for (int r = 0; r < 4; r++) acc[i][j][r] = 0.f;

    const int lr = lane & 7;
    const int lm = (lane >> 3) & 1;
    const int lc = lane >> 4;

    load_tile(0, 0);
    load_tile(1, 1);

    for (int i = 0; i < NITG; i++) {
        if (i == NITG - 1) cp_wait<0>(); else cp_wait<1>();
        __syncthreads();

        int buf = i % 3;
        uint32_t sa = sAb + (uint32_t)buf * A_BUF * 2;
        uint32_t sb = sBb + (uint32_t)buf * B_BUF * 2;
#pragma unroll
        for (int ks = 0; ks < 2; ks++) {
            uint32_t afr[4][4], bfr[4][4];
            const uint32_t coff = ((uint32_t)(ks * 16 + lc * 8)) * 2;
#pragma unroll
            for (int mt = 0; mt < 4; mt++)
                ldm_x4(afr[mt],
                       sa + ((uint32_t)(wm * 64 + mt * 16 + lr + lm * 8) * STR) * 2 + coff);
#pragma unroll
            for (int nt2 = 0; nt2 < 4; nt2++)
                ldm_x4(bfr[nt2],
                       sb + ((uint32_t)(wn * 64 + nt2 * 16 + lr + lm * 8) * STR) * 2 + coff);
#pragma unroll
            for (int mt = 0; mt < 4; mt++)
#pragma unroll
                for (int nt = 0; nt < 8; nt++)
                    mma_16816(acc[mt][nt], afr[mt],
                              bfr[nt >> 1][nt & 1], bfr[nt >> 1][(nt & 1) + 2]);
        }

        if (i + 2 < NITG) load_tile((i + 2) % 3, i + 2);
    }

    // epilogue
    const int g = lane >> 2, c2 = (lane & 3) * 2;
#pragma unroll
    for (int mt = 0; mt < 4; mt++) {
#pragma unroll
        for (int half = 0; half < 2; half++) {
            int m = m0 + wm * 64 + mt * 16 + g + half * 8;
            if (mode == 0) {
                int b = m >> 11, s = m & 2047;
                int ht = n0 >> 7;
                __half* dsth;
                if (ht < 16)
                    dsth = g_qh0 + (((size_t)(b * NH + ht)) * SEQL + s) * HD;
                else if (ht < 24)
                    dsth = g_kh + (((size_t)(b * NKV + (ht - 16))) * SEQL + s) * HD;
                else
                    dsth = g_vh + (((size_t)(b * NKV + (ht - 24))) * SEQL + s) * HD;
#pragma unroll
                for (int nt = 0; nt < 8; nt++) {
                    int col = wn * 64 + nt * 8 + c2;
                    __half2 h2 = __floats2half2_rn(acc[mt][nt][half * 2],
                                                   acc[mt][nt][half * 2 + 1]);
                    *(__half2*)(dsth + col) = h2;
                }
            } else {
                float* dst = C + (size_t)m * DIMN + n0;
#pragma unroll
                for (int nt = 0; nt < 8; nt++) {
                    int col = wn * 64 + nt * 8 + c2;
                    float2 v2 = make_float2(acc[mt][nt][half * 2],
                                            acc[mt][nt][half * 2 + 1]);
                    *(float2*)(dst + col) = v2;
                }
            }
        }
    }
}

// ---------------------------------------------------------------------------
// K3: ekh = exp(rope(kh)) fp16 via __expf; accumulate column sums (fp32).
// ---------------------------------------------------------------------------
__global__ __launch_bounds__(256) void k_rope_k(const float* __restrict__ fc)
{
    __shared__ float s_part[8][128];
    int bhk = blockIdx.x;
    int w   = threadIdx.x >> 5;
    int l   = threadIdx.x & 31;
    float sum0 = 0.f, sum1 = 0.f, sum2 = 0.f, sum3 = 0.f;
#pragma unroll
    for (int r = 0; r < 8; r++) {
        int s = blockIdx.y * 64 + w * 8 + r;
        size_t off = ((size_t)bhk * SEQL + s) * HD + l * 4;
        __half2 a0 = *(const __half2*)(g_kh + off);
        __half2 a1 = *(const __half2*)(g_kh + off + 2);
        float vx = __low2float(a0), vy = __high2float(a0);
        float vz = __low2float(a1), vw = __high2float(a1);
        float4 f = *(const float4*)(fc + (size_t)s * HD + l * 4);
        float o0 = vx * f.x - vy * f.y;
        float o1 = vx * f.y + vy * f.x;
        float o2 = vz * f.z - vw * f.w;
        float o3 = vz * f.w + vw * f.z;
        float e0 = __expf(o0), e1 = __expf(o1), e2 = __expf(o2), e3 = __expf(o3);
        *(__half2*)(g_ekh + off)     = __floats2half2_rn(e0, e1);
        *(__half2*)(g_ekh + off + 2) = __floats2half2_rn(e2, e3);
        sum0 += e0; sum1 += e1; sum2 += e2; sum3 += e3;
    }
    s_part[w][l * 4 + 0] = sum0;
    s_part[w][l * 4 + 1] = sum1;
    s_part[w][l * 4 + 2] = sum2;
    s_part[w][l * 4 + 3] = sum3;
    __syncthreads();
    if (threadIdx.x < 128) {
        float a = 0.f;
#pragma unroll
        for (int w2 = 0; w2 < 8; w2++) a += s_part[w2][threadIdx.x];
        atomicAdd(&g_colsum[bhk * HD + threadIdx.x], a);
    }
}

// ---------------------------------------------------------------------------
// K4: per-chunk kv = ek^T @ v on HMMA. ALSO inverts g_colsum (block-strided,
// 256 blocks x 8 elems = 2048) before its main work — removes the k_rcp launch.
// ---------------------------------------------------------------------------
#define KVSTR 136
#define KV_SMEM (2 * 128 * KVSTR * 2)   // 69632 bytes

__global__ __launch_bounds__(128, 2) void k_kvchunk_tc()
{
    extern __shared__ __half smkv[];
    __half* es = smkv;
    __half* vs = smkv + 128 * KVSTR;

    // fused reciprocal of colsum (runs before rope_q, which is launched later)
    if (threadIdx.x < 8) {
        int i = blockIdx.x * 8 + threadIdx.x;
        g_colsum[i] = __frcp_rn(g_colsum[i]);
    }

    const int bhk = blockIdx.x >> 4;
    const int n   = blockIdx.x & 15;
    const __half* eb = g_ekh + ((size_t)bhk * SEQL + n * CHK) * HD;
    const __half* vb = g_vh  + ((size_t)bhk * SEQL + n * CHK) * HD;
    const int t = threadIdx.x, lane = t & 31, w = t >> 5;
    uint32_t esb = smem_u32(es), vsb = smem_u32(vs);

#pragma unroll
    for (int it = 0; it < 16; it++) {
        int idx = it * 128 + t;
        int r = idx >> 4, seg = idx & 15;
        uint32_t so = ((uint32_t)r * KVSTR + seg * 8) * 2;
        cp16(esb + so, eb + (size_t)r * HD + seg * 8);
        cp16(vsb + so, vb + (size_t)r * HD + seg * 8);
    }
    cp_commit();
    cp_wait<0>();
    __syncthreads();

    const int lr = lane & 7, lm = (lane >> 3) & 1, lc = lane >> 4;
    const int g = lane >> 2, qd = (lane & 3) * 2;

    float acc[2][16][4];
#pragma unroll
    for (int i = 0; i < 2; i++)
#pragma unroll
        for (int j = 0; j < 16; j++)
#pragma unroll
            for (int r = 0; r < 4; r++) acc[i][j][r] = 0.f;

#pragma unroll
    for (int ks = 0; ks < 8; ks++) {
        uint32_t afr[2][4], tmp[4], bfr[8][4];
        const uint32_t rowb = ((uint32_t)(ks * 16 + lr + lm * 8)) * KVSTR;
#pragma unroll
        for (int mt = 0; mt < 2; mt++) {
            ldm_x4_t(tmp, esb + (rowb + w * 32 + mt * 16 + lc * 8) * 2);
            afr[mt][0] = tmp[0]; afr[mt][1] = tmp[2];
            afr[mt][2] = tmp[1]; afr[mt][3] = tmp[3];
        }
#pragma unroll
        for (int p = 0; p < 8; p++)
            ldm_x4_t(bfr[p], vsb + (rowb + p * 16 + lc * 8) * 2);
#pragma unroll
        for (int mt = 0; mt < 2; mt++)
#pragma unroll
            for (int nt = 0; nt < 16; nt++)
                mma_16816(acc[mt][nt], afr[mt],
                          bfr[nt >> 1][(nt & 1) * 2], bfr[nt >> 1][(nt & 1) * 2 + 1]);
    }

    size_t base = ((size_t)bhk * NCH + n) * (HD * HD);
#pragma unroll
    for (int mt = 0; mt < 2; mt++) {
#pragma unroll
        for (int half = 0; half < 2; half++) {
            int d = w * 32 + mt * 16 + g + half * 8;
#pragma unroll
            for (int nt = 0; nt < 16; nt++) {
                float2 v2 = make_float2(acc[mt][nt][half * 2],
                                        acc[mt][nt][half * 2 + 1]);
                *(float2*)(g_kv + base + (size_t)d * HD + nt * 8 + qd) = v2;
            }
        }
    }
}

// ---------------------------------------------------------------------------
// K2: q' = softmax(rope(qh0)*s) * invcolsum * QSCALE -> fp16 (fast math).
// Runs AFTER kvchunk (which inverts colsum).
// ---------------------------------------------------------------------------
__global__ __launch_bounds__(256) void k_rope_q(const float* __restrict__ fc)
{
    int r = blockIdx.x * 8 + (threadIdx.x >> 5);
    int l = threadIdx.x & 31;
    int s  = r & 2047;
    int bh = r >> 11;
    int h  = bh & 15;
    int b  = bh >> 4;

    size_t off = (size_t)r * HD + l * 4;
    __half2 a0 = *(const __half2*)(g_qh0 + off);
    __half2 a1 = *(const __half2*)(g_qh0 + off + 2);
    float vx = __low2float(a0), vy = __high2float(a0);
    float vz = __low2float(a1), vw = __high2float(a1);
    float4 f = *(const float4*)(fc + (size_t)s * HD + l * 4);
    const float scale = 0.08838834764831845f;
    float o0 = (vx * f.x - vy * f.y) * scale;
    float o1 = (vx * f.y + vy * f.x) * scale;
    float o2 = (vz * f.z - vw * f.w) * scale;
    float o3 = (vz * f.w + vw * f.z) * scale;

    float mx = fmaxf(fmaxf(o0, o1), fmaxf(o2, o3));
#pragma unroll
    for (int off2 = 16; off2; off2 >>= 1) mx = fmaxf(mx, __shfl_xor_sync(0xffffffffu, mx, off2));
    float e0 = __expf(o0 - mx), e1 = __expf(o1 - mx);
    float e2 = __expf(o2 - mx), e3 = __expf(o3 - mx);
    float ss = e0 + e1 + e2 + e3;
#pragma unroll
    for (int off2 = 16; off2; off2 >>= 1) ss += __shfl_xor_sync(0xffffffffu, ss, off2);
    float inv = __fdividef(QSCALE, ss);

    const float* csp = g_colsum + ((b * NKV + (h >> 1)) * HD) + l * 4;   // 1/colsum
    float4 cs = *(const float4*)csp;
    __half* qp = g_qh + off;
    *(__half2*)(qp)     = __floats2half2_rn(e0 * inv * cs.x, e1 * inv * cs.y);
    *(__half2*)(qp + 2) = __floats2half2_rn(e2 * inv * cs.z, e3 * inv * cs.w);
}

// ---------------------------------------------------------------------------
// K5: exclusive prefix sum over chunks -> fp16 g_cumh.
// ---------------------------------------------------------------------------
__global__ void k_prefix()
{
    int bhk  = blockIdx.x;
    int elem = blockIdx.y * 256 + threadIdx.x;
    size_t base = (size_t)bhk * NCH * (HD * HD) + elem;
    float acc = 0.f;
#pragma unroll
    for (int n = 0; n < NCH; n++) {
        g_cumh[base + (size_t)n * (HD * HD)] = __float2half(acc);
        acc += g_kv[base + (size_t)n * (HD * HD)];
    }
}

// ---------------------------------------------------------------------------
// K6: per-(b,h,chunk) attention on HMMA.
// ---------------------------------------------------------------------------
#define ASTR 136
#define ATILE (128 * ASTR)
#define ATTN2_SMEM (3 * ATILE * 2)   // 104448 bytes

__global__ __launch_bounds__(128, 2) void k_attn_tc()
{
    extern __shared__ __half smh[];
    __half* qs = smh;
    __half* es = smh + ATILE;
    __half* vs = smh + 2 * ATILE;

    const int bid = blockIdx.x;
    const int b = bid >> 8;
    const int h = (bid >> 4) & 15;
    const int n = bid & 15;
    const int hk = h >> 1;
    const int t = threadIdx.x, lane = t & 31, w = t >> 5;

    const __half* qb = g_qh  + (((size_t)(b * NH  + h ) * SEQL) + n * CHK) * HD;
    const __half* eb = g_ekh + (((size_t)(b * NKV + hk) * SEQL) + n * CHK) * HD;
    const __half* vb = g_vh  + (((size_t)(b * NKV + hk) * SEQL) + n * CHK) * HD;
    const __half* cb = g_cumh + ((size_t)(b * NKV + hk) * NCH + n) * (HD * HD);

    uint32_t qsb = smem_u32(qs), esb = smem_u32(es), vsb = smem_u32(vs);

#pragma unroll
    for (int it = 0; it < 16; it++) {
        int idx = it * 128 + t;
        int r = idx >> 4, seg = idx & 15;
        uint32_t so = ((uint32_t)r * ASTR + seg * 8) * 2;
        cp16(qsb + so, qb + (size_t)r * HD + seg * 8);
        cp16(esb + so, eb + (size_t)r * HD + seg * 8);
        cp16(vsb + so, vb + (size_t)r * HD + seg * 8);
    }
    cp_commit();
    cp_wait<0>();
    __syncthreads();

    const int lr = lane & 7, lm = (lane >> 3) & 1, lc = lane >> 4;
    const int g = lane >> 2, qd = (lane & 3) * 2;

    float sacc[2][16][4];
#pragma unroll
    for (int i = 0; i < 2; i++)
#pragma unroll
        for (int j = 0; j < 16; j++)
#pragma unroll
            for (int r = 0; r < 4; r++) sacc[i][j][r] = 0.f;

#pragma unroll
    for (int ks = 0; ks < 8; ks++) {
        uint32_t afr[2][4], bfr[8][4];
        const uint32_t coff = ((uint32_t)(ks * 16 + lc * 8)) * 2;
#pragma unroll
        for (int mt = 0; mt < 2; mt++)
            ldm_x4(afr[mt], qsb + ((uint32_t)(w * 32 + mt * 16 + lr + lm * 8) * ASTR) * 2 + coff);
#pragma unroll
        for (int p = 0; p < 8; p++)
            ldm_x4(bfr[p], esb + ((uint32_t)(p * 16 + lr + lm * 8) * ASTR) * 2 + coff);
#pragma unroll
        for (int mt = 0; mt < 2; mt++)
#pragma unroll
            for (int nt = 0; nt < 16; nt++)
                mma_16816(sacc[mt][nt], afr[mt],
                          bfr[nt >> 1][nt & 1], bfr[nt >> 1][(nt & 1) + 2]);
    }

    __syncthreads();
#pragma unroll
    for (int it = 0; it < 16; it++) {
        int idx = it * 128 + t;
        int r = idx >> 4, seg = idx & 15;
        cp16(esb + ((uint32_t)r * ASTR + seg * 8) * 2, cb + (size_t)r * HD + seg * 8);
    }
    cp_commit();

    uint32_t sfr[2][8][4];
#pragma unroll
    for (int mt = 0; mt < 2; mt++) {
        int c0 = w * 32 + mt * 16 + g;
#pragma unroll
        for (int j = 0; j < 8; j++) {
            int mA = j * 16 + qd;
            int mB = j * 16 + 8 + qd;
            float* e0 = sacc[mt][2 * j];
            float* e1 = sacc[mt][2 * j + 1];
            __half2 p0 = __floats2half2_rn(mA     <= c0     ? e0[0] : 0.f,
                                           mA + 1 <= c0     ? e0[1] : 0.f);
            __half2 p1 = __floats2half2_rn(mA     <= c0 + 8 ? e0[2] : 0.f,
                                           mA + 1 <= c0 + 8 ? e0[3] : 0.f);
            __half2 p2 = __floats2half2_rn(mB     <= c0     ? e1[0] : 0.f,
                                           mB + 1 <= c0     ? e1[1] : 0.f);
            __half2 p3 = __floats2half2_rn(mB     <= c0 + 8 ? e1[2] : 0.f,
                                           mB + 1 <= c0 + 8 ? e1[3] : 0.f);
            sfr[mt][j][0] = *(uint32_t*)&p0;
            sfr[mt][j][1] = *(uint32_t*)&p1;
            sfr[mt][j][2] = *(uint32_t*)&p2;
            sfr[mt][j][3] = *(uint32_t*)&p3;
        }
    }

    cp_wait<0>();
    __syncthreads();

#pragma unroll
    for (int eh = 0; eh < 2; eh++) {
        float oacc[2][8][4];
#pragma unroll
        for (int i = 0; i < 2; i++)
#pragma unroll
            for (int j = 0; j < 8; j++)
#pragma unroll
                for (int r = 0; r < 4; r++) oacc[i][j][r] = 0.f;

#pragma unroll
        for (int j = 0; j < 8; j++) {
            uint32_t vfr[4][4];
#pragma unroll
            for (int ep = 0; ep < 4; ep++)
                ldm_x4_t(vfr[ep],
                         vsb + ((uint32_t)(j * 16 + lr + lm * 8) * ASTR
                                + eh * 64 + ep * 16 + lc * 8) * 2);
#pragma unroll
            for (int mt = 0; mt < 2; mt++)
#pragma unroll
                for (int nt = 0; nt < 8; nt++)
                    mma_16816(oacc[mt][nt], sfr[mt][j],
                              vfr[nt >> 1][(nt & 1) * 2], vfr[nt >> 1][(nt & 1) * 2 + 1]);
        }

#pragma unroll
        for (int ks = 0; ks < 8; ks++) {
            uint32_t afr[2][4], cfr[4][4];
            const uint32_t coff = ((uint32_t)(ks * 16 + lc * 8)) * 2;
#pragma unroll
            for (int mt = 0; mt < 2; mt++)
                ldm_x4(afr[mt], qsb + ((uint32_t)(w * 32 + mt * 16 + lr + lm * 8) * ASTR) * 2 + coff);
#pragma unroll
            for (int ep = 0; ep < 4; ep++)
                ldm_x4_t(cfr[ep],
                         esb + ((uint32_t)(ks * 16 + lr + lm * 8) * ASTR
                                + eh * 64 + ep * 16 + lc * 8) * 2);
#pragma unroll
            for (int mt = 0; mt < 2; mt++)
#pragma unroll
                for (int nt = 0; nt < 8; nt++)
                    mma_16816(oacc[mt][nt], afr[mt],
                              cfr[nt >> 1][(nt & 1) * 2], cfr[nt >> 1][(nt & 1) * 2 + 1]);
        }

#pragma unroll
        for (int mt = 0; mt < 2; mt++) {
#pragma unroll
            for (int half = 0; half < 2; half++) {
                int c = w * 32 + mt * 16 + g + half * 8;
                int s = n * CHK + c;
                unsigned short* orow = g_a2 + (size_t)(b * SEQL + s) * KP + h * HD;
#pragma unroll
                for (int nt = 0; nt < 8; nt++) {
                    int e = eh * 64 + nt * 8 + qd;
                    __half2 h2 = __floats2half2_rn(oacc[mt][nt][half * 2] * QDESCALE,
                                                   oacc[mt][nt][half * 2 + 1] * QDESCALE);
                    *(__half2*)(orow + e) = h2;
                }
            }
        }
    }
}

// ---------------------------------------------------------------------------
extern "C" void kernel_launch(void* const* d_in, const int* in_sizes, int n_in,
                              void* d_out, int out_size)
{
    const float* x  = (const float*)d_in[0];
    const float* fc = (const float*)d_in[1];
    const float* wq = (const float*)d_in[2];
    const float* wk = (const float*)d_in[3];
    const float* wv = (const float*)d_in[4];
    const float* wo = (const float*)d_in[5];
    float* out = (float*)d_out;

    cudaFuncSetAttribute(k_gemm_mma, cudaFuncAttributeMaxDynamicSharedMemorySize, GEMM_SMEM);
    cudaFuncSetAttribute(k_attn_tc, cudaFuncAttributeMaxDynamicSharedMemorySize, ATTN2_SMEM);
    cudaFuncSetAttribute(k_kvchunk_tc, cudaFuncAttributeMaxDynamicSharedMemorySize, KV_SMEM);

    void *p_x2, *p_w2, *p_a2, *p_wo2, *p_cs;
    cudaGetSymbolAddress(&p_x2, g_x2);
    cudaGetSymbolAddress(&p_w2, g_w2);
    cudaGetSymbolAddress(&p_a2, g_a2);
    cudaGetSymbolAddress(&p_wo2, g_wo2);
    cudaGetSymbolAddress(&p_cs, g_colsum);
    unsigned short* x2  = (unsigned short*)p_x2;
    unsigned short* w2  = (unsigned short*)p_w2;
    unsigned short* a2  = (unsigned short*)p_a2;
    unsigned short* wo2 = (unsigned short*)p_wo2;

    k_cvt_all<<<10240, 256>>>(x, wq, wk, wv, wo);
    cudaMemsetAsync(p_cs, 0, BATCHN * NKV * HD * sizeof(float));

    // QKV projection (q/k/v all fp16 scatter)
    k_gemm_mma<<<dim3(32, 32), 128, GEMM_SMEM>>>(
        (const __half*)x2, (const __half*)w2, nullptr, 0);

    // RoPE-k (colsum), then kvchunk (also inverts colsum), then rope-q
    k_rope_k<<<dim3(16, 32), 256>>>(fc);
    k_kvchunk_tc<<<256, 128, KV_SMEM>>>();
    k_rope_q<<<8192, 256>>>(fc);

    // prefix + attention
    k_prefix<<<dim3(16, 64), 256>>>();
    k_attn_tc<<<512, 128, ATTN2_SMEM>>>();

    // output projection
    k_gemm_mma<<<dim3(16, 32), 128, GEMM_SMEM>>>(
        (const __half*)a2, (const __half*)wo2, out, 1);
}